// round 9
// baseline (speedup 1.0000x reference)
#include <cuda_runtime.h>
#include <cuda_bf16.h>
#include <cstdint>

typedef unsigned long long ull;
typedef uint32_t u32;

#define TOKS 200704          // 4096 windows * 49 tokens (= 1568 * 128)
#define NWIN 64

// ---------------- device scratch ----------------
__device__ __nv_bfloat16 g_xe[(size_t)TOKS * 384];    // x split [t][hi(192)|lo(192)]
__device__ float         g_qkv[(size_t)TOKS * 576];   // qkv fp32
__device__ __nv_bfloat16 g_oe[(size_t)TOKS * 384];    // attn out split [hi|lo]
__device__ __nv_bfloat16 g_wqe[576 * 576];            // qkv_w packed [n][wh|wl|wh]
__device__ __nv_bfloat16 g_wpe[192 * 576];            // proj_w packed
__device__ float         g_bm[64 * 6 * 49 * 56];      // bias+mask combined, j padded to 56

__device__ __forceinline__ u32 smem_u32(const void* p) {
    u32 a;
    asm("{ .reg .u64 t; cvta.to.shared.u64 t, %1; cvt.u32.u64 %0, t; }" : "=r"(a) : "l"(p));
    return a;
}
__device__ __forceinline__ void cp16(u32 saddr, const void* gaddr) {
    asm volatile("cp.async.cg.shared.global [%0], [%1], 16;" :: "r"(saddr), "l"(gaddr));
}
__device__ __forceinline__ void ldm4(u32* r, u32 addr) {
    asm volatile("ldmatrix.sync.aligned.m8n8.x4.shared.b16 {%0,%1,%2,%3}, [%4];"
                 : "=r"(r[0]), "=r"(r[1]), "=r"(r[2]), "=r"(r[3]) : "r"(addr));
}
__device__ __forceinline__ void mma16816(float* d, const u32* a, u32 b0, u32 b1) {
    asm volatile("mma.sync.aligned.m16n8k16.row.col.f32.bf16.bf16.f32 "
                 "{%0,%1,%2,%3}, {%4,%5,%6,%7}, {%8,%9}, {%0,%1,%2,%3};"
                 : "+f"(d[0]), "+f"(d[1]), "+f"(d[2]), "+f"(d[3])
                 : "r"(a[0]), "r"(a[1]), "r"(a[2]), "r"(a[3]), "r"(b0), "r"(b1));
}
__device__ __forceinline__ ull fma2(ull a, ull b, ull c) {
    ull d; asm("fma.rn.f32x2 %0, %1, %2, %3;" : "=l"(d) : "l"(a), "l"(b), "l"(c)); return d;
}
__device__ __forceinline__ ull add2(ull a, ull b) {
    ull d; asm("add.rn.f32x2 %0, %1, %2;" : "=l"(d) : "l"(a), "l"(b)); return d;
}
__device__ __forceinline__ ull pack2(float x, float y) {
    ull d; asm("mov.b64 %0, {%1, %2};" : "=l"(d) : "f"(x), "f"(y)); return d;
}
__device__ __forceinline__ float2 unp2(ull a) {
    float2 r; asm("mov.b64 {%0, %1}, %2;" : "=f"(r.x), "=f"(r.y) : "l"(a)); return r;
}

// ---------------- prep: split-pack weights + combine bias/mask ----------------
__global__ void prep_kernel(const float* __restrict__ qkv_w, const float* __restrict__ proj_w,
                            const float* __restrict__ bias_table, const int* __restrict__ rel_index,
                            const float* __restrict__ mask) {
    int tid = blockIdx.x * blockDim.x + threadIdx.x;
    int stride = gridDim.x * blockDim.x;
    for (int i = tid; i < 576 * 192; i += stride) {
        int n = i / 192, k = i - n * 192;
        float w = qkv_w[i];
        __nv_bfloat16 h = __float2bfloat16(w);
        __nv_bfloat16 l = __float2bfloat16(w - __bfloat162float(h));
        g_wqe[(size_t)n * 576 + k]       = h;
        g_wqe[(size_t)n * 576 + 192 + k] = l;
        g_wqe[(size_t)n * 576 + 384 + k] = h;
    }
    for (int i = tid; i < 192 * 192; i += stride) {
        int n = i / 192, k = i - n * 192;
        float w = proj_w[i];
        __nv_bfloat16 h = __float2bfloat16(w);
        __nv_bfloat16 l = __float2bfloat16(w - __bfloat162float(h));
        g_wpe[(size_t)n * 576 + k]       = h;
        g_wpe[(size_t)n * 576 + 192 + k] = l;
        g_wpe[(size_t)n * 576 + 384 + k] = h;
    }
    for (int i = tid; i < 64 * 6 * 49 * 56; i += stride) {
        int j = i % 56; int rest = i / 56;
        int ir = rest % 49; rest /= 49;
        int hh = rest % 6; int wm = rest / 6;
        float v = 0.f;
        if (j < 49)
            v = bias_table[rel_index[ir * 49 + j] * 6 + hh] + mask[wm * 2401 + ir * 49 + j];
        g_bm[i] = v;
    }
}

// ---------------- x -> bf16 split [hi|lo] (384 wide) ----------------
__global__ void xconv_kernel(const float* __restrict__ x) {
    size_t idx = (size_t)blockIdx.x * 256 + threadIdx.x;
    size_t t = idx / 96;
    int p = (int)(idx - t * 96);
    float2 v = *(const float2*)(x + t * 192 + 2 * p);
    __nv_bfloat16 h0 = __float2bfloat16(v.x), h1 = __float2bfloat16(v.y);
    __nv_bfloat16 l0 = __float2bfloat16(v.x - __bfloat162float(h0));
    __nv_bfloat16 l1 = __float2bfloat16(v.y - __bfloat162float(h1));
    __nv_bfloat162 hp; hp.x = h0; hp.y = h1;
    __nv_bfloat162 lp; lp.x = l0; lp.y = l1;
    size_t base = t * 384 + 2 * p;
    *(__nv_bfloat162*)(g_xe + base)       = hp;
    *(__nv_bfloat162*)(g_xe + base + 192) = lp;
}

// ---------------- mma.sync GEMM, 3-stage cp.async pipeline ----------------
// grid = (n_tiles, m_tiles): n fastest so one A tile's n-tiles are co-resident
// and A stays L2-hot across its 9 (or 3) B passes.
#define GSMEM 73728

__global__ __launch_bounds__(256, 2)
void gemm_mma(const float* __restrict__ bias, float* __restrict__ out_param, int which) {
    extern __shared__ char sm[];
    const __nv_bfloat16* Ae = which ? g_oe : g_xe;
    const __nv_bfloat16* We = which ? g_wpe : g_wqe;
    float* outp = which ? out_param : g_qkv;
    const int Ncols = which ? 192 : 576;

    const u32 sb = smem_u32(sm);
    const int tid  = threadIdx.x;
    const int lane = tid & 31;
    const int wid  = tid >> 5;
    const int wm   = wid >> 1;
    const int wn   = wid & 1;
    const size_t row0 = (size_t)blockIdx.y * 128;
    const int    n0   = blockIdx.x * 64;

    float acc[2][4][4];
    #pragma unroll
    for (int mt = 0; mt < 2; mt++)
        #pragma unroll
        for (int nt = 0; nt < 4; nt++)
            #pragma unroll
            for (int q = 0; q < 4; q++) acc[mt][nt][q] = 0.f;

    auto load_chunk = [&](int kc, int buf) {
        int aoff = (kc < 3) ? kc * 64 : (kc < 6 ? (kc - 3) * 64 : (kc - 6) * 64 + 192);
        const u32 sA = sb + (u32)buf * 16384u;
        const u32 sB = sb + 49152u + (u32)buf * 8192u;
        #pragma unroll
        for (int s = 0; s < 6; s++) {
            int j = tid + s * 256;
            if (j < 1024) {
                int r = j >> 3, c = j & 7;
                u32 saddr = sA + (u32)r * 128u + (u32)((c ^ (r & 7)) << 4);
                cp16(saddr, Ae + (row0 + r) * 384 + aoff + c * 8);
            } else {
                int jj = j - 1024;
                int r = jj >> 3, c = jj & 7;
                u32 saddr = sB + (u32)r * 128u + (u32)((c ^ (r & 7)) << 4);
                cp16(saddr, We + (size_t)(n0 + r) * 576 + kc * 64 + c * 8);
            }
        }
        asm volatile("cp.async.commit_group;" ::: "memory");
    };

    load_chunk(0, 0);
    load_chunk(1, 1);

    #pragma unroll 1
    for (int kc = 0; kc < 9; kc++) {
        if (kc < 8) asm volatile("cp.async.wait_group 1;" ::: "memory");
        else        asm volatile("cp.async.wait_group 0;" ::: "memory");
        __syncthreads();
        if (kc + 2 < 9) load_chunk(kc + 2, (kc + 2) % 3);

        const int buf = kc % 3;
        const u32 sA = sb + (u32)buf * 16384u;
        const u32 sB = sb + 49152u + (u32)buf * 8192u;

        #pragma unroll
        for (int ks = 0; ks < 4; ks++) {
            u32 afr[2][4], bfr[2][4];
            #pragma unroll
            for (int mt = 0; mt < 2; mt++) {
                int row = wm * 32 + mt * 16 + (lane & 15);
                int c   = ks * 2 + (lane >> 4);
                ldm4(afr[mt], sA + (u32)row * 128u + (u32)((c ^ (row & 7)) << 4));
            }
            #pragma unroll
            for (int np = 0; np < 2; np++) {
                int brow = wn * 32 + np * 16 + (lane & 7) + ((lane >> 4) & 1) * 8;
                int c    = ks * 2 + ((lane >> 3) & 1);
                ldm4(bfr[np], sB + (u32)brow * 128u + (u32)((c ^ (brow & 7)) << 4));
            }
            #pragma unroll
            for (int mt = 0; mt < 2; mt++)
                #pragma unroll
                for (int nt = 0; nt < 4; nt++)
                    mma16816(acc[mt][nt], afr[mt], bfr[nt >> 1][(nt & 1) * 2], bfr[nt >> 1][(nt & 1) * 2 + 1]);
        }
        __syncthreads();
    }

    const int tr = lane >> 2, tc = (lane & 3) * 2;
    #pragma unroll
    for (int mt = 0; mt < 2; mt++) {
        #pragma unroll
        for (int nt = 0; nt < 4; nt++) {
            int col = n0 + wn * 32 + nt * 8 + tc;
            float b0 = bias[col], b1 = bias[col + 1];
            size_t r_lo = row0 + wm * 32 + mt * 16 + tr;
            float2 v0; v0.x = acc[mt][nt][0] + b0; v0.y = acc[mt][nt][1] + b1;
            float2 v1; v1.x = acc[mt][nt][2] + b0; v1.y = acc[mt][nt][3] + b1;
            *(float2*)(outp + r_lo * Ncols + col)       = v0;
            *(float2*)(outp + (r_lo + 8) * Ncols + col) = v1;
        }
    }
}

// ---------------- attention: one CTA per (window, head), 128 threads ----------------
// smem (floats, 7770): qs @0 (1568), kt @1568 (1792), vs @3360 (1568),
// sA @4928 (2842). pt @0 overlaps qs/kt after P1.
// P1: tasks of 13 rows (i0 = wid*13; base offsets x32 keep alignment).
// P3: tasks of 12/13 rows at i0 = wid*12 (multiple of 4 -> float4-aligned pt reads).
#define AQS 0
#define AKT 1568
#define AVS 3360
#define ASA 4928
#define ATT_F 7770

__global__ __launch_bounds__(128, 7)
void attn_kernel() {
    __shared__ float s[ATT_F];
    float* qs = s + AQS;
    float* kt = s + AKT;
    float* vs = s + AVS;
    float* sA = s + ASA;
    float* pt = s;   // overlaps qs/kt after P1

    const int tid  = threadIdx.x;
    const int lane = tid & 31;
    const int wid  = tid >> 5;
    const int h    = blockIdx.x;     // 0..5
    const int win  = blockIdx.y;     // 0..4095
    const int wsel = win & (NWIN - 1);
    const size_t tok0 = (size_t)win * 49;
    const float scale = 0.17677669529663687f;

    // ---- P0: stage q (scaled, [i][32]), k (transposed [d][56j]), v ([j][32]) ----
    for (int idx = tid; idx < 49 * 24; idx += 128) {
        int t = idx / 24, p = idx - t * 24;       // p: 0..7 q, 8..15 k, 16..23 v
        int sec = p >> 3, c4 = p & 7;
        float4 v = *(const float4*)(g_qkv + (tok0 + t) * 576 + sec * 192 + h * 32 + c4 * 4);
        if (sec == 0) {
            v.x *= scale; v.y *= scale; v.z *= scale; v.w *= scale;
            *(float4*)(qs + t * 32 + c4 * 4) = v;
        } else if (sec == 1) {
            int c = c4 * 4;
            kt[(c + 0) * 56 + t] = v.x;
            kt[(c + 1) * 56 + t] = v.y;
            kt[(c + 2) * 56 + t] = v.z;
            kt[(c + 3) * 56 + t] = v.w;
        } else {
            *(float4*)(vs + t * 32 + c4 * 4) = v;
        }
    }
    __syncthreads();

    // ---- P1: scores sA[i][j]; ONE task per warp: 13 rows (last: 10) ----
    {
        const int i0 = wid * 13;
        const int nrows = (i0 + 13 <= 49) ? 13 : (49 - i0);
        ull acc[13];
        #pragma unroll
        for (int ii = 0; ii < 13; ii++) acc[ii] = 0ULL;
        const float* qb = qs + i0 * 32;          // rows beyond 48 read junk; discarded
        const float* kb = kt + 2 * lane;
        #pragma unroll 2
        for (int dq = 0; dq < 8; dq++) {
            float2 k0 = *(const float2*)(kb + (4 * dq + 0) * 56);
            float2 k1 = *(const float2*)(kb + (4 * dq + 1) * 56);
            float2 k2 = *(const float2*)(kb + (4 * dq + 2) * 56);
            float2 k3 = *(const float2*)(kb + (4 * dq + 3) * 56);
            ull ku0 = pack2(k0.x, k0.y), ku1 = pack2(k1.x, k1.y);
            ull ku2 = pack2(k2.x, k2.y), ku3 = pack2(k3.x, k3.y);
            #pragma unroll
            for (int ii = 0; ii < 13; ii++) {
                float4 qf = *(const float4*)(qb + ii * 32 + 4 * dq);
                acc[ii] = fma2(pack2(qf.x, qf.x), ku0, acc[ii]);
                acc[ii] = fma2(pack2(qf.y, qf.y), ku1, acc[ii]);
                acc[ii] = fma2(pack2(qf.z, qf.z), ku2, acc[ii]);
                acc[ii] = fma2(pack2(qf.w, qf.w), ku3, acc[ii]);
            }
        }
        if (lane < 25) {
            int j0 = 2 * lane;
            const float* bmrow = g_bm + (size_t)((wsel * 6 + h) * 49 + i0) * 56 + j0;
            #pragma unroll
            for (int ii = 0; ii < 13; ii++) {
                if (ii < nrows) {
                    ull bm2 = *(const ull*)(bmrow + ii * 56);
                    *(ull*)(sA + (i0 + ii) * 58 + j0) = add2(acc[ii], bm2);
                }
            }
        }
    }
    __syncthreads();

    // ---- P2: softmax rows + transpose into pt[j][56i] ----
    if (tid < 49) {
        float* row = sA + tid * 58;
        float m = row[0];
        #pragma unroll 7
        for (int j = 1; j < 49; j++) m = fmaxf(m, row[j]);
        float sum = 0.f;
        #pragma unroll 7
        for (int j = 0; j < 49; j++) { float e = __expf(row[j] - m); row[j] = e; sum += e; }
        float inv = 1.f / sum;
        float* ptb = pt + tid;
        #pragma unroll 7
        for (int j = 0; j < 49; j++) ptb[j * 56] = row[j] * inv;
    }
    __syncthreads();

    // ---- P3: O = P @ V; tasks at i0 = wid*12 (16B-aligned), nrows 12/12/12/13 ----
    {
        const int i0 = wid * 12;
        const int nrows = (wid < 3) ? 12 : 13;
        ull acc[7] = {0ULL, 0ULL, 0ULL, 0ULL, 0ULL, 0ULL, 0ULL};
        const float* vp = vs + lane;
        const float* pb = pt + i0;
        #pragma unroll 7
        for (int j = 0; j < 49; j++) {
            float vvv = vp[j * 32];
            ull v2 = pack2(vvv, vvv);
            const float4* pr = (const float4*)(pb + j * 56);   // i0 mult of 4 -> aligned
            float4 a = pr[0], b = pr[1], c = pr[2];            // i0+11 <= 47 < 56
            float2 dlo = ((const float2*)pr)[6];               // rows i0+12..13 (<56)
            acc[0] = fma2(pack2(a.x, a.y), v2, acc[0]);
            acc[1] = fma2(pack2(a.z, a.w), v2, acc[1]);
            acc[2] = fma2(pack2(b.x, b.y), v2, acc[2]);
            acc[3] = fma2(pack2(b.z, b.w), v2, acc[3]);
            acc[4] = fma2(pack2(c.x, c.y), v2, acc[4]);
            acc[5] = fma2(pack2(c.z, c.w), v2, acc[5]);
            acc[6] = fma2(pack2(dlo.x, dlo.y), v2, acc[6]);
        }
        int cg = h * 32 + lane;
        #pragma unroll
        for (int p = 0; p < 7; p++) {
            float2 o = unp2(acc[p]);
            #pragma unroll
            for (int e = 0; e < 2; e++) {
                int ri = 2 * p + e;                 // row within task
                float ov = e ? o.y : o.x;
                if (ri < nrows) {
                    int iv = i0 + ri;
                    __nv_bfloat16 hi = __float2bfloat16(ov);
                    __nv_bfloat16 lo = __float2bfloat16(ov - __bfloat162float(hi));
                    size_t base = (tok0 + iv) * 384 + cg;
                    g_oe[base]       = hi;
                    g_oe[base + 192] = lo;
                }
            }
        }
    }
}

// ---------------- launch ----------------
extern "C" void kernel_launch(void* const* d_in, const int* in_sizes, int n_in,
                              void* d_out, int out_size) {
    const float* x          = (const float*)d_in[0];
    const float* mask       = (const float*)d_in[1];
    const float* qkv_w      = (const float*)d_in[2];
    const float* qkv_b      = (const float*)d_in[3];
    const float* proj_w     = (const float*)d_in[4];
    const float* proj_b     = (const float*)d_in[5];
    const float* bias_table = (const float*)d_in[6];
    const int*   rel_index  = (const int*)d_in[7];
    float* out = (float*)d_out;

    prep_kernel<<<120, 256>>>(qkv_w, proj_w, bias_table, rel_index, mask);
    xconv_kernel<<<(TOKS * 96) / 256, 256>>>(x);

    cudaFuncSetAttribute(gemm_mma, cudaFuncAttributeMaxDynamicSharedMemorySize, GSMEM);

    dim3 gq(9, TOKS / 128);
    gemm_mma<<<gq, 256, GSMEM>>>(qkv_b, nullptr, 0);   // QKV: N=576, n-tile fastest
    dim3 ga(6, 4096);
    attn_kernel<<<ga, 128>>>();                        // 24576 CTAs
    dim3 gp(3, TOKS / 128);
    gemm_mma<<<gp, 256, GSMEM>>>(proj_b, out, 1);      // proj: N=192
}

// round 10
// speedup vs baseline: 1.1050x; 1.1050x over previous
#include <cuda_runtime.h>
#include <cuda_bf16.h>
#include <cstdint>

typedef unsigned long long ull;
typedef uint32_t u32;

#define TOKS 200704          // 4096 windows * 49 tokens (= 1568 * 128)
#define NWIN 64
#define QSCALE 0.17677669529663687f

// ---------------- device scratch (zero-initialized at module load) ----------------
__device__ __nv_bfloat16 g_xe[(size_t)TOKS * 384];           // x split [t][hi|lo]
__device__ __nv_bfloat16 g_oe[(size_t)TOKS * 384];           // attn out split [hi|lo]
__device__ __nv_bfloat16 g_qke[(size_t)4096 * 6 * 49 * 64];  // q scaled, [win][h][i][qh(32)|ql(32)]
__device__ __nv_bfloat16 g_kke[(size_t)4096 * 6 * 49 * 64];  // k, [win][h][j][kh|kl]
__device__ __nv_bfloat16 g_vhe[(size_t)4096 * 6 * 32 * 64];  // v hi, [win][h][c][64j] (j>=49 stays 0)
__device__ __nv_bfloat16 g_vle[(size_t)4096 * 6 * 32 * 64];  // v lo
__device__ __nv_bfloat16 g_wqe[576 * 576];                   // qkv_w packed [n][wh|wl|wh]
__device__ __nv_bfloat16 g_wpe[192 * 576];                   // proj_w packed
__device__ float         g_bm[64 * 6 * 49 * 56];             // bias+mask, j padded to 56

__device__ __forceinline__ u32 smem_u32(const void* p) {
    u32 a;
    asm("{ .reg .u64 t; cvta.to.shared.u64 t, %1; cvt.u32.u64 %0, t; }" : "=r"(a) : "l"(p));
    return a;
}
__device__ __forceinline__ void cp16(u32 saddr, const void* gaddr) {
    asm volatile("cp.async.cg.shared.global [%0], [%1], 16;" :: "r"(saddr), "l"(gaddr));
}
__device__ __forceinline__ void ldm4(u32* r, u32 addr) {
    asm volatile("ldmatrix.sync.aligned.m8n8.x4.shared.b16 {%0,%1,%2,%3}, [%4];"
                 : "=r"(r[0]), "=r"(r[1]), "=r"(r[2]), "=r"(r[3]) : "r"(addr));
}
__device__ __forceinline__ void mma16816(float* d, const u32* a, u32 b0, u32 b1) {
    asm volatile("mma.sync.aligned.m16n8k16.row.col.f32.bf16.bf16.f32 "
                 "{%0,%1,%2,%3}, {%4,%5,%6,%7}, {%8,%9}, {%0,%1,%2,%3};"
                 : "+f"(d[0]), "+f"(d[1]), "+f"(d[2]), "+f"(d[3])
                 : "r"(a[0]), "r"(a[1]), "r"(a[2]), "r"(a[3]), "r"(b0), "r"(b1));
}
// pack two f32 into bf16x2: lo half = first arg
__device__ __forceinline__ u32 cvt2(float lo, float hi) {
    u32 r; asm("cvt.rn.bf16x2.f32 %0, %1, %2;" : "=r"(r) : "f"(hi), "f"(lo)); return r;
}
__device__ __forceinline__ float bflo(u32 p) { return __uint_as_float(p << 16); }
__device__ __forceinline__ float bfhi(u32 p) { return __uint_as_float(p & 0xFFFF0000u); }

// ---------------- prep: split-pack weights + combine bias/mask ----------------
__global__ void prep_kernel(const float* __restrict__ qkv_w, const float* __restrict__ proj_w,
                            const float* __restrict__ bias_table, const int* __restrict__ rel_index,
                            const float* __restrict__ mask) {
    int tid = blockIdx.x * blockDim.x + threadIdx.x;
    int stride = gridDim.x * blockDim.x;
    for (int i = tid; i < 576 * 192; i += stride) {
        int n = i / 192, k = i - n * 192;
        float w = qkv_w[i];
        __nv_bfloat16 h = __float2bfloat16(w);
        __nv_bfloat16 l = __float2bfloat16(w - __bfloat162float(h));
        g_wqe[(size_t)n * 576 + k]       = h;
        g_wqe[(size_t)n * 576 + 192 + k] = l;
        g_wqe[(size_t)n * 576 + 384 + k] = h;
    }
    for (int i = tid; i < 192 * 192; i += stride) {
        int n = i / 192, k = i - n * 192;
        float w = proj_w[i];
        __nv_bfloat16 h = __float2bfloat16(w);
        __nv_bfloat16 l = __float2bfloat16(w - __bfloat162float(h));
        g_wpe[(size_t)n * 576 + k]       = h;
        g_wpe[(size_t)n * 576 + 192 + k] = l;
        g_wpe[(size_t)n * 576 + 384 + k] = h;
    }
    for (int i = tid; i < 64 * 6 * 49 * 56; i += stride) {
        int j = i % 56; int rest = i / 56;
        int ir = rest % 49; rest /= 49;
        int hh = rest % 6; int wm = rest / 6;
        float v = 0.f;
        if (j < 49)
            v = bias_table[rel_index[ir * 49 + j] * 6 + hh] + mask[wm * 2401 + ir * 49 + j];
        g_bm[i] = v;
    }
}

// ---------------- x -> bf16 split [hi|lo] (384 wide) ----------------
__global__ void xconv_kernel(const float* __restrict__ x) {
    size_t idx = (size_t)blockIdx.x * 256 + threadIdx.x;
    size_t t = idx / 96;
    int p = (int)(idx - t * 96);
    float2 v = *(const float2*)(x + t * 192 + 2 * p);
    __nv_bfloat16 h0 = __float2bfloat16(v.x), h1 = __float2bfloat16(v.y);
    __nv_bfloat16 l0 = __float2bfloat16(v.x - __bfloat162float(h0));
    __nv_bfloat16 l1 = __float2bfloat16(v.y - __bfloat162float(h1));
    __nv_bfloat162 hp; hp.x = h0; hp.y = h1;
    __nv_bfloat162 lp; lp.x = l0; lp.y = l1;
    size_t base = t * 384 + 2 * p;
    *(__nv_bfloat162*)(g_xe + base)       = hp;
    *(__nv_bfloat162*)(g_xe + base + 192) = lp;
}

// ---------------- mma.sync GEMM, 3-stage cp.async pipeline ----------------
// which=0: A=g_xe, W=g_wqe; epilogue writes split-bf16 q/k/v layouts for attn.
// which=1: A=g_oe, W=g_wpe; epilogue writes fp32 out.
#define GSMEM 73728

__global__ __launch_bounds__(256, 2)
void gemm_mma(const float* __restrict__ bias, float* __restrict__ out_param, int which) {
    extern __shared__ char sm[];
    const __nv_bfloat16* Ae = which ? g_oe : g_xe;
    const __nv_bfloat16* We = which ? g_wpe : g_wqe;
    const int Ncols = which ? 192 : 576;

    const u32 sb = smem_u32(sm);
    const int tid  = threadIdx.x;
    const int lane = tid & 31;
    const int wid  = tid >> 5;
    const int wm   = wid >> 1;
    const int wn   = wid & 1;
    const size_t row0 = (size_t)blockIdx.y * 128;
    const int    n0   = blockIdx.x * 64;

    float acc[2][4][4];
    #pragma unroll
    for (int mt = 0; mt < 2; mt++)
        #pragma unroll
        for (int nt = 0; nt < 4; nt++)
            #pragma unroll
            for (int q = 0; q < 4; q++) acc[mt][nt][q] = 0.f;

    auto load_chunk = [&](int kc, int buf) {
        int aoff = (kc < 3) ? kc * 64 : (kc < 6 ? (kc - 3) * 64 : (kc - 6) * 64 + 192);
        const u32 sA = sb + (u32)buf * 16384u;
        const u32 sB = sb + 49152u + (u32)buf * 8192u;
        #pragma unroll
        for (int s = 0; s < 6; s++) {
            int j = tid + s * 256;
            if (j < 1024) {
                int r = j >> 3, c = j & 7;
                u32 saddr = sA + (u32)r * 128u + (u32)((c ^ (r & 7)) << 4);
                cp16(saddr, Ae + (row0 + r) * 384 + aoff + c * 8);
            } else {
                int jj = j - 1024;
                int r = jj >> 3, c = jj & 7;
                u32 saddr = sB + (u32)r * 128u + (u32)((c ^ (r & 7)) << 4);
                cp16(saddr, We + (size_t)(n0 + r) * 576 + kc * 64 + c * 8);
            }
        }
        asm volatile("cp.async.commit_group;" ::: "memory");
    };

    load_chunk(0, 0);
    load_chunk(1, 1);

    #pragma unroll 1
    for (int kc = 0; kc < 9; kc++) {
        if (kc < 8) asm volatile("cp.async.wait_group 1;" ::: "memory");
        else        asm volatile("cp.async.wait_group 0;" ::: "memory");
        __syncthreads();
        if (kc + 2 < 9) load_chunk(kc + 2, (kc + 2) % 3);

        const int buf = kc % 3;
        const u32 sA = sb + (u32)buf * 16384u;
        const u32 sB = sb + 49152u + (u32)buf * 8192u;

        #pragma unroll
        for (int ks = 0; ks < 4; ks++) {
            u32 afr[2][4], bfr[2][4];
            #pragma unroll
            for (int mt = 0; mt < 2; mt++) {
                int row = wm * 32 + mt * 16 + (lane & 15);
                int c   = ks * 2 + (lane >> 4);
                ldm4(afr[mt], sA + (u32)row * 128u + (u32)((c ^ (row & 7)) << 4));
            }
            #pragma unroll
            for (int np = 0; np < 2; np++) {
                int brow = wn * 32 + np * 16 + (lane & 7) + ((lane >> 4) & 1) * 8;
                int c    = ks * 2 + ((lane >> 3) & 1);
                ldm4(bfr[np], sB + (u32)brow * 128u + (u32)((c ^ (brow & 7)) << 4));
            }
            #pragma unroll
            for (int mt = 0; mt < 2; mt++)
                #pragma unroll
                for (int nt = 0; nt < 4; nt++)
                    mma16816(acc[mt][nt], afr[mt], bfr[nt >> 1][(nt & 1) * 2], bfr[nt >> 1][(nt & 1) * 2 + 1]);
        }
        __syncthreads();
    }

    const int tr = lane >> 2, tc = (lane & 3) * 2;
    if (which) {
        #pragma unroll
        for (int mt = 0; mt < 2; mt++)
            #pragma unroll
            for (int nt = 0; nt < 4; nt++) {
                int col = n0 + wn * 32 + nt * 8 + tc;
                float b0 = bias[col], b1 = bias[col + 1];
                size_t r_lo = row0 + wm * 32 + mt * 16 + tr;
                float2 v0; v0.x = acc[mt][nt][0] + b0; v0.y = acc[mt][nt][1] + b1;
                float2 v1; v1.x = acc[mt][nt][2] + b0; v1.y = acc[mt][nt][3] + b1;
                *(float2*)(out_param + r_lo * Ncols + col)       = v0;
                *(float2*)(out_param + (r_lo + 8) * Ncols + col) = v1;
            }
    } else {
        const int sec = n0 / 192;   // 0=q, 1=k, 2=v (64-tile never spans sections)
        #pragma unroll
        for (int mt = 0; mt < 2; mt++)
            #pragma unroll
            for (int nt = 0; nt < 4; nt++) {
                int col = n0 + wn * 32 + nt * 8 + tc;
                int hh  = (col % 192) >> 5;
                int d   = col & 31;
                float b0 = bias[col], b1 = bias[col + 1];
                #pragma unroll
                for (int half = 0; half < 2; half++) {
                    u32 r = (u32)(row0 + wm * 32 + mt * 16 + tr + half * 8);
                    float x0 = acc[mt][nt][half * 2 + 0] + b0;
                    float x1 = acc[mt][nt][half * 2 + 1] + b1;
                    if (sec == 0) { x0 *= QSCALE; x1 *= QSCALE; }
                    u32 win = r / 49u, i = r - win * 49u;
                    u32 hp = cvt2(x0, x1);
                    u32 lp = cvt2(x0 - bflo(hp), x1 - bfhi(hp));
                    if (sec < 2) {
                        __nv_bfloat16* base = (sec == 0 ? g_qke : g_kke)
                            + (((size_t)win * 6 + hh) * 49 + i) * 64 + d;
                        *(u32*)(base)      = hp;
                        *(u32*)(base + 32) = lp;
                    } else {
                        size_t vb = (((size_t)win * 6 + hh) * 32 + d) * 64 + i;
                        __nv_bfloat16 h0 = __float2bfloat16(x0);
                        __nv_bfloat16 h1 = __float2bfloat16(x1);
                        g_vhe[vb]      = h0;
                        g_vhe[vb + 64] = h1;
                        g_vle[vb]      = __float2bfloat16(x0 - __bfloat162float(h0));
                        g_vle[vb + 64] = __float2bfloat16(x1 - __bfloat162float(h1));
                    }
                }
            }
    }
}

// ---------------- attention: tensor-core QK^T and P@V, softmax in registers ----
// One CTA per window, 128 threads, 6 heads sequential.
// smem tiles (128B rows, swizzle c^(r&7)): qe[64][64] 8K, ke[64][64] 8K,
// vh[32][64] 4K, vl[32][64] 4K. k rows >=49 zeroed once; v cols j>=49 are
// zero from global zero-init.
__global__ __launch_bounds__(128, 4)
void attn_kernel() {
    __shared__ __align__(16) char smbuf[24576];
    const u32 sq  = smem_u32(smbuf);
    const u32 sk  = sq + 8192u;
    const u32 svh = sq + 16384u;
    const u32 svl = sq + 20480u;

    const int tid  = threadIdx.x;
    const int lane = tid & 31;
    const int wid  = tid >> 5;
    const int win  = blockIdx.x;
    const int wsel = win & (NWIN - 1);
    const size_t tok0 = (size_t)win * 49;

    // zero k rows 49..63 once
    {
        float4 z = make_float4(0.f, 0.f, 0.f, 0.f);
        for (int idx = tid; idx < 15 * 8; idx += 128) {
            int r = 49 + (idx >> 3), ch = idx & 7;
            *(float4*)(smbuf + 8192 + r * 128 + ((ch ^ (r & 7)) << 4)) = z;
        }
    }

    const int tcq = 2 * (lane & 3);
    const int r0  = wid * 16 + (lane >> 2);   // acc row (low half); +8 for high

    for (int h = 0; h < 6; h++) {
        __syncthreads();   // prior head's reads done before overwrite
        // ---- stage q,k (49 rows x 8 chunks) and vh,vl (32 rows x 8 chunks) ----
        {
            const size_t qb = ((size_t)win * 6 + h) * 49 * 64;
            for (int idx = tid; idx < 392; idx += 128) {
                int r = idx >> 3, ch = idx & 7;
                u32 off = (u32)(r * 128 + ((ch ^ (r & 7)) << 4));
                *(float4*)(smbuf + off)        = *(const float4*)(g_qke + qb + r * 64 + ch * 8);
                *(float4*)(smbuf + 8192 + off) = *(const float4*)(g_kke + qb + r * 64 + ch * 8);
            }
            const size_t vb = ((size_t)win * 6 + h) * 32 * 64;
            for (int idx = tid; idx < 256; idx += 128) {
                int c = idx >> 3, ch = idx & 7;
                u32 off = (u32)(c * 128 + ((ch ^ (c & 7)) << 4));
                *(float4*)(smbuf + 16384 + off) = *(const float4*)(g_vhe + vb + c * 64 + ch * 8);
                *(float4*)(smbuf + 20480 + off) = *(const float4*)(g_vle + vb + c * 64 + ch * 8);
            }
        }
        __syncthreads();

        // ---- A fragments for q (4 k-steps: 0,1 = qh; 2,3 = ql) ----
        u32 aq[4][4];
        {
            int row = wid * 16 + (lane & 15);
            #pragma unroll
            for (int s = 0; s < 4; s++) {
                int c = s * 2 + (lane >> 4);
                ldm4(aq[s], sq + (u32)(row * 128 + ((c ^ (row & 7)) << 4)));
            }
        }

        // ---- QK^T: 3-term split via fragment re-pairing ----
        float sc[8][4];
        #pragma unroll
        for (int nt = 0; nt < 8; nt++)
            #pragma unroll
            for (int q = 0; q < 4; q++) sc[nt][q] = 0.f;
        {
            const int pa[6] = {0, 1, 0, 1, 2, 3};   // A k-steps
            const int pb[6] = {0, 1, 2, 3, 0, 1};   // B k-steps: hh, hl, lh
            #pragma unroll
            for (int vs = 0; vs < 6; vs++) {
                #pragma unroll
                for (int np = 0; np < 4; np++) {
                    u32 bk[4];
                    int brow = np * 16 + (lane & 7) + ((lane >> 4) & 1) * 8;
                    int c    = pb[vs] * 2 + ((lane >> 3) & 1);
                    ldm4(bk, sk + (u32)(brow * 128 + ((c ^ (brow & 7)) << 4)));
                    mma16816(sc[np * 2],     aq[pa[vs]], bk[0], bk[1]);
                    mma16816(sc[np * 2 + 1], aq[pa[vs]], bk[2], bk[3]);
                }
            }
        }

        // ---- bias+mask, masking, softmax (register + quad shfl) ----
        const float* bmb = g_bm + ((size_t)(wsel * 6 + h) * 49) * 56;
        float m0 = -1e30f, m1 = -1e30f;
        #pragma unroll
        for (int nt = 0; nt < 8; nt++) {
            int c0 = nt * 8 + tcq;
            bool k0 = (c0 < 49), k1 = (c0 + 1 < 49);
            float2 bm0 = make_float2(0.f, 0.f), bm1 = make_float2(0.f, 0.f);
            if (k0 && r0 < 49)     bm0 = *(const float2*)(bmb + r0 * 56 + c0);
            if (k0 && r0 + 8 < 49) bm1 = *(const float2*)(bmb + (r0 + 8) * 56 + c0);
            sc[nt][0] = k0 ? sc[nt][0] + bm0.x : -1e30f;
            sc[nt][1] = k1 ? sc[nt][1] + bm0.y : -1e30f;
            sc[nt][2] = k0 ? sc[nt][2] + bm1.x : -1e30f;
            sc[nt][3] = k1 ? sc[nt][3] + bm1.y : -1e30f;
            m0 = fmaxf(m0, fmaxf(sc[nt][0], sc[nt][1]));
            m1 = fmaxf(m1, fmaxf(sc[nt][2], sc[nt][3]));
        }
        m0 = fmaxf(m0, __shfl_xor_sync(0xFFFFFFFFu, m0, 1));
        m0 = fmaxf(m0, __shfl_xor_sync(0xFFFFFFFFu, m0, 2));
        m1 = fmaxf(m1, __shfl_xor_sync(0xFFFFFFFFu, m1, 1));
        m1 = fmaxf(m1, __shfl_xor_sync(0xFFFFFFFFu, m1, 2));
        float s0 = 0.f, s1 = 0.f;
        #pragma unroll
        for (int nt = 0; nt < 8; nt++) {
            sc[nt][0] = __expf(sc[nt][0] - m0); s0 += sc[nt][0];
            sc[nt][1] = __expf(sc[nt][1] - m0); s0 += sc[nt][1];
            sc[nt][2] = __expf(sc[nt][2] - m1); s1 += sc[nt][2];
            sc[nt][3] = __expf(sc[nt][3] - m1); s1 += sc[nt][3];
        }
        s0 += __shfl_xor_sync(0xFFFFFFFFu, s0, 1);
        s0 += __shfl_xor_sync(0xFFFFFFFFu, s0, 2);
        s1 += __shfl_xor_sync(0xFFFFFFFFu, s1, 1);
        s1 += __shfl_xor_sync(0xFFFFFFFFu, s1, 2);
        float inv0 = 1.f / s0, inv1 = 1.f / s1;

        // ---- convert probs -> A-fragments (acc layout == A-frag layout) ----
        u32 ph[4][4], pl[4][4];
        #pragma unroll
        for (int s = 0; s < 4; s++) {
            float p00 = sc[2 * s][0] * inv0,     p01 = sc[2 * s][1] * inv0;
            float p10 = sc[2 * s][2] * inv1,     p11 = sc[2 * s][3] * inv1;
            float p20 = sc[2 * s + 1][0] * inv0, p21 = sc[2 * s + 1][1] * inv0;
            float p30 = sc[2 * s + 1][2] * inv1, p31 = sc[2 * s + 1][3] * inv1;
            ph[s][0] = cvt2(p00, p01); pl[s][0] = cvt2(p00 - bflo(ph[s][0]), p01 - bfhi(ph[s][0]));
            ph[s][1] = cvt2(p10, p11); pl[s][1] = cvt2(p10 - bflo(ph[s][1]), p11 - bfhi(ph[s][1]));
            ph[s][2] = cvt2(p20, p21); pl[s][2] = cvt2(p20 - bflo(ph[s][2]), p21 - bfhi(ph[s][2]));
            ph[s][3] = cvt2(p30, p31); pl[s][3] = cvt2(p30 - bflo(ph[s][3]), p31 - bfhi(ph[s][3]));
        }

        // ---- P @ V: terms (Ph,Vh), (Ph,Vl), (Pl,Vh) ----
        float ov[4][4];
        #pragma unroll
        for (int nt = 0; nt < 4; nt++)
            #pragma unroll
            for (int q = 0; q < 4; q++) ov[nt][q] = 0.f;
        #pragma unroll
        for (int term = 0; term < 3; term++) {
            const u32 (*pa)[4] = (term == 2) ? pl : ph;
            const u32 vbase = (term == 1) ? svl : svh;
            #pragma unroll
            for (int s = 0; s < 4; s++) {
                #pragma unroll
                for (int np = 0; np < 2; np++) {
                    u32 bv[4];
                    int brow = np * 16 + (lane & 7) + ((lane >> 4) & 1) * 8;
                    int c    = s * 2 + ((lane >> 3) & 1);
                    ldm4(bv, vbase + (u32)(brow * 128 + ((c ^ (brow & 7)) << 4)));
                    mma16816(ov[np * 2],     pa[s], bv[0], bv[1]);
                    mma16816(ov[np * 2 + 1], pa[s], bv[2], bv[3]);
                }
            }
        }

        // ---- store o (split bf16) to g_oe ----
        #pragma unroll
        for (int nt = 0; nt < 4; nt++) {
            int c0 = nt * 8 + tcq;
            #pragma unroll
            for (int half = 0; half < 2; half++) {
                int iv = r0 + half * 8;
                if (iv < 49) {
                    float x0 = ov[nt][half * 2 + 0];
                    float x1 = ov[nt][half * 2 + 1];
                    u32 hp = cvt2(x0, x1);
                    u32 lp = cvt2(x0 - bflo(hp), x1 - bfhi(hp));
                    __nv_bfloat16* base = g_oe + (tok0 + iv) * 384 + h * 32 + c0;
                    *(u32*)(base)       = hp;
                    *(u32*)(base + 192) = lp;
                }
            }
        }
    }
}

// ---------------- launch ----------------
extern "C" void kernel_launch(void* const* d_in, const int* in_sizes, int n_in,
                              void* d_out, int out_size) {
    const float* x          = (const float*)d_in[0];
    const float* mask       = (const float*)d_in[1];
    const float* qkv_w      = (const float*)d_in[2];
    const float* qkv_b      = (const float*)d_in[3];
    const float* proj_w     = (const float*)d_in[4];
    const float* proj_b     = (const float*)d_in[5];
    const float* bias_table = (const float*)d_in[6];
    const int*   rel_index  = (const int*)d_in[7];
    float* out = (float*)d_out;

    prep_kernel<<<120, 256>>>(qkv_w, proj_w, bias_table, rel_index, mask);
    xconv_kernel<<<(TOKS * 96) / 256, 256>>>(x);

    cudaFuncSetAttribute(gemm_mma, cudaFuncAttributeMaxDynamicSharedMemorySize, GSMEM);

    dim3 gq(9, TOKS / 128);
    gemm_mma<<<gq, 256, GSMEM>>>(qkv_b, nullptr, 0);   // QKV -> split q/k/v layouts
    attn_kernel<<<4096, 128>>>();                       // one CTA per window
    dim3 gp(3, TOKS / 128);
    gemm_mma<<<gp, 256, GSMEM>>>(proj_b, out, 1);       // proj: N=192
}

// round 11
// speedup vs baseline: 1.2329x; 1.1157x over previous
#include <cuda_runtime.h>
#include <cuda_bf16.h>
#include <cstdint>

typedef unsigned long long ull;
typedef uint32_t u32;

#define TOKS 200704          // 4096 windows * 49 tokens (= 1568 * 128)
#define NWIN 64
#define QSCALE 0.17677669529663687f

// ---------------- device scratch (zero-initialized at module load) ----------------
__device__ __nv_bfloat16 g_xe[(size_t)TOKS * 384];           // x split [t][hi|lo]
__device__ __nv_bfloat16 g_oe[(size_t)TOKS * 384];           // attn out split [hi|lo]
__device__ __nv_bfloat16 g_qke[(size_t)4096 * 6 * 49 * 64];  // q scaled, [win][h][i][qh(32)|ql(32)]
__device__ __nv_bfloat16 g_kke[(size_t)4096 * 6 * 49 * 64];  // k, [win][h][j][kh|kl]
__device__ __nv_bfloat16 g_vhe[(size_t)4096 * 6 * 32 * 64];  // v hi, [win][h][c][64j] (j>=49 stays 0)
__device__ __nv_bfloat16 g_vle[(size_t)4096 * 6 * 32 * 64];  // v lo
__device__ __nv_bfloat16 g_wqe[576 * 576];                   // qkv_w packed [n][wh|wl|wh]
__device__ __nv_bfloat16 g_wpe[192 * 576];                   // proj_w packed
__device__ float         g_bm[64 * 6 * 49 * 56];             // bias+mask, j padded to 56

__device__ __forceinline__ u32 smem_u32(const void* p) {
    u32 a;
    asm("{ .reg .u64 t; cvta.to.shared.u64 t, %1; cvt.u32.u64 %0, t; }" : "=r"(a) : "l"(p));
    return a;
}
__device__ __forceinline__ void cp16(u32 saddr, const void* gaddr) {
    asm volatile("cp.async.cg.shared.global [%0], [%1], 16;" :: "r"(saddr), "l"(gaddr));
}
__device__ __forceinline__ void ldm4(u32* r, u32 addr) {
    asm volatile("ldmatrix.sync.aligned.m8n8.x4.shared.b16 {%0,%1,%2,%3}, [%4];"
                 : "=r"(r[0]), "=r"(r[1]), "=r"(r[2]), "=r"(r[3]) : "r"(addr));
}
__device__ __forceinline__ void mma16816(float* d, const u32* a, u32 b0, u32 b1) {
    asm volatile("mma.sync.aligned.m16n8k16.row.col.f32.bf16.bf16.f32 "
                 "{%0,%1,%2,%3}, {%4,%5,%6,%7}, {%8,%9}, {%0,%1,%2,%3};"
                 : "+f"(d[0]), "+f"(d[1]), "+f"(d[2]), "+f"(d[3])
                 : "r"(a[0]), "r"(a[1]), "r"(a[2]), "r"(a[3]), "r"(b0), "r"(b1));
}
// pack two f32 into bf16x2: lo half = first arg
__device__ __forceinline__ u32 cvt2(float lo, float hi) {
    u32 r; asm("cvt.rn.bf16x2.f32 %0, %1, %2;" : "=r"(r) : "f"(hi), "f"(lo)); return r;
}
__device__ __forceinline__ float bflo(u32 p) { return __uint_as_float(p << 16); }
__device__ __forceinline__ float bfhi(u32 p) { return __uint_as_float(p & 0xFFFF0000u); }

// ---------------- prep: split-pack weights + combine bias/mask ----------------
__global__ void prep_kernel(const float* __restrict__ qkv_w, const float* __restrict__ proj_w,
                            const float* __restrict__ bias_table, const int* __restrict__ rel_index,
                            const float* __restrict__ mask) {
    int tid = blockIdx.x * blockDim.x + threadIdx.x;
    int stride = gridDim.x * blockDim.x;
    for (int i = tid; i < 576 * 192; i += stride) {
        int n = i / 192, k = i - n * 192;
        float w = qkv_w[i];
        __nv_bfloat16 h = __float2bfloat16(w);
        __nv_bfloat16 l = __float2bfloat16(w - __bfloat162float(h));
        g_wqe[(size_t)n * 576 + k]       = h;
        g_wqe[(size_t)n * 576 + 192 + k] = l;
        g_wqe[(size_t)n * 576 + 384 + k] = h;
    }
    for (int i = tid; i < 192 * 192; i += stride) {
        int n = i / 192, k = i - n * 192;
        float w = proj_w[i];
        __nv_bfloat16 h = __float2bfloat16(w);
        __nv_bfloat16 l = __float2bfloat16(w - __bfloat162float(h));
        g_wpe[(size_t)n * 576 + k]       = h;
        g_wpe[(size_t)n * 576 + 192 + k] = l;
        g_wpe[(size_t)n * 576 + 384 + k] = h;
    }
    for (int i = tid; i < 64 * 6 * 49 * 56; i += stride) {
        int j = i % 56; int rest = i / 56;
        int ir = rest % 49; rest /= 49;
        int hh = rest % 6; int wm = rest / 6;
        float v = 0.f;
        if (j < 49)
            v = bias_table[rel_index[ir * 49 + j] * 6 + hh] + mask[wm * 2401 + ir * 49 + j];
        g_bm[i] = v;
    }
}

// ---------------- x -> bf16 split [hi|lo] (384 wide) ----------------
__global__ void xconv_kernel(const float* __restrict__ x) {
    size_t idx = (size_t)blockIdx.x * 256 + threadIdx.x;
    size_t t = idx / 96;
    int p = (int)(idx - t * 96);
    float2 v = *(const float2*)(x + t * 192 + 2 * p);
    __nv_bfloat16 h0 = __float2bfloat16(v.x), h1 = __float2bfloat16(v.y);
    __nv_bfloat16 l0 = __float2bfloat16(v.x - __bfloat162float(h0));
    __nv_bfloat16 l1 = __float2bfloat16(v.y - __bfloat162float(h1));
    __nv_bfloat162 hp; hp.x = h0; hp.y = h1;
    __nv_bfloat162 lp; lp.x = l0; lp.y = l1;
    size_t base = t * 384 + 2 * p;
    *(__nv_bfloat162*)(g_xe + base)       = hp;
    *(__nv_bfloat162*)(g_xe + base + 192) = lp;
}

// ---------------- mma.sync GEMM, 3-stage cp.async pipeline ----------------
// which=0: A=g_xe, W=g_wqe; epilogue writes split-bf16 q/k/v layouts for attn.
// which=1: A=g_oe, W=g_wpe; epilogue writes fp32 out.
#define GSMEM 73728

__global__ __launch_bounds__(256, 2)
void gemm_mma(const float* __restrict__ bias, float* __restrict__ out_param, int which) {
    extern __shared__ char sm[];
    const __nv_bfloat16* Ae = which ? g_oe : g_xe;
    const __nv_bfloat16* We = which ? g_wpe : g_wqe;
    const int Ncols = which ? 192 : 576;

    const u32 sb = smem_u32(sm);
    const int tid  = threadIdx.x;
    const int lane = tid & 31;
    const int wid  = tid >> 5;
    const int wm   = wid >> 1;
    const int wn   = wid & 1;
    const size_t row0 = (size_t)blockIdx.y * 128;
    const int    n0   = blockIdx.x * 64;

    float acc[2][4][4];
    #pragma unroll
    for (int mt = 0; mt < 2; mt++)
        #pragma unroll
        for (int nt = 0; nt < 4; nt++)
            #pragma unroll
            for (int q = 0; q < 4; q++) acc[mt][nt][q] = 0.f;

    auto load_chunk = [&](int kc, int buf) {
        int aoff = (kc < 3) ? kc * 64 : (kc < 6 ? (kc - 3) * 64 : (kc - 6) * 64 + 192);
        const u32 sA = sb + (u32)buf * 16384u;
        const u32 sB = sb + 49152u + (u32)buf * 8192u;
        #pragma unroll
        for (int s = 0; s < 6; s++) {
            int j = tid + s * 256;
            if (j < 1024) {
                int r = j >> 3, c = j & 7;
                u32 saddr = sA + (u32)r * 128u + (u32)((c ^ (r & 7)) << 4);
                cp16(saddr, Ae + (row0 + r) * 384 + aoff + c * 8);
            } else {
                int jj = j - 1024;
                int r = jj >> 3, c = jj & 7;
                u32 saddr = sB + (u32)r * 128u + (u32)((c ^ (r & 7)) << 4);
                cp16(saddr, We + (size_t)(n0 + r) * 576 + kc * 64 + c * 8);
            }
        }
        asm volatile("cp.async.commit_group;" ::: "memory");
    };

    load_chunk(0, 0);
    load_chunk(1, 1);

    #pragma unroll 1
    for (int kc = 0; kc < 9; kc++) {
        if (kc < 8) asm volatile("cp.async.wait_group 1;" ::: "memory");
        else        asm volatile("cp.async.wait_group 0;" ::: "memory");
        __syncthreads();
        if (kc + 2 < 9) load_chunk(kc + 2, (kc + 2) % 3);

        const int buf = kc % 3;
        const u32 sA = sb + (u32)buf * 16384u;
        const u32 sB = sb + 49152u + (u32)buf * 8192u;

        #pragma unroll
        for (int ks = 0; ks < 4; ks++) {
            u32 afr[2][4], bfr[2][4];
            #pragma unroll
            for (int mt = 0; mt < 2; mt++) {
                int row = wm * 32 + mt * 16 + (lane & 15);
                int c   = ks * 2 + (lane >> 4);
                ldm4(afr[mt], sA + (u32)row * 128u + (u32)((c ^ (row & 7)) << 4));
            }
            #pragma unroll
            for (int np = 0; np < 2; np++) {
                int brow = wn * 32 + np * 16 + (lane & 7) + ((lane >> 4) & 1) * 8;
                int c    = ks * 2 + ((lane >> 3) & 1);
                ldm4(bfr[np], sB + (u32)brow * 128u + (u32)((c ^ (brow & 7)) << 4));
            }
            #pragma unroll
            for (int mt = 0; mt < 2; mt++)
                #pragma unroll
                for (int nt = 0; nt < 4; nt++)
                    mma16816(acc[mt][nt], afr[mt], bfr[nt >> 1][(nt & 1) * 2], bfr[nt >> 1][(nt & 1) * 2 + 1]);
        }
        __syncthreads();
    }

    const int tr = lane >> 2, tc = (lane & 3) * 2;
    if (which) {
        #pragma unroll
        for (int mt = 0; mt < 2; mt++)
            #pragma unroll
            for (int nt = 0; nt < 4; nt++) {
                int col = n0 + wn * 32 + nt * 8 + tc;
                float b0 = bias[col], b1 = bias[col + 1];
                size_t r_lo = row0 + wm * 32 + mt * 16 + tr;
                float2 v0; v0.x = acc[mt][nt][0] + b0; v0.y = acc[mt][nt][1] + b1;
                float2 v1; v1.x = acc[mt][nt][2] + b0; v1.y = acc[mt][nt][3] + b1;
                *(float2*)(out_param + r_lo * Ncols + col)       = v0;
                *(float2*)(out_param + (r_lo + 8) * Ncols + col) = v1;
            }
    } else {
        const int sec = n0 / 192;   // 0=q, 1=k, 2=v (64-tile never spans sections)
        #pragma unroll
        for (int mt = 0; mt < 2; mt++)
            #pragma unroll
            for (int nt = 0; nt < 4; nt++) {
                int col = n0 + wn * 32 + nt * 8 + tc;
                int hh  = (col % 192) >> 5;
                int d   = col & 31;
                float b0 = bias[col], b1 = bias[col + 1];
                #pragma unroll
                for (int half = 0; half < 2; half++) {
                    u32 r = (u32)(row0 + wm * 32 + mt * 16 + tr + half * 8);
                    float x0 = acc[mt][nt][half * 2 + 0] + b0;
                    float x1 = acc[mt][nt][half * 2 + 1] + b1;
                    if (sec == 0) { x0 *= QSCALE; x1 *= QSCALE; }
                    u32 win = r / 49u, i = r - win * 49u;
                    u32 hp = cvt2(x0, x1);
                    u32 lp = cvt2(x0 - bflo(hp), x1 - bfhi(hp));
                    if (sec < 2) {
                        __nv_bfloat16* base = (sec == 0 ? g_qke : g_kke)
                            + (((size_t)win * 6 + hh) * 49 + i) * 64 + d;
                        *(u32*)(base)      = hp;
                        *(u32*)(base + 32) = lp;
                    } else {
                        size_t vb = (((size_t)win * 6 + hh) * 32 + d) * 64 + i;
                        __nv_bfloat16 h0 = __float2bfloat16(x0);
                        __nv_bfloat16 h1 = __float2bfloat16(x1);
                        g_vhe[vb]      = h0;
                        g_vhe[vb + 64] = h1;
                        g_vle[vb]      = __float2bfloat16(x0 - __bfloat162float(h0));
                        g_vle[vb + 64] = __float2bfloat16(x1 - __bfloat162float(h1));
                    }
                }
            }
    }
}

// ---------------- attention: tensor-core QK^T and P@V, softmax in registers ----
// One CTA per window, 128 threads, 6 heads sequential with cp.async
// double-buffered staging (2 x 24 KB buffers = 48 KB static smem, 4 CTAs/SM).
// Per buffer: qe[64][64] @0 (8K), ke[64][64] @8K, vh[32][64] @16K, vl[32][64] @20K.
#define HBUF 24576

__global__ __launch_bounds__(128, 4)
void attn_kernel() {
    __shared__ __align__(16) char smbuf[2 * HBUF];
    const u32 sbase = smem_u32(smbuf);

    const int tid  = threadIdx.x;
    const int lane = tid & 31;
    const int wid  = tid >> 5;
    const int win  = blockIdx.x;
    const int wsel = win & (NWIN - 1);
    const size_t tok0 = (size_t)win * 49;

    // zero k pad rows (49..63) in BOTH buffers once (staging never writes them)
    {
        float4 z = make_float4(0.f, 0.f, 0.f, 0.f);
        #pragma unroll
        for (int b = 0; b < 2; b++)
            for (int idx = tid; idx < 15 * 8; idx += 128) {
                int r = 49 + (idx >> 3), ch = idx & 7;
                *(float4*)(smbuf + b * HBUF + 8192 + r * 128 + ((ch ^ (r & 7)) << 4)) = z;
            }
    }

    auto stage = [&](int h, int buf) {
        const u32 sq = sbase + (u32)buf * HBUF;
        const size_t qb = ((size_t)win * 6 + h) * 49 * 64;
        for (int idx = tid; idx < 392; idx += 128) {
            int r = idx >> 3, ch = idx & 7;
            u32 off = (u32)(r * 128 + ((ch ^ (r & 7)) << 4));
            cp16(sq + off,         g_qke + qb + r * 64 + ch * 8);
            cp16(sq + 8192u + off, g_kke + qb + r * 64 + ch * 8);
        }
        const size_t vb = ((size_t)win * 6 + h) * 32 * 64;
        for (int idx = tid; idx < 256; idx += 128) {
            int c = idx >> 3, ch = idx & 7;
            u32 off = (u32)(c * 128 + ((ch ^ (c & 7)) << 4));
            cp16(sq + 16384u + off, g_vhe + vb + c * 64 + ch * 8);
            cp16(sq + 20480u + off, g_vle + vb + c * 64 + ch * 8);
        }
        asm volatile("cp.async.commit_group;" ::: "memory");
    };

    const int tcq = 2 * (lane & 3);
    const int r0  = wid * 16 + (lane >> 2);   // acc row (low half); +8 for high

    stage(0, 0);

    #pragma unroll 1
    for (int h = 0; h < 6; h++) {
        __syncthreads();                       // all done reading buf (h+1)&1 (head h-1)
        if (h < 5) stage(h + 1, (h + 1) & 1);
        if (h < 5) asm volatile("cp.async.wait_group 1;" ::: "memory");
        else       asm volatile("cp.async.wait_group 0;" ::: "memory");
        __syncthreads();                       // buf h&1 data visible to all

        const u32 sq  = sbase + (u32)(h & 1) * HBUF;
        const u32 sk  = sq + 8192u;
        const u32 svh = sq + 16384u;
        const u32 svl = sq + 20480u;

        // ---- A fragments for q (4 k-steps: 0,1 = qh; 2,3 = ql) ----
        u32 aq[4][4];
        {
            int row = wid * 16 + (lane & 15);
            #pragma unroll
            for (int s = 0; s < 4; s++) {
                int c = s * 2 + (lane >> 4);
                ldm4(aq[s], sq + (u32)(row * 128 + ((c ^ (row & 7)) << 4)));
            }
        }

        // ---- QK^T: 3-term split via fragment re-pairing ----
        float sc[8][4];
        #pragma unroll
        for (int nt = 0; nt < 8; nt++)
            #pragma unroll
            for (int q = 0; q < 4; q++) sc[nt][q] = 0.f;
        {
            const int pa[6] = {0, 1, 0, 1, 2, 3};   // A k-steps
            const int pb[6] = {0, 1, 2, 3, 0, 1};   // B k-steps: hh, hl, lh
            #pragma unroll
            for (int vs = 0; vs < 6; vs++) {
                #pragma unroll
                for (int np = 0; np < 4; np++) {
                    u32 bk[4];
                    int brow = np * 16 + (lane & 7) + ((lane >> 4) & 1) * 8;
                    int c    = pb[vs] * 2 + ((lane >> 3) & 1);
                    ldm4(bk, sk + (u32)(brow * 128 + ((c ^ (brow & 7)) << 4)));
                    mma16816(sc[np * 2],     aq[pa[vs]], bk[0], bk[1]);
                    mma16816(sc[np * 2 + 1], aq[pa[vs]], bk[2], bk[3]);
                }
            }
        }

        // ---- bias+mask, masking, softmax (register + quad shfl) ----
        const float* bmb = g_bm + ((size_t)(wsel * 6 + h) * 49) * 56;
        float m0 = -1e30f, m1 = -1e30f;
        #pragma unroll
        for (int nt = 0; nt < 8; nt++) {
            int c0 = nt * 8 + tcq;
            bool k0 = (c0 < 49), k1 = (c0 + 1 < 49);
            float2 bm0 = make_float2(0.f, 0.f), bm1 = make_float2(0.f, 0.f);
            if (k0 && r0 < 49)     bm0 = *(const float2*)(bmb + r0 * 56 + c0);
            if (k0 && r0 + 8 < 49) bm1 = *(const float2*)(bmb + (r0 + 8) * 56 + c0);
            sc[nt][0] = k0 ? sc[nt][0] + bm0.x : -1e30f;
            sc[nt][1] = k1 ? sc[nt][1] + bm0.y : -1e30f;
            sc[nt][2] = k0 ? sc[nt][2] + bm1.x : -1e30f;
            sc[nt][3] = k1 ? sc[nt][3] + bm1.y : -1e30f;
            m0 = fmaxf(m0, fmaxf(sc[nt][0], sc[nt][1]));
            m1 = fmaxf(m1, fmaxf(sc[nt][2], sc[nt][3]));
        }
        m0 = fmaxf(m0, __shfl_xor_sync(0xFFFFFFFFu, m0, 1));
        m0 = fmaxf(m0, __shfl_xor_sync(0xFFFFFFFFu, m0, 2));
        m1 = fmaxf(m1, __shfl_xor_sync(0xFFFFFFFFu, m1, 1));
        m1 = fmaxf(m1, __shfl_xor_sync(0xFFFFFFFFu, m1, 2));
        float s0 = 0.f, s1 = 0.f;
        #pragma unroll
        for (int nt = 0; nt < 8; nt++) {
            sc[nt][0] = __expf(sc[nt][0] - m0); s0 += sc[nt][0];
            sc[nt][1] = __expf(sc[nt][1] - m0); s0 += sc[nt][1];
            sc[nt][2] = __expf(sc[nt][2] - m1); s1 += sc[nt][2];
            sc[nt][3] = __expf(sc[nt][3] - m1); s1 += sc[nt][3];
        }
        s0 += __shfl_xor_sync(0xFFFFFFFFu, s0, 1);
        s0 += __shfl_xor_sync(0xFFFFFFFFu, s0, 2);
        s1 += __shfl_xor_sync(0xFFFFFFFFu, s1, 1);
        s1 += __shfl_xor_sync(0xFFFFFFFFu, s1, 2);
        float inv0 = 1.f / s0, inv1 = 1.f / s1;

        // ---- convert probs -> A-fragments (acc layout == A-frag layout) ----
        u32 ph[4][4], pl[4][4];
        #pragma unroll
        for (int s = 0; s < 4; s++) {
            float p00 = sc[2 * s][0] * inv0,     p01 = sc[2 * s][1] * inv0;
            float p10 = sc[2 * s][2] * inv1,     p11 = sc[2 * s][3] * inv1;
            float p20 = sc[2 * s + 1][0] * inv0, p21 = sc[2 * s + 1][1] * inv0;
            float p30 = sc[2 * s + 1][2] * inv1, p31 = sc[2 * s + 1][3] * inv1;
            ph[s][0] = cvt2(p00, p01); pl[s][0] = cvt2(p00 - bflo(ph[s][0]), p01 - bfhi(ph[s][0]));
            ph[s][1] = cvt2(p10, p11); pl[s][1] = cvt2(p10 - bflo(ph[s][1]), p11 - bfhi(ph[s][1]));
            ph[s][2] = cvt2(p20, p21); pl[s][2] = cvt2(p20 - bflo(ph[s][2]), p21 - bfhi(ph[s][2]));
            ph[s][3] = cvt2(p30, p31); pl[s][3] = cvt2(p30 - bflo(ph[s][3]), p31 - bfhi(ph[s][3]));
        }

        // ---- P @ V: terms (Ph,Vh), (Ph,Vl), (Pl,Vh) ----
        float ov[4][4];
        #pragma unroll
        for (int nt = 0; nt < 4; nt++)
            #pragma unroll
            for (int q = 0; q < 4; q++) ov[nt][q] = 0.f;
        #pragma unroll
        for (int term = 0; term < 3; term++) {
            const u32 (*pa)[4] = (term == 2) ? pl : ph;
            const u32 vbase = (term == 1) ? svl : svh;
            #pragma unroll
            for (int s = 0; s < 4; s++) {
                #pragma unroll
                for (int np = 0; np < 2; np++) {
                    u32 bv[4];
                    int brow = np * 16 + (lane & 7) + ((lane >> 4) & 1) * 8;
                    int c    = s * 2 + ((lane >> 3) & 1);
                    ldm4(bv, vbase + (u32)(brow * 128 + ((c ^ (brow & 7)) << 4)));
                    mma16816(ov[np * 2],     pa[s], bv[0], bv[1]);
                    mma16816(ov[np * 2 + 1], pa[s], bv[2], bv[3]);
                }
            }
        }

        // ---- store o (split bf16) to g_oe ----
        #pragma unroll
        for (int nt = 0; nt < 4; nt++) {
            int c0 = nt * 8 + tcq;
            #pragma unroll
            for (int half = 0; half < 2; half++) {
                int iv = r0 + half * 8;
                if (iv < 49) {
                    float x0 = ov[nt][half * 2 + 0];
                    float x1 = ov[nt][half * 2 + 1];
                    u32 hp = cvt2(x0, x1);
                    u32 lp = cvt2(x0 - bflo(hp), x1 - bfhi(hp));
                    __nv_bfloat16* base = g_oe + (tok0 + iv) * 384 + h * 32 + c0;
                    *(u32*)(base)       = hp;
                    *(u32*)(base + 192) = lp;
                }
            }
        }
    }
}

// ---------------- launch ----------------
extern "C" void kernel_launch(void* const* d_in, const int* in_sizes, int n_in,
                              void* d_out, int out_size) {
    const float* x          = (const float*)d_in[0];
    const float* mask       = (const float*)d_in[1];
    const float* qkv_w      = (const float*)d_in[2];
    const float* qkv_b      = (const float*)d_in[3];
    const float* proj_w     = (const float*)d_in[4];
    const float* proj_b     = (const float*)d_in[5];
    const float* bias_table = (const float*)d_in[6];
    const int*   rel_index  = (const int*)d_in[7];
    float* out = (float*)d_out;

    prep_kernel<<<120, 256>>>(qkv_w, proj_w, bias_table, rel_index, mask);
    xconv_kernel<<<(TOKS * 96) / 256, 256>>>(x);

    cudaFuncSetAttribute(gemm_mma, cudaFuncAttributeMaxDynamicSharedMemorySize, GSMEM);

    dim3 gq(9, TOKS / 128);
    gemm_mma<<<gq, 256, GSMEM>>>(qkv_b, nullptr, 0);   // QKV -> split q/k/v layouts
    attn_kernel<<<4096, 128>>>();                       // one CTA per window
    dim3 gp(3, TOKS / 128);
    gemm_mma<<<gp, 256, GSMEM>>>(proj_b, out, 1);       // proj: N=192
}

// round 12
// speedup vs baseline: 1.2835x; 1.0411x over previous
#include <cuda_runtime.h>
#include <cuda_bf16.h>
#include <cstdint>

typedef unsigned long long ull;
typedef uint32_t u32;

#define TOKS 200704          // 4096 windows * 49 tokens (= 1568 * 128)
#define NWIN 64
#define QSCALE 0.17677669529663687f

// ---------------- device scratch (zero-initialized at module load) ----------------
__device__ __nv_bfloat16 g_xe[(size_t)TOKS * 384];           // x split [t][hi|lo]
__device__ __nv_bfloat16 g_oe[(size_t)TOKS * 384];           // attn out split [hi|lo]
__device__ __nv_bfloat16 g_qke[(size_t)4096 * 6 * 49 * 64];  // q scaled, [win][h][i][qh(32)|ql(32)]
__device__ __nv_bfloat16 g_kke[(size_t)4096 * 6 * 49 * 64];  // k, [win][h][j][kh|kl]
__device__ __nv_bfloat16 g_vhe[(size_t)4096 * 6 * 32 * 64];  // v hi, [win][h][c][64j] (j>=49 stays 0)
__device__ __nv_bfloat16 g_vle[(size_t)4096 * 6 * 32 * 64];  // v lo
__device__ __nv_bfloat16 g_wqe[576 * 576];                   // qkv_w packed [n][wh|wl|wh]
__device__ __nv_bfloat16 g_wpe[192 * 576];                   // proj_w packed
__device__ float         g_bm[64 * 6 * 49 * 56];             // bias+mask, j padded to 56

__device__ __forceinline__ u32 smem_u32(const void* p) {
    u32 a;
    asm("{ .reg .u64 t; cvta.to.shared.u64 t, %1; cvt.u32.u64 %0, t; }" : "=r"(a) : "l"(p));
    return a;
}
__device__ __forceinline__ void cp16(u32 saddr, const void* gaddr) {
    asm volatile("cp.async.cg.shared.global [%0], [%1], 16;" :: "r"(saddr), "l"(gaddr));
}
__device__ __forceinline__ void ldm4(u32* r, u32 addr) {
    asm volatile("ldmatrix.sync.aligned.m8n8.x4.shared.b16 {%0,%1,%2,%3}, [%4];"
                 : "=r"(r[0]), "=r"(r[1]), "=r"(r[2]), "=r"(r[3]) : "r"(addr));
}
__device__ __forceinline__ void mma16816(float* d, const u32* a, u32 b0, u32 b1) {
    asm volatile("mma.sync.aligned.m16n8k16.row.col.f32.bf16.bf16.f32 "
                 "{%0,%1,%2,%3}, {%4,%5,%6,%7}, {%8,%9}, {%0,%1,%2,%3};"
                 : "+f"(d[0]), "+f"(d[1]), "+f"(d[2]), "+f"(d[3])
                 : "r"(a[0]), "r"(a[1]), "r"(a[2]), "r"(a[3]), "r"(b0), "r"(b1));
}
// pack two f32 into bf16x2: lo half = first arg
__device__ __forceinline__ u32 cvt2(float lo, float hi) {
    u32 r; asm("cvt.rn.bf16x2.f32 %0, %1, %2;" : "=r"(r) : "f"(hi), "f"(lo)); return r;
}
__device__ __forceinline__ float bflo(u32 p) { return __uint_as_float(p << 16); }
__device__ __forceinline__ float bfhi(u32 p) { return __uint_as_float(p & 0xFFFF0000u); }

// ---------------- prep: split-pack weights + combine bias/mask ----------------
__global__ void prep_kernel(const float* __restrict__ qkv_w, const float* __restrict__ proj_w,
                            const float* __restrict__ bias_table, const int* __restrict__ rel_index,
                            const float* __restrict__ mask) {
    int tid = blockIdx.x * blockDim.x + threadIdx.x;
    int stride = gridDim.x * blockDim.x;
    for (int i = tid; i < 576 * 192; i += stride) {
        int n = i / 192, k = i - n * 192;
        float w = qkv_w[i];
        __nv_bfloat16 h = __float2bfloat16(w);
        __nv_bfloat16 l = __float2bfloat16(w - __bfloat162float(h));
        g_wqe[(size_t)n * 576 + k]       = h;
        g_wqe[(size_t)n * 576 + 192 + k] = l;
        g_wqe[(size_t)n * 576 + 384 + k] = h;
    }
    for (int i = tid; i < 192 * 192; i += stride) {
        int n = i / 192, k = i - n * 192;
        float w = proj_w[i];
        __nv_bfloat16 h = __float2bfloat16(w);
        __nv_bfloat16 l = __float2bfloat16(w - __bfloat162float(h));
        g_wpe[(size_t)n * 576 + k]       = h;
        g_wpe[(size_t)n * 576 + 192 + k] = l;
        g_wpe[(size_t)n * 576 + 384 + k] = h;
    }
    for (int i = tid; i < 64 * 6 * 49 * 56; i += stride) {
        int j = i % 56; int rest = i / 56;
        int ir = rest % 49; rest /= 49;
        int hh = rest % 6; int wm = rest / 6;
        float v = 0.f;
        if (j < 49)
            v = bias_table[rel_index[ir * 49 + j] * 6 + hh] + mask[wm * 2401 + ir * 49 + j];
        g_bm[i] = v;
    }
}

// ---------------- x -> bf16 split [hi|lo] (384 wide) ----------------
__global__ void xconv_kernel(const float* __restrict__ x) {
    size_t idx = (size_t)blockIdx.x * 256 + threadIdx.x;
    size_t t = idx / 96;
    int p = (int)(idx - t * 96);
    float2 v = *(const float2*)(x + t * 192 + 2 * p);
    __nv_bfloat16 h0 = __float2bfloat16(v.x), h1 = __float2bfloat16(v.y);
    __nv_bfloat16 l0 = __float2bfloat16(v.x - __bfloat162float(h0));
    __nv_bfloat16 l1 = __float2bfloat16(v.y - __bfloat162float(h1));
    __nv_bfloat162 hp; hp.x = h0; hp.y = h1;
    __nv_bfloat162 lp; lp.x = l0; lp.y = l1;
    size_t base = t * 384 + 2 * p;
    *(__nv_bfloat162*)(g_xe + base)       = hp;
    *(__nv_bfloat162*)(g_xe + base + 192) = lp;
}

// ---------------- mma.sync GEMM, 3-stage cp.async pipeline ----------------
// which=0: A=g_xe, W=g_wqe; epilogue stages acc in smem, coalesced split-bf16
//          q/k/v writes. which=1: A=g_oe, W=g_wpe; fp32 out.
#define GSMEM 73728
#define STG_STRIDE 68

__global__ __launch_bounds__(256, 2)
void gemm_mma(const float* __restrict__ bias, float* __restrict__ out_param, int which) {
    extern __shared__ char sm[];
    const __nv_bfloat16* Ae = which ? g_oe : g_xe;
    const __nv_bfloat16* We = which ? g_wpe : g_wqe;
    const int Ncols = which ? 192 : 576;

    const u32 sb = smem_u32(sm);
    const int tid  = threadIdx.x;
    const int lane = tid & 31;
    const int wid  = tid >> 5;
    const int wm   = wid >> 1;
    const int wn   = wid & 1;
    const size_t row0 = (size_t)blockIdx.y * 128;
    const int    n0   = blockIdx.x * 64;

    float acc[2][4][4];
    #pragma unroll
    for (int mt = 0; mt < 2; mt++)
        #pragma unroll
        for (int nt = 0; nt < 4; nt++)
            #pragma unroll
            for (int q = 0; q < 4; q++) acc[mt][nt][q] = 0.f;

    auto load_chunk = [&](int kc, int buf) {
        int aoff = (kc < 3) ? kc * 64 : (kc < 6 ? (kc - 3) * 64 : (kc - 6) * 64 + 192);
        const u32 sA = sb + (u32)buf * 16384u;
        const u32 sB = sb + 49152u + (u32)buf * 8192u;
        #pragma unroll
        for (int s = 0; s < 6; s++) {
            int j = tid + s * 256;
            if (j < 1024) {
                int r = j >> 3, c = j & 7;
                u32 saddr = sA + (u32)r * 128u + (u32)((c ^ (r & 7)) << 4);
                cp16(saddr, Ae + (row0 + r) * 384 + aoff + c * 8);
            } else {
                int jj = j - 1024;
                int r = jj >> 3, c = jj & 7;
                u32 saddr = sB + (u32)r * 128u + (u32)((c ^ (r & 7)) << 4);
                cp16(saddr, We + (size_t)(n0 + r) * 576 + kc * 64 + c * 8);
            }
        }
        asm volatile("cp.async.commit_group;" ::: "memory");
    };

    load_chunk(0, 0);
    load_chunk(1, 1);

    #pragma unroll 1
    for (int kc = 0; kc < 9; kc++) {
        if (kc < 8) asm volatile("cp.async.wait_group 1;" ::: "memory");
        else        asm volatile("cp.async.wait_group 0;" ::: "memory");
        __syncthreads();
        if (kc + 2 < 9) load_chunk(kc + 2, (kc + 2) % 3);

        const int buf = kc % 3;
        const u32 sA = sb + (u32)buf * 16384u;
        const u32 sB = sb + 49152u + (u32)buf * 8192u;

        #pragma unroll
        for (int ks = 0; ks < 4; ks++) {
            u32 afr[2][4], bfr[2][4];
            #pragma unroll
            for (int mt = 0; mt < 2; mt++) {
                int row = wm * 32 + mt * 16 + (lane & 15);
                int c   = ks * 2 + (lane >> 4);
                ldm4(afr[mt], sA + (u32)row * 128u + (u32)((c ^ (row & 7)) << 4));
            }
            #pragma unroll
            for (int np = 0; np < 2; np++) {
                int brow = wn * 32 + np * 16 + (lane & 7) + ((lane >> 4) & 1) * 8;
                int c    = ks * 2 + ((lane >> 3) & 1);
                ldm4(bfr[np], sB + (u32)brow * 128u + (u32)((c ^ (brow & 7)) << 4));
            }
            #pragma unroll
            for (int mt = 0; mt < 2; mt++)
                #pragma unroll
                for (int nt = 0; nt < 4; nt++)
                    mma16816(acc[mt][nt], afr[mt], bfr[nt >> 1][(nt & 1) * 2], bfr[nt >> 1][(nt & 1) * 2 + 1]);
        }
        __syncthreads();
    }

    const int tr = lane >> 2, tc = (lane & 3) * 2;
    if (which) {
        #pragma unroll
        for (int mt = 0; mt < 2; mt++)
            #pragma unroll
            for (int nt = 0; nt < 4; nt++) {
                int col = n0 + wn * 32 + nt * 8 + tc;
                float b0 = bias[col], b1 = bias[col + 1];
                size_t r_lo = row0 + wm * 32 + mt * 16 + tr;
                float2 v0; v0.x = acc[mt][nt][0] + b0; v0.y = acc[mt][nt][1] + b1;
                float2 v1; v1.x = acc[mt][nt][2] + b0; v1.y = acc[mt][nt][3] + b1;
                *(float2*)(out_param + r_lo * Ncols + col)       = v0;
                *(float2*)(out_param + (r_lo + 8) * Ncols + col) = v1;
            }
    } else {
        // ---- stage acc (bias + optional q-scale applied) into smem fp32 tile ----
        const int sec = n0 / 192;        // 0=q, 1=k, 2=v
        const int head0 = (n0 % 192) >> 5;
        float* stg = (float*)sm;         // [128][STG_STRIDE]
        #pragma unroll
        for (int mt = 0; mt < 2; mt++)
            #pragma unroll
            for (int nt = 0; nt < 4; nt++) {
                int col = wn * 32 + nt * 8 + tc;
                float b0 = bias[n0 + col], b1 = bias[n0 + col + 1];
                #pragma unroll
                for (int half = 0; half < 2; half++) {
                    int r = wm * 32 + mt * 16 + tr + half * 8;
                    float x0 = acc[mt][nt][half * 2 + 0] + b0;
                    float x1 = acc[mt][nt][half * 2 + 1] + b1;
                    if (sec == 0) { x0 *= QSCALE; x1 *= QSCALE; }
                    stg[r * STG_STRIDE + col]     = x0;
                    stg[r * STG_STRIDE + col + 1] = x1;
                }
            }
        __syncthreads();

        if (sec < 2) {
            // q/k: 128 tokens x 16 colgroups of 4; per job write 8B hi + 8B lo
            __nv_bfloat16* gbase = sec == 0 ? g_qke : g_kke;
            for (int idx = tid; idx < 2048; idx += 256) {
                int t = idx >> 4, cg = idx & 15;
                int hh = cg >> 3, d0 = (cg & 7) * 4;
                u32 r = (u32)(row0 + t);
                u32 win = r / 49u, i = r - win * 49u;
                const float* sp = stg + t * STG_STRIDE + hh * 32 + d0;
                float x0 = sp[0], x1 = sp[1], x2 = sp[2], x3 = sp[3];
                u32 hp0 = cvt2(x0, x1), hp1 = cvt2(x2, x3);
                u32 lp0 = cvt2(x0 - bflo(hp0), x1 - bfhi(hp0));
                u32 lp1 = cvt2(x2 - bflo(hp1), x3 - bfhi(hp1));
                __nv_bfloat16* base = gbase + (((size_t)win * 6 + head0 + hh) * 49 + i) * 64 + d0;
                ((u32*)base)[0] = hp0; ((u32*)base)[1] = hp1;
                ((u32*)(base + 32))[0] = lp0; ((u32*)(base + 32))[1] = lp1;
            }
        } else {
            // v: token-fastest lane order -> contiguous 2B stores per window segment
            for (int idx = tid; idx < 8192; idx += 256) {
                int d = idx >> 7, t = idx & 127;
                int hh = d >> 5, dd = d & 31;
                u32 r = (u32)(row0 + t);
                u32 win = r / 49u, i = r - win * 49u;
                float x = stg[t * STG_STRIDE + d];
                __nv_bfloat16 h0 = __float2bfloat16(x);
                size_t vb = (((size_t)win * 6 + head0 + hh) * 32 + dd) * 64 + i;
                g_vhe[vb] = h0;
                g_vle[vb] = __float2bfloat16(x - __bfloat162float(h0));
            }
        }
    }
}

// ---------------- attention: tensor-core QK^T and P@V, softmax in registers ----
// One CTA per window, 128 threads, 6 heads, cp.async double-buffered staging.
#define HBUF 24576

__global__ __launch_bounds__(128, 4)
void attn_kernel() {
    __shared__ __align__(16) char smbuf[2 * HBUF];
    const u32 sbase = smem_u32(smbuf);

    const int tid  = threadIdx.x;
    const int lane = tid & 31;
    const int wid  = tid >> 5;
    const int win  = blockIdx.x;
    const int wsel = win & (NWIN - 1);
    const size_t tok0 = (size_t)win * 49;

    // zero k pad rows (49..63) in BOTH buffers once
    {
        float4 z = make_float4(0.f, 0.f, 0.f, 0.f);
        #pragma unroll
        for (int b = 0; b < 2; b++)
            for (int idx = tid; idx < 15 * 8; idx += 128) {
                int r = 49 + (idx >> 3), ch = idx & 7;
                *(float4*)(smbuf + b * HBUF + 8192 + r * 128 + ((ch ^ (r & 7)) << 4)) = z;
            }
    }

    auto stage = [&](int h, int buf) {
        const u32 sq = sbase + (u32)buf * HBUF;
        const size_t qb = ((size_t)win * 6 + h) * 49 * 64;
        for (int idx = tid; idx < 392; idx += 128) {
            int r = idx >> 3, ch = idx & 7;
            u32 off = (u32)(r * 128 + ((ch ^ (r & 7)) << 4));
            cp16(sq + off,         g_qke + qb + r * 64 + ch * 8);
            cp16(sq + 8192u + off, g_kke + qb + r * 64 + ch * 8);
        }
        const size_t vb = ((size_t)win * 6 + h) * 32 * 64;
        for (int idx = tid; idx < 256; idx += 128) {
            int c = idx >> 3, ch = idx & 7;
            u32 off = (u32)(c * 128 + ((ch ^ (c & 7)) << 4));
            cp16(sq + 16384u + off, g_vhe + vb + c * 64 + ch * 8);
            cp16(sq + 20480u + off, g_vle + vb + c * 64 + ch * 8);
        }
        asm volatile("cp.async.commit_group;" ::: "memory");
    };

    const int tcq = 2 * (lane & 3);
    const int r0  = wid * 16 + (lane >> 2);

    stage(0, 0);

    #pragma unroll 1
    for (int h = 0; h < 6; h++) {
        __syncthreads();
        if (h < 5) stage(h + 1, (h + 1) & 1);
        if (h < 5) asm volatile("cp.async.wait_group 1;" ::: "memory");
        else       asm volatile("cp.async.wait_group 0;" ::: "memory");
        __syncthreads();

        const u32 sq  = sbase + (u32)(h & 1) * HBUF;
        const u32 sk  = sq + 8192u;
        const u32 svh = sq + 16384u;
        const u32 svl = sq + 20480u;

        u32 aq[4][4];
        {
            int row = wid * 16 + (lane & 15);
            #pragma unroll
            for (int s = 0; s < 4; s++) {
                int c = s * 2 + (lane >> 4);
                ldm4(aq[s], sq + (u32)(row * 128 + ((c ^ (row & 7)) << 4)));
            }
        }

        float sc[8][4];
        #pragma unroll
        for (int nt = 0; nt < 8; nt++)
            #pragma unroll
            for (int q = 0; q < 4; q++) sc[nt][q] = 0.f;
        {
            const int pa[6] = {0, 1, 0, 1, 2, 3};
            const int pb[6] = {0, 1, 2, 3, 0, 1};
            #pragma unroll
            for (int vs = 0; vs < 6; vs++) {
                #pragma unroll
                for (int np = 0; np < 4; np++) {
                    u32 bk[4];
                    int brow = np * 16 + (lane & 7) + ((lane >> 4) & 1) * 8;
                    int c    = pb[vs] * 2 + ((lane >> 3) & 1);
                    ldm4(bk, sk + (u32)(brow * 128 + ((c ^ (brow & 7)) << 4)));
                    mma16816(sc[np * 2],     aq[pa[vs]], bk[0], bk[1]);
                    mma16816(sc[np * 2 + 1], aq[pa[vs]], bk[2], bk[3]);
                }
            }
        }

        const float* bmb = g_bm + ((size_t)(wsel * 6 + h) * 49) * 56;
        float m0 = -1e30f, m1 = -1e30f;
        #pragma unroll
        for (int nt = 0; nt < 8; nt++) {
            int c0 = nt * 8 + tcq;
            bool k0 = (c0 < 49), k1 = (c0 + 1 < 49);
            float2 bm0 = make_float2(0.f, 0.f), bm1 = make_float2(0.f, 0.f);
            if (k0 && r0 < 49)     bm0 = *(const float2*)(bmb + r0 * 56 + c0);
            if (k0 && r0 + 8 < 49) bm1 = *(const float2*)(bmb + (r0 + 8) * 56 + c0);
            sc[nt][0] = k0 ? sc[nt][0] + bm0.x : -1e30f;
            sc[nt][1] = k1 ? sc[nt][1] + bm0.y : -1e30f;
            sc[nt][2] = k0 ? sc[nt][2] + bm1.x : -1e30f;
            sc[nt][3] = k1 ? sc[nt][3] + bm1.y : -1e30f;
            m0 = fmaxf(m0, fmaxf(sc[nt][0], sc[nt][1]));
            m1 = fmaxf(m1, fmaxf(sc[nt][2], sc[nt][3]));
        }
        m0 = fmaxf(m0, __shfl_xor_sync(0xFFFFFFFFu, m0, 1));
        m0 = fmaxf(m0, __shfl_xor_sync(0xFFFFFFFFu, m0, 2));
        m1 = fmaxf(m1, __shfl_xor_sync(0xFFFFFFFFu, m1, 1));
        m1 = fmaxf(m1, __shfl_xor_sync(0xFFFFFFFFu, m1, 2));
        float s0 = 0.f, s1 = 0.f;
        #pragma unroll
        for (int nt = 0; nt < 8; nt++) {
            sc[nt][0] = __expf(sc[nt][0] - m0); s0 += sc[nt][0];
            sc[nt][1] = __expf(sc[nt][1] - m0); s0 += sc[nt][1];
            sc[nt][2] = __expf(sc[nt][2] - m1); s1 += sc[nt][2];
            sc[nt][3] = __expf(sc[nt][3] - m1); s1 += sc[nt][3];
        }
        s0 += __shfl_xor_sync(0xFFFFFFFFu, s0, 1);
        s0 += __shfl_xor_sync(0xFFFFFFFFu, s0, 2);
        s1 += __shfl_xor_sync(0xFFFFFFFFu, s1, 1);
        s1 += __shfl_xor_sync(0xFFFFFFFFu, s1, 2);
        float inv0 = 1.f / s0, inv1 = 1.f / s1;

        u32 ph[4][4], pl[4][4];
        #pragma unroll
        for (int s = 0; s < 4; s++) {
            float p00 = sc[2 * s][0] * inv0,     p01 = sc[2 * s][1] * inv0;
            float p10 = sc[2 * s][2] * inv1,     p11 = sc[2 * s][3] * inv1;
            float p20 = sc[2 * s + 1][0] * inv0, p21 = sc[2 * s + 1][1] * inv0;
            float p30 = sc[2 * s + 1][2] * inv1, p31 = sc[2 * s + 1][3] * inv1;
            ph[s][0] = cvt2(p00, p01); pl[s][0] = cvt2(p00 - bflo(ph[s][0]), p01 - bfhi(ph[s][0]));
            ph[s][1] = cvt2(p10, p11); pl[s][1] = cvt2(p10 - bflo(ph[s][1]), p11 - bfhi(ph[s][1]));
            ph[s][2] = cvt2(p20, p21); pl[s][2] = cvt2(p20 - bflo(ph[s][2]), p21 - bfhi(ph[s][2]));
            ph[s][3] = cvt2(p30, p31); pl[s][3] = cvt2(p30 - bflo(ph[s][3]), p31 - bfhi(ph[s][3]));
        }

        float ov[4][4];
        #pragma unroll
        for (int nt = 0; nt < 4; nt++)
            #pragma unroll
            for (int q = 0; q < 4; q++) ov[nt][q] = 0.f;
        #pragma unroll
        for (int term = 0; term < 3; term++) {
            const u32 (*pa)[4] = (term == 2) ? pl : ph;
            const u32 vbase = (term == 1) ? svl : svh;
            #pragma unroll
            for (int s = 0; s < 4; s++) {
                #pragma unroll
                for (int np = 0; np < 2; np++) {
                    u32 bv[4];
                    int brow = np * 16 + (lane & 7) + ((lane >> 4) & 1) * 8;
                    int c    = s * 2 + ((lane >> 3) & 1);
                    ldm4(bv, vbase + (u32)(brow * 128 + ((c ^ (brow & 7)) << 4)));
                    mma16816(ov[np * 2],     pa[s], bv[0], bv[1]);
                    mma16816(ov[np * 2 + 1], pa[s], bv[2], bv[3]);
                }
            }
        }

        #pragma unroll
        for (int nt = 0; nt < 4; nt++) {
            int c0 = nt * 8 + tcq;
            #pragma unroll
            for (int half = 0; half < 2; half++) {
                int iv = r0 + half * 8;
                if (iv < 49) {
                    float x0 = ov[nt][half * 2 + 0];
                    float x1 = ov[nt][half * 2 + 1];
                    u32 hp = cvt2(x0, x1);
                    u32 lp = cvt2(x0 - bflo(hp), x1 - bfhi(hp));
                    __nv_bfloat16* base = g_oe + (tok0 + iv) * 384 + h * 32 + c0;
                    *(u32*)(base)       = hp;
                    *(u32*)(base + 192) = lp;
                }
            }
        }
    }
}

// ---------------- launch ----------------
extern "C" void kernel_launch(void* const* d_in, const int* in_sizes, int n_in,
                              void* d_out, int out_size) {
    const float* x          = (const float*)d_in[0];
    const float* mask       = (const float*)d_in[1];
    const float* qkv_w      = (const float*)d_in[2];
    const float* qkv_b      = (const float*)d_in[3];
    const float* proj_w     = (const float*)d_in[4];
    const float* proj_b     = (const float*)d_in[5];
    const float* bias_table = (const float*)d_in[6];
    const int*   rel_index  = (const int*)d_in[7];
    float* out = (float*)d_out;

    prep_kernel<<<120, 256>>>(qkv_w, proj_w, bias_table, rel_index, mask);
    xconv_kernel<<<(TOKS * 96) / 256, 256>>>(x);

    cudaFuncSetAttribute(gemm_mma, cudaFuncAttributeMaxDynamicSharedMemorySize, GSMEM);

    dim3 gq(9, TOKS / 128);
    gemm_mma<<<gq, 256, GSMEM>>>(qkv_b, nullptr, 0);   // QKV -> split q/k/v layouts
    attn_kernel<<<4096, 128>>>();                       // one CTA per window
    dim3 gp(3, TOKS / 128);
    gemm_mma<<<gp, 256, GSMEM>>>(proj_b, out, 1);       // proj: N=192
}

// round 13
// speedup vs baseline: 1.3071x; 1.0184x over previous
#include <cuda_runtime.h>
#include <cuda_bf16.h>
#include <cstdint>

typedef unsigned long long ull;
typedef uint32_t u32;

#define TOKS 200704          // 4096 windows * 49 tokens (= 1568 * 128)
#define NWIN 64
#define QSCALE 0.17677669529663687f

// ---------------- device scratch (zero-initialized at module load) ----------------
__device__ __nv_bfloat16 g_xe[(size_t)TOKS * 384];           // x split [t][hi|lo]
__device__ __nv_bfloat16 g_oe[(size_t)TOKS * 384];           // attn out split [hi|lo]
__device__ __nv_bfloat16 g_qke[(size_t)4096 * 6 * 49 * 64];  // q scaled, [win][h][i][qh(32)|ql(32)]
__device__ __nv_bfloat16 g_kke[(size_t)4096 * 6 * 49 * 64];  // k, [win][h][j][kh|kl]
__device__ __nv_bfloat16 g_vhe[(size_t)4096 * 6 * 32 * 64];  // v hi, [win][h][c][64j] (j>=49 stays 0)
__device__ __nv_bfloat16 g_vle[(size_t)4096 * 6 * 32 * 64];  // v lo
__device__ __nv_bfloat16 g_wqe[576 * 576];                   // qkv_w packed [n][wh|wl|wh]
__device__ __nv_bfloat16 g_wpe[192 * 576];                   // proj_w packed
__device__ float         g_bm[64 * 6 * 49 * 56];             // bias+mask, j padded to 56

__device__ __forceinline__ u32 smem_u32(const void* p) {
    u32 a;
    asm("{ .reg .u64 t; cvta.to.shared.u64 t, %1; cvt.u32.u64 %0, t; }" : "=r"(a) : "l"(p));
    return a;
}
__device__ __forceinline__ void cp16(u32 saddr, const void* gaddr) {
    asm volatile("cp.async.cg.shared.global [%0], [%1], 16;" :: "r"(saddr), "l"(gaddr));
}
__device__ __forceinline__ void ldm4(u32* r, u32 addr) {
    asm volatile("ldmatrix.sync.aligned.m8n8.x4.shared.b16 {%0,%1,%2,%3}, [%4];"
                 : "=r"(r[0]), "=r"(r[1]), "=r"(r[2]), "=r"(r[3]) : "r"(addr));
}
__device__ __forceinline__ void mma16816(float* d, const u32* a, u32 b0, u32 b1) {
    asm volatile("mma.sync.aligned.m16n8k16.row.col.f32.bf16.bf16.f32 "
                 "{%0,%1,%2,%3}, {%4,%5,%6,%7}, {%8,%9}, {%0,%1,%2,%3};"
                 : "+f"(d[0]), "+f"(d[1]), "+f"(d[2]), "+f"(d[3])
                 : "r"(a[0]), "r"(a[1]), "r"(a[2]), "r"(a[3]), "r"(b0), "r"(b1));
}
// pack two f32 into bf16x2: lo half = first arg
__device__ __forceinline__ u32 cvt2(float lo, float hi) {
    u32 r; asm("cvt.rn.bf16x2.f32 %0, %1, %2;" : "=r"(r) : "f"(hi), "f"(lo)); return r;
}
__device__ __forceinline__ float bflo(u32 p) { return __uint_as_float(p << 16); }
__device__ __forceinline__ float bfhi(u32 p) { return __uint_as_float(p & 0xFFFF0000u); }

// ---------------- prep: split-pack weights + combine bias/mask ----------------
__global__ void prep_kernel(const float* __restrict__ qkv_w, const float* __restrict__ proj_w,
                            const float* __restrict__ bias_table, const int* __restrict__ rel_index,
                            const float* __restrict__ mask) {
    int tid = blockIdx.x * blockDim.x + threadIdx.x;
    int stride = gridDim.x * blockDim.x;
    for (int i = tid; i < 576 * 192; i += stride) {
        int n = i / 192, k = i - n * 192;
        float w = qkv_w[i];
        __nv_bfloat16 h = __float2bfloat16(w);
        __nv_bfloat16 l = __float2bfloat16(w - __bfloat162float(h));
        g_wqe[(size_t)n * 576 + k]       = h;
        g_wqe[(size_t)n * 576 + 192 + k] = l;
        g_wqe[(size_t)n * 576 + 384 + k] = h;
    }
    for (int i = tid; i < 192 * 192; i += stride) {
        int n = i / 192, k = i - n * 192;
        float w = proj_w[i];
        __nv_bfloat16 h = __float2bfloat16(w);
        __nv_bfloat16 l = __float2bfloat16(w - __bfloat162float(h));
        g_wpe[(size_t)n * 576 + k]       = h;
        g_wpe[(size_t)n * 576 + 192 + k] = l;
        g_wpe[(size_t)n * 576 + 384 + k] = h;
    }
    for (int i = tid; i < 64 * 6 * 49 * 56; i += stride) {
        int j = i % 56; int rest = i / 56;
        int ir = rest % 49; rest /= 49;
        int hh = rest % 6; int wm = rest / 6;
        float v = 0.f;
        if (j < 49)
            v = bias_table[rel_index[ir * 49 + j] * 6 + hh] + mask[wm * 2401 + ir * 49 + j];
        g_bm[i] = v;
    }
}

// ---------------- x -> bf16 split [hi|lo] (384 wide) ----------------
__global__ void xconv_kernel(const float* __restrict__ x) {
    size_t idx = (size_t)blockIdx.x * 256 + threadIdx.x;
    size_t t = idx / 96;
    int p = (int)(idx - t * 96);
    float2 v = *(const float2*)(x + t * 192 + 2 * p);
    __nv_bfloat16 h0 = __float2bfloat16(v.x), h1 = __float2bfloat16(v.y);
    __nv_bfloat16 l0 = __float2bfloat16(v.x - __bfloat162float(h0));
    __nv_bfloat16 l1 = __float2bfloat16(v.y - __bfloat162float(h1));
    __nv_bfloat162 hp; hp.x = h0; hp.y = h1;
    __nv_bfloat162 lp; lp.x = l0; lp.y = l1;
    size_t base = t * 384 + 2 * p;
    *(__nv_bfloat162*)(g_xe + base)       = hp;
    *(__nv_bfloat162*)(g_xe + base + 192) = lp;
}

// ---------------- mma.sync GEMM, 3-stage cp.async pipeline, ONE sync/chunk ----
// Schedule per chunk: wait(kc) -> sync -> issue(kc+2) -> compute(kc).
// The sync proves every thread finished compute(kc-1) on buf (kc+2)%3 == (kc-1)%3
// before anyone overwrites it, AND that all threads' group-kc data is visible.
#define GSMEM 73728
#define STG_STRIDE 68

__global__ __launch_bounds__(256, 2)
void gemm_mma(const float* __restrict__ bias, float* __restrict__ out_param, int which) {
    extern __shared__ char sm[];
    const __nv_bfloat16* Ae = which ? g_oe : g_xe;
    const __nv_bfloat16* We = which ? g_wpe : g_wqe;
    const int Ncols = which ? 192 : 576;

    const u32 sb = smem_u32(sm);
    const int tid  = threadIdx.x;
    const int lane = tid & 31;
    const int wid  = tid >> 5;
    const int wm   = wid >> 1;
    const int wn   = wid & 1;
    const size_t row0 = (size_t)blockIdx.y * 128;
    const int    n0   = blockIdx.x * 64;

    float acc[2][4][4];
    #pragma unroll
    for (int mt = 0; mt < 2; mt++)
        #pragma unroll
        for (int nt = 0; nt < 4; nt++)
            #pragma unroll
            for (int q = 0; q < 4; q++) acc[mt][nt][q] = 0.f;

    auto load_chunk = [&](int kc, int buf) {
        int aoff = (kc < 3) ? kc * 64 : (kc < 6 ? (kc - 3) * 64 : (kc - 6) * 64 + 192);
        const u32 sA = sb + (u32)buf * 16384u;
        const u32 sB = sb + 49152u + (u32)buf * 8192u;
        #pragma unroll
        for (int s = 0; s < 6; s++) {
            int j = tid + s * 256;
            if (j < 1024) {
                int r = j >> 3, c = j & 7;
                u32 saddr = sA + (u32)r * 128u + (u32)((c ^ (r & 7)) << 4);
                cp16(saddr, Ae + (row0 + r) * 384 + aoff + c * 8);
            } else {
                int jj = j - 1024;
                int r = jj >> 3, c = jj & 7;
                u32 saddr = sB + (u32)r * 128u + (u32)((c ^ (r & 7)) << 4);
                cp16(saddr, We + (size_t)(n0 + r) * 576 + kc * 64 + c * 8);
            }
        }
        asm volatile("cp.async.commit_group;" ::: "memory");
    };

    load_chunk(0, 0);
    load_chunk(1, 1);

    #pragma unroll 1
    for (int kc = 0; kc < 9; kc++) {
        if (kc < 8) asm volatile("cp.async.wait_group 1;" ::: "memory");
        else        asm volatile("cp.async.wait_group 0;" ::: "memory");
        __syncthreads();
        if (kc + 2 < 9) load_chunk(kc + 2, (kc + 2) % 3);

        const int buf = kc % 3;
        const u32 sA = sb + (u32)buf * 16384u;
        const u32 sB = sb + 49152u + (u32)buf * 8192u;

        #pragma unroll
        for (int ks = 0; ks < 4; ks++) {
            u32 afr[2][4], bfr[2][4];
            #pragma unroll
            for (int mt = 0; mt < 2; mt++) {
                int row = wm * 32 + mt * 16 + (lane & 15);
                int c   = ks * 2 + (lane >> 4);
                ldm4(afr[mt], sA + (u32)row * 128u + (u32)((c ^ (row & 7)) << 4));
            }
            #pragma unroll
            for (int np = 0; np < 2; np++) {
                int brow = wn * 32 + np * 16 + (lane & 7) + ((lane >> 4) & 1) * 8;
                int c    = ks * 2 + ((lane >> 3) & 1);
                ldm4(bfr[np], sB + (u32)brow * 128u + (u32)((c ^ (brow & 7)) << 4));
            }
            #pragma unroll
            for (int mt = 0; mt < 2; mt++)
                #pragma unroll
                for (int nt = 0; nt < 4; nt++)
                    mma16816(acc[mt][nt], afr[mt], bfr[nt >> 1][(nt & 1) * 2], bfr[nt >> 1][(nt & 1) * 2 + 1]);
        }
    }

    const int tr = lane >> 2, tc = (lane & 3) * 2;
    if (which) {
        #pragma unroll
        for (int mt = 0; mt < 2; mt++)
            #pragma unroll
            for (int nt = 0; nt < 4; nt++) {
                int col = n0 + wn * 32 + nt * 8 + tc;
                float b0 = bias[col], b1 = bias[col + 1];
                size_t r_lo = row0 + wm * 32 + mt * 16 + tr;
                float2 v0; v0.x = acc[mt][nt][0] + b0; v0.y = acc[mt][nt][1] + b1;
                float2 v1; v1.x = acc[mt][nt][2] + b0; v1.y = acc[mt][nt][3] + b1;
                *(float2*)(out_param + r_lo * Ncols + col)       = v0;
                *(float2*)(out_param + (r_lo + 8) * Ncols + col) = v1;
            }
    } else {
        __syncthreads();                 // all compute done before reusing buffers as stg
        // ---- stage acc (bias + optional q-scale applied) into smem fp32 tile ----
        const int sec = n0 / 192;        // 0=q, 1=k, 2=v
        const int head0 = (n0 % 192) >> 5;
        float* stg = (float*)sm;         // [128][STG_STRIDE]
        #pragma unroll
        for (int mt = 0; mt < 2; mt++)
            #pragma unroll
            for (int nt = 0; nt < 4; nt++) {
                int col = wn * 32 + nt * 8 + tc;
                float b0 = bias[n0 + col], b1 = bias[n0 + col + 1];
                #pragma unroll
                for (int half = 0; half < 2; half++) {
                    int r = wm * 32 + mt * 16 + tr + half * 8;
                    float x0 = acc[mt][nt][half * 2 + 0] + b0;
                    float x1 = acc[mt][nt][half * 2 + 1] + b1;
                    if (sec == 0) { x0 *= QSCALE; x1 *= QSCALE; }
                    stg[r * STG_STRIDE + col]     = x0;
                    stg[r * STG_STRIDE + col + 1] = x1;
                }
            }
        __syncthreads();

        if (sec < 2) {
            // q/k: 128 tokens x 16 colgroups of 4; per job write 8B hi + 8B lo
            __nv_bfloat16* gbase = sec == 0 ? g_qke : g_kke;
            for (int idx = tid; idx < 2048; idx += 256) {
                int t = idx >> 4, cg = idx & 15;
                int hh = cg >> 3, d0 = (cg & 7) * 4;
                u32 r = (u32)(row0 + t);
                u32 win = r / 49u, i = r - win * 49u;
                const float* sp = stg + t * STG_STRIDE + hh * 32 + d0;
                float x0 = sp[0], x1 = sp[1], x2 = sp[2], x3 = sp[3];
                u32 hp0 = cvt2(x0, x1), hp1 = cvt2(x2, x3);
                u32 lp0 = cvt2(x0 - bflo(hp0), x1 - bfhi(hp0));
                u32 lp1 = cvt2(x2 - bflo(hp1), x3 - bfhi(hp1));
                __nv_bfloat16* base = gbase + (((size_t)win * 6 + head0 + hh) * 49 + i) * 64 + d0;
                ((u32*)base)[0] = hp0; ((u32*)base)[1] = hp1;
                ((u32*)(base + 32))[0] = lp0; ((u32*)(base + 32))[1] = lp1;
            }
        } else {
            // v: token-fastest lane order -> contiguous 2B stores per window segment
            for (int idx = tid; idx < 8192; idx += 256) {
                int d = idx >> 7, t = idx & 127;
                int hh = d >> 5, dd = d & 31;
                u32 r = (u32)(row0 + t);
                u32 win = r / 49u, i = r - win * 49u;
                float x = stg[t * STG_STRIDE + d];
                __nv_bfloat16 h0 = __float2bfloat16(x);
                size_t vb = (((size_t)win * 6 + head0 + hh) * 32 + dd) * 64 + i;
                g_vhe[vb] = h0;
                g_vle[vb] = __float2bfloat16(x - __bfloat162float(h0));
            }
        }
    }
}

// ---------------- attention: tensor-core QK^T and P@V, softmax in registers ----
// One CTA per window, 128 threads, 6 heads, cp.async double-buffered staging.
#define HBUF 24576

__global__ __launch_bounds__(128, 4)
void attn_kernel() {
    __shared__ __align__(16) char smbuf[2 * HBUF];
    const u32 sbase = smem_u32(smbuf);

    const int tid  = threadIdx.x;
    const int lane = tid & 31;
    const int wid  = tid >> 5;
    const int win  = blockIdx.x;
    const int wsel = win & (NWIN - 1);
    const size_t tok0 = (size_t)win * 49;

    // zero k pad rows (49..63) in BOTH buffers once
    {
        float4 z = make_float4(0.f, 0.f, 0.f, 0.f);
        #pragma unroll
        for (int b = 0; b < 2; b++)
            for (int idx = tid; idx < 15 * 8; idx += 128) {
                int r = 49 + (idx >> 3), ch = idx & 7;
                *(float4*)(smbuf + b * HBUF + 8192 + r * 128 + ((ch ^ (r & 7)) << 4)) = z;
            }
    }

    auto stage = [&](int h, int buf) {
        const u32 sq = sbase + (u32)buf * HBUF;
        const size_t qb = ((size_t)win * 6 + h) * 49 * 64;
        for (int idx = tid; idx < 392; idx += 128) {
            int r = idx >> 3, ch = idx & 7;
            u32 off = (u32)(r * 128 + ((ch ^ (r & 7)) << 4));
            cp16(sq + off,         g_qke + qb + r * 64 + ch * 8);
            cp16(sq + 8192u + off, g_kke + qb + r * 64 + ch * 8);
        }
        const size_t vb = ((size_t)win * 6 + h) * 32 * 64;
        for (int idx = tid; idx < 256; idx += 128) {
            int c = idx >> 3, ch = idx & 7;
            u32 off = (u32)(c * 128 + ((ch ^ (c & 7)) << 4));
            cp16(sq + 16384u + off, g_vhe + vb + c * 64 + ch * 8);
            cp16(sq + 20480u + off, g_vle + vb + c * 64 + ch * 8);
        }
        asm volatile("cp.async.commit_group;" ::: "memory");
    };

    const int tcq = 2 * (lane & 3);
    const int r0  = wid * 16 + (lane >> 2);

    stage(0, 0);

    #pragma unroll 1
    for (int h = 0; h < 6; h++) {
        __syncthreads();
        if (h < 5) stage(h + 1, (h + 1) & 1);
        if (h < 5) asm volatile("cp.async.wait_group 1;" ::: "memory");
        else       asm volatile("cp.async.wait_group 0;" ::: "memory");
        __syncthreads();

        const u32 sq  = sbase + (u32)(h & 1) * HBUF;
        const u32 sk  = sq + 8192u;
        const u32 svh = sq + 16384u;
        const u32 svl = sq + 20480u;

        u32 aq[4][4];
        {
            int row = wid * 16 + (lane & 15);
            #pragma unroll
            for (int s = 0; s < 4; s++) {
                int c = s * 2 + (lane >> 4);
                ldm4(aq[s], sq + (u32)(row * 128 + ((c ^ (row & 7)) << 4)));
            }
        }

        float sc[8][4];
        #pragma unroll
        for (int nt = 0; nt < 8; nt++)
            #pragma unroll
            for (int q = 0; q < 4; q++) sc[nt][q] = 0.f;
        {
            const int pa[6] = {0, 1, 0, 1, 2, 3};
            const int pb[6] = {0, 1, 2, 3, 0, 1};
            #pragma unroll
            for (int vs = 0; vs < 6; vs++) {
                #pragma unroll
                for (int np = 0; np < 4; np++) {
                    u32 bk[4];
                    int brow = np * 16 + (lane & 7) + ((lane >> 4) & 1) * 8;
                    int c    = pb[vs] * 2 + ((lane >> 3) & 1);
                    ldm4(bk, sk + (u32)(brow * 128 + ((c ^ (brow & 7)) << 4)));
                    mma16816(sc[np * 2],     aq[pa[vs]], bk[0], bk[1]);
                    mma16816(sc[np * 2 + 1], aq[pa[vs]], bk[2], bk[3]);
                }
            }
        }

        const float* bmb = g_bm + ((size_t)(wsel * 6 + h) * 49) * 56;
        float m0 = -1e30f, m1 = -1e30f;
        #pragma unroll
        for (int nt = 0; nt < 8; nt++) {
            int c0 = nt * 8 + tcq;
            bool k0 = (c0 < 49), k1 = (c0 + 1 < 49);
            float2 bm0 = make_float2(0.f, 0.f), bm1 = make_float2(0.f, 0.f);
            if (k0 && r0 < 49)     bm0 = *(const float2*)(bmb + r0 * 56 + c0);
            if (k0 && r0 + 8 < 49) bm1 = *(const float2*)(bmb + (r0 + 8) * 56 + c0);
            sc[nt][0] = k0 ? sc[nt][0] + bm0.x : -1e30f;
            sc[nt][1] = k1 ? sc[nt][1] + bm0.y : -1e30f;
            sc[nt][2] = k0 ? sc[nt][2] + bm1.x : -1e30f;
            sc[nt][3] = k1 ? sc[nt][3] + bm1.y : -1e30f;
            m0 = fmaxf(m0, fmaxf(sc[nt][0], sc[nt][1]));
            m1 = fmaxf(m1, fmaxf(sc[nt][2], sc[nt][3]));
        }
        m0 = fmaxf(m0, __shfl_xor_sync(0xFFFFFFFFu, m0, 1));
        m0 = fmaxf(m0, __shfl_xor_sync(0xFFFFFFFFu, m0, 2));
        m1 = fmaxf(m1, __shfl_xor_sync(0xFFFFFFFFu, m1, 1));
        m1 = fmaxf(m1, __shfl_xor_sync(0xFFFFFFFFu, m1, 2));
        float s0 = 0.f, s1 = 0.f;
        #pragma unroll
        for (int nt = 0; nt < 8; nt++) {
            sc[nt][0] = __expf(sc[nt][0] - m0); s0 += sc[nt][0];
            sc[nt][1] = __expf(sc[nt][1] - m0); s0 += sc[nt][1];
            sc[nt][2] = __expf(sc[nt][2] - m1); s1 += sc[nt][2];
            sc[nt][3] = __expf(sc[nt][3] - m1); s1 += sc[nt][3];
        }
        s0 += __shfl_xor_sync(0xFFFFFFFFu, s0, 1);
        s0 += __shfl_xor_sync(0xFFFFFFFFu, s0, 2);
        s1 += __shfl_xor_sync(0xFFFFFFFFu, s1, 1);
        s1 += __shfl_xor_sync(0xFFFFFFFFu, s1, 2);
        float inv0 = 1.f / s0, inv1 = 1.f / s1;

        u32 ph[4][4], pl[4][4];
        #pragma unroll
        for (int s = 0; s < 4; s++) {
            float p00 = sc[2 * s][0] * inv0,     p01 = sc[2 * s][1] * inv0;
            float p10 = sc[2 * s][2] * inv1,     p11 = sc[2 * s][3] * inv1;
            float p20 = sc[2 * s + 1][0] * inv0, p21 = sc[2 * s + 1][1] * inv0;
            float p30 = sc[2 * s + 1][2] * inv1, p31 = sc[2 * s + 1][3] * inv1;
            ph[s][0] = cvt2(p00, p01); pl[s][0] = cvt2(p00 - bflo(ph[s][0]), p01 - bfhi(ph[s][0]));
            ph[s][1] = cvt2(p10, p11); pl[s][1] = cvt2(p10 - bflo(ph[s][1]), p11 - bfhi(ph[s][1]));
            ph[s][2] = cvt2(p20, p21); pl[s][2] = cvt2(p20 - bflo(ph[s][2]), p21 - bfhi(ph[s][2]));
            ph[s][3] = cvt2(p30, p31); pl[s][3] = cvt2(p30 - bflo(ph[s][3]), p31 - bfhi(ph[s][3]));
        }

        float ov[4][4];
        #pragma unroll
        for (int nt = 0; nt < 4; nt++)
            #pragma unroll
            for (int q = 0; q < 4; q++) ov[nt][q] = 0.f;
        #pragma unroll
        for (int term = 0; term < 3; term++) {
            const u32 (*pa)[4] = (term == 2) ? pl : ph;
            const u32 vbase = (term == 1) ? svl : svh;
            #pragma unroll
            for (int s = 0; s < 4; s++) {
                #pragma unroll
                for (int np = 0; np < 2; np++) {
                    u32 bv[4];
                    int brow = np * 16 + (lane & 7) + ((lane >> 4) & 1) * 8;
                    int c    = s * 2 + ((lane >> 3) & 1);
                    ldm4(bv, vbase + (u32)(brow * 128 + ((c ^ (brow & 7)) << 4)));
                    mma16816(ov[np * 2],     pa[s], bv[0], bv[1]);
                    mma16816(ov[np * 2 + 1], pa[s], bv[2], bv[3]);
                }
            }
        }

        #pragma unroll
        for (int nt = 0; nt < 4; nt++) {
            int c0 = nt * 8 + tcq;
            #pragma unroll
            for (int half = 0; half < 2; half++) {
                int iv = r0 + half * 8;
                if (iv < 49) {
                    float x0 = ov[nt][half * 2 + 0];
                    float x1 = ov[nt][half * 2 + 1];
                    u32 hp = cvt2(x0, x1);
                    u32 lp = cvt2(x0 - bflo(hp), x1 - bfhi(hp));
                    __nv_bfloat16* base = g_oe + (tok0 + iv) * 384 + h * 32 + c0;
                    *(u32*)(base)       = hp;
                    *(u32*)(base + 192) = lp;
                }
            }
        }
    }
}

// ---------------- launch ----------------
extern "C" void kernel_launch(void* const* d_in, const int* in_sizes, int n_in,
                              void* d_out, int out_size) {
    const float* x          = (const float*)d_in[0];
    const float* mask       = (const float*)d_in[1];
    const float* qkv_w      = (const float*)d_in[2];
    const float* qkv_b      = (const float*)d_in[3];
    const float* proj_w     = (const float*)d_in[4];
    const float* proj_b     = (const float*)d_in[5];
    const float* bias_table = (const float*)d_in[6];
    const int*   rel_index  = (const int*)d_in[7];
    float* out = (float*)d_out;

    prep_kernel<<<120, 256>>>(qkv_w, proj_w, bias_table, rel_index, mask);
    xconv_kernel<<<(TOKS * 96) / 256, 256>>>(x);

    cudaFuncSetAttribute(gemm_mma, cudaFuncAttributeMaxDynamicSharedMemorySize, GSMEM);

    dim3 gq(9, TOKS / 128);
    gemm_mma<<<gq, 256, GSMEM>>>(qkv_b, nullptr, 0);   // QKV -> split q/k/v layouts
    attn_kernel<<<4096, 128>>>();                       // one CTA per window
    dim3 gp(3, TOKS / 128);
    gemm_mma<<<gp, 256, GSMEM>>>(proj_b, out, 1);       // proj: N=192
}

// round 14
// speedup vs baseline: 1.3360x; 1.0221x over previous
#include <cuda_runtime.h>
#include <cuda_bf16.h>
#include <cstdint>

typedef unsigned long long ull;
typedef uint32_t u32;

#define TOKS 200704          // 4096 windows * 49 tokens (= 1568 * 128)
#define NWIN 64
#define QSCALE 0.17677669529663687f

// ---------------- device scratch (zero-initialized at module load) ----------------
__device__ __nv_bfloat16 g_xe[(size_t)TOKS * 384];           // x split [t][hi|lo]
__device__ __nv_bfloat16 g_oe[(size_t)TOKS * 384];           // attn out split [hi|lo]
__device__ __nv_bfloat16 g_qke[(size_t)4096 * 6 * 49 * 64];  // q scaled, [win][h][i][qh(32)|ql(32)]
__device__ __nv_bfloat16 g_kke[(size_t)4096 * 6 * 49 * 64];  // k, [win][h][j][kh|kl]
__device__ __nv_bfloat16 g_vhe[(size_t)4096 * 6 * 32 * 64];  // v hi, [win][h][c][64j] (j>=49 stays 0)
__device__ __nv_bfloat16 g_vle[(size_t)4096 * 6 * 32 * 64];  // v lo
__device__ __nv_bfloat16 g_wqe[576 * 576];                   // qkv_w packed [n][wh|wl|wh]
__device__ __nv_bfloat16 g_wpe[192 * 576];                   // proj_w packed
__device__ float         g_bm[64 * 6 * 49 * 56];             // bias+mask, j padded to 56

__device__ __forceinline__ u32 smem_u32(const void* p) {
    u32 a;
    asm("{ .reg .u64 t; cvta.to.shared.u64 t, %1; cvt.u32.u64 %0, t; }" : "=r"(a) : "l"(p));
    return a;
}
__device__ __forceinline__ void cp16(u32 saddr, const void* gaddr) {
    asm volatile("cp.async.cg.shared.global [%0], [%1], 16;" :: "r"(saddr), "l"(gaddr));
}
__device__ __forceinline__ void ldm4(u32* r, u32 addr) {
    asm volatile("ldmatrix.sync.aligned.m8n8.x4.shared.b16 {%0,%1,%2,%3}, [%4];"
                 : "=r"(r[0]), "=r"(r[1]), "=r"(r[2]), "=r"(r[3]) : "r"(addr));
}
__device__ __forceinline__ void mma16816(float* d, const u32* a, u32 b0, u32 b1) {
    asm volatile("mma.sync.aligned.m16n8k16.row.col.f32.bf16.bf16.f32 "
                 "{%0,%1,%2,%3}, {%4,%5,%6,%7}, {%8,%9}, {%0,%1,%2,%3};"
                 : "+f"(d[0]), "+f"(d[1]), "+f"(d[2]), "+f"(d[3])
                 : "r"(a[0]), "r"(a[1]), "r"(a[2]), "r"(a[3]), "r"(b0), "r"(b1));
}
// pack two f32 into bf16x2: lo half = first arg
__device__ __forceinline__ u32 cvt2(float lo, float hi) {
    u32 r; asm("cvt.rn.bf16x2.f32 %0, %1, %2;" : "=r"(r) : "f"(hi), "f"(lo)); return r;
}
__device__ __forceinline__ float bflo(u32 p) { return __uint_as_float(p << 16); }
__device__ __forceinline__ float bfhi(u32 p) { return __uint_as_float(p & 0xFFFF0000u); }

// ---------------- prep: split-pack weights + combine bias/mask ----------------
__global__ void prep_kernel(const float* __restrict__ qkv_w, const float* __restrict__ proj_w,
                            const float* __restrict__ bias_table, const int* __restrict__ rel_index,
                            const float* __restrict__ mask) {
    int tid = blockIdx.x * blockDim.x + threadIdx.x;
    int stride = gridDim.x * blockDim.x;
    for (int i = tid; i < 576 * 192; i += stride) {
        int n = i / 192, k = i - n * 192;
        float w = qkv_w[i];
        __nv_bfloat16 h = __float2bfloat16(w);
        __nv_bfloat16 l = __float2bfloat16(w - __bfloat162float(h));
        g_wqe[(size_t)n * 576 + k]       = h;
        g_wqe[(size_t)n * 576 + 192 + k] = l;
        g_wqe[(size_t)n * 576 + 384 + k] = h;
    }
    for (int i = tid; i < 192 * 192; i += stride) {
        int n = i / 192, k = i - n * 192;
        float w = proj_w[i];
        __nv_bfloat16 h = __float2bfloat16(w);
        __nv_bfloat16 l = __float2bfloat16(w - __bfloat162float(h));
        g_wpe[(size_t)n * 576 + k]       = h;
        g_wpe[(size_t)n * 576 + 192 + k] = l;
        g_wpe[(size_t)n * 576 + 384 + k] = h;
    }
    for (int i = tid; i < 64 * 6 * 49 * 56; i += stride) {
        int j = i % 56; int rest = i / 56;
        int ir = rest % 49; rest /= 49;
        int hh = rest % 6; int wm = rest / 6;
        float v = 0.f;
        if (j < 49)
            v = bias_table[rel_index[ir * 49 + j] * 6 + hh] + mask[wm * 2401 + ir * 49 + j];
        g_bm[i] = v;
    }
}

// ---------------- x -> bf16 split [hi|lo] (384 wide) ----------------
__global__ void xconv_kernel(const float* __restrict__ x) {
    size_t idx = (size_t)blockIdx.x * 256 + threadIdx.x;
    size_t t = idx / 96;
    int p = (int)(idx - t * 96);
    float2 v = *(const float2*)(x + t * 192 + 2 * p);
    __nv_bfloat16 h0 = __float2bfloat16(v.x), h1 = __float2bfloat16(v.y);
    __nv_bfloat16 l0 = __float2bfloat16(v.x - __bfloat162float(h0));
    __nv_bfloat16 l1 = __float2bfloat16(v.y - __bfloat162float(h1));
    __nv_bfloat162 hp; hp.x = h0; hp.y = h1;
    __nv_bfloat162 lp; lp.x = l0; lp.y = l1;
    size_t base = t * 384 + 2 * p;
    *(__nv_bfloat162*)(g_xe + base)       = hp;
    *(__nv_bfloat162*)(g_xe + base + 192) = lp;
}

// ---------------- mma.sync GEMM, 3-stage cp.async pipeline, ONE sync/chunk ----
// 3 CTAs/SM (216 KB smem of 228 KB) -> 24 warps/SM for latency hiding.
#define GSMEM 73728
#define STG_STRIDE 68

__global__ __launch_bounds__(256, 3)
void gemm_mma(const float* __restrict__ bias, float* __restrict__ out_param, int which) {
    extern __shared__ char sm[];
    const __nv_bfloat16* Ae = which ? g_oe : g_xe;
    const __nv_bfloat16* We = which ? g_wpe : g_wqe;
    const int Ncols = which ? 192 : 576;

    const u32 sb = smem_u32(sm);
    const int tid  = threadIdx.x;
    const int lane = tid & 31;
    const int wid  = tid >> 5;
    const int wm   = wid >> 1;
    const int wn   = wid & 1;
    const size_t row0 = (size_t)blockIdx.y * 128;
    const int    n0   = blockIdx.x * 64;

    float acc[2][4][4];
    #pragma unroll
    for (int mt = 0; mt < 2; mt++)
        #pragma unroll
        for (int nt = 0; nt < 4; nt++)
            #pragma unroll
            for (int q = 0; q < 4; q++) acc[mt][nt][q] = 0.f;

    auto load_chunk = [&](int kc, int buf) {
        int aoff = (kc < 3) ? kc * 64 : (kc < 6 ? (kc - 3) * 64 : (kc - 6) * 64 + 192);
        const u32 sA = sb + (u32)buf * 16384u;
        const u32 sB = sb + 49152u + (u32)buf * 8192u;
        #pragma unroll
        for (int s = 0; s < 6; s++) {
            int j = tid + s * 256;
            if (j < 1024) {
                int r = j >> 3, c = j & 7;
                u32 saddr = sA + (u32)r * 128u + (u32)((c ^ (r & 7)) << 4);
                cp16(saddr, Ae + (row0 + r) * 384 + aoff + c * 8);
            } else {
                int jj = j - 1024;
                int r = jj >> 3, c = jj & 7;
                u32 saddr = sB + (u32)r * 128u + (u32)((c ^ (r & 7)) << 4);
                cp16(saddr, We + (size_t)(n0 + r) * 576 + kc * 64 + c * 8);
            }
        }
        asm volatile("cp.async.commit_group;" ::: "memory");
    };

    load_chunk(0, 0);
    load_chunk(1, 1);

    #pragma unroll 1
    for (int kc = 0; kc < 9; kc++) {
        if (kc < 8) asm volatile("cp.async.wait_group 1;" ::: "memory");
        else        asm volatile("cp.async.wait_group 0;" ::: "memory");
        __syncthreads();
        if (kc + 2 < 9) load_chunk(kc + 2, (kc + 2) % 3);

        const int buf = kc % 3;
        const u32 sA = sb + (u32)buf * 16384u;
        const u32 sB = sb + 49152u + (u32)buf * 8192u;

        #pragma unroll
        for (int ks = 0; ks < 4; ks++) {
            u32 afr[2][4], bfr[2][4];
            #pragma unroll
            for (int mt = 0; mt < 2; mt++) {
                int row = wm * 32 + mt * 16 + (lane & 15);
                int c   = ks * 2 + (lane >> 4);
                ldm4(afr[mt], sA + (u32)row * 128u + (u32)((c ^ (row & 7)) << 4));
            }
            #pragma unroll
            for (int np = 0; np < 2; np++) {
                int brow = wn * 32 + np * 16 + (lane & 7) + ((lane >> 4) & 1) * 8;
                int c    = ks * 2 + ((lane >> 3) & 1);
                ldm4(bfr[np], sB + (u32)brow * 128u + (u32)((c ^ (brow & 7)) << 4));
            }
            #pragma unroll
            for (int mt = 0; mt < 2; mt++)
                #pragma unroll
                for (int nt = 0; nt < 4; nt++)
                    mma16816(acc[mt][nt], afr[mt], bfr[nt >> 1][(nt & 1) * 2], bfr[nt >> 1][(nt & 1) * 2 + 1]);
        }
    }

    const int tr = lane >> 2, tc = (lane & 3) * 2;
    if (which) {
        #pragma unroll
        for (int mt = 0; mt < 2; mt++)
            #pragma unroll
            for (int nt = 0; nt < 4; nt++) {
                int col = n0 + wn * 32 + nt * 8 + tc;
                float b0 = bias[col], b1 = bias[col + 1];
                size_t r_lo = row0 + wm * 32 + mt * 16 + tr;
                float2 v0; v0.x = acc[mt][nt][0] + b0; v0.y = acc[mt][nt][1] + b1;
                float2 v1; v1.x = acc[mt][nt][2] + b0; v1.y = acc[mt][nt][3] + b1;
                *(float2*)(out_param + r_lo * Ncols + col)       = v0;
                *(float2*)(out_param + (r_lo + 8) * Ncols + col) = v1;
            }
    } else {
        __syncthreads();                 // all compute done before reusing buffers as stg
        // ---- stage acc (bias + optional q-scale applied) into smem fp32 tile ----
        const int sec = n0 / 192;        // 0=q, 1=k, 2=v
        const int head0 = (n0 % 192) >> 5;
        float* stg = (float*)sm;         // [128][STG_STRIDE]
        #pragma unroll
        for (int mt = 0; mt < 2; mt++)
            #pragma unroll
            for (int nt = 0; nt < 4; nt++) {
                int col = wn * 32 + nt * 8 + tc;
                float b0 = bias[n0 + col], b1 = bias[n0 + col + 1];
                #pragma unroll
                for (int half = 0; half < 2; half++) {
                    int r = wm * 32 + mt * 16 + tr + half * 8;
                    float x0 = acc[mt][nt][half * 2 + 0] + b0;
                    float x1 = acc[mt][nt][half * 2 + 1] + b1;
                    if (sec == 0) { x0 *= QSCALE; x1 *= QSCALE; }
                    stg[r * STG_STRIDE + col]     = x0;
                    stg[r * STG_STRIDE + col + 1] = x1;
                }
            }
        __syncthreads();

        if (sec < 2) {
            // q/k: 128 tokens x 16 colgroups of 4; per job write 8B hi + 8B lo
            __nv_bfloat16* gbase = sec == 0 ? g_qke : g_kke;
            for (int idx = tid; idx < 2048; idx += 256) {
                int t = idx >> 4, cg = idx & 15;
                int hh = cg >> 3, d0 = (cg & 7) * 4;
                u32 r = (u32)(row0 + t);
                u32 win = r / 49u, i = r - win * 49u;
                const float* sp = stg + t * STG_STRIDE + hh * 32 + d0;
                float x0 = sp[0], x1 = sp[1], x2 = sp[2], x3 = sp[3];
                u32 hp0 = cvt2(x0, x1), hp1 = cvt2(x2, x3);
                u32 lp0 = cvt2(x0 - bflo(hp0), x1 - bfhi(hp0));
                u32 lp1 = cvt2(x2 - bflo(hp1), x3 - bfhi(hp1));
                __nv_bfloat16* base = gbase + (((size_t)win * 6 + head0 + hh) * 49 + i) * 64 + d0;
                ((u32*)base)[0] = hp0; ((u32*)base)[1] = hp1;
                ((u32*)(base + 32))[0] = lp0; ((u32*)(base + 32))[1] = lp1;
            }
        } else {
            // v: token-fastest lane order -> contiguous 2B stores per window segment
            for (int idx = tid; idx < 8192; idx += 256) {
                int d = idx >> 7, t = idx & 127;
                int hh = d >> 5, dd = d & 31;
                u32 r = (u32)(row0 + t);
                u32 win = r / 49u, i = r - win * 49u;
                float x = stg[t * STG_STRIDE + d];
                __nv_bfloat16 h0 = __float2bfloat16(x);
                size_t vb = (((size_t)win * 6 + head0 + hh) * 32 + dd) * 64 + i;
                g_vhe[vb] = h0;
                g_vle[vb] = __float2bfloat16(x - __bfloat162float(h0));
            }
        }
    }
}

// ---------------- attention: tensor-core QK^T and P@V, softmax in registers ----
// One CTA per window, 128 threads, 6 heads, cp.async double-buffered staging.
#define HBUF 24576

__global__ __launch_bounds__(128, 4)
void attn_kernel() {
    __shared__ __align__(16) char smbuf[2 * HBUF];
    const u32 sbase = smem_u32(smbuf);

    const int tid  = threadIdx.x;
    const int lane = tid & 31;
    const int wid  = tid >> 5;
    const int win  = blockIdx.x;
    const int wsel = win & (NWIN - 1);
    const size_t tok0 = (size_t)win * 49;

    // zero k pad rows (49..63) in BOTH buffers once
    {
        float4 z = make_float4(0.f, 0.f, 0.f, 0.f);
        #pragma unroll
        for (int b = 0; b < 2; b++)
            for (int idx = tid; idx < 15 * 8; idx += 128) {
                int r = 49 + (idx >> 3), ch = idx & 7;
                *(float4*)(smbuf + b * HBUF + 8192 + r * 128 + ((ch ^ (r & 7)) << 4)) = z;
            }
    }

    auto stage = [&](int h, int buf) {
        const u32 sq = sbase + (u32)buf * HBUF;
        const size_t qb = ((size_t)win * 6 + h) * 49 * 64;
        for (int idx = tid; idx < 392; idx += 128) {
            int r = idx >> 3, ch = idx & 7;
            u32 off = (u32)(r * 128 + ((ch ^ (r & 7)) << 4));
            cp16(sq + off,         g_qke + qb + r * 64 + ch * 8);
            cp16(sq + 8192u + off, g_kke + qb + r * 64 + ch * 8);
        }
        const size_t vb = ((size_t)win * 6 + h) * 32 * 64;
        for (int idx = tid; idx < 256; idx += 128) {
            int c = idx >> 3, ch = idx & 7;
            u32 off = (u32)(c * 128 + ((ch ^ (c & 7)) << 4));
            cp16(sq + 16384u + off, g_vhe + vb + c * 64 + ch * 8);
            cp16(sq + 20480u + off, g_vle + vb + c * 64 + ch * 8);
        }
        asm volatile("cp.async.commit_group;" ::: "memory");
    };

    const int tcq = 2 * (lane & 3);
    const int r0  = wid * 16 + (lane >> 2);

    stage(0, 0);

    #pragma unroll 1
    for (int h = 0; h < 6; h++) {
        __syncthreads();
        if (h < 5) stage(h + 1, (h + 1) & 1);
        if (h < 5) asm volatile("cp.async.wait_group 1;" ::: "memory");
        else       asm volatile("cp.async.wait_group 0;" ::: "memory");
        __syncthreads();

        const u32 sq  = sbase + (u32)(h & 1) * HBUF;
        const u32 sk  = sq + 8192u;
        const u32 svh = sq + 16384u;
        const u32 svl = sq + 20480u;

        u32 aq[4][4];
        {
            int row = wid * 16 + (lane & 15);
            #pragma unroll
            for (int s = 0; s < 4; s++) {
                int c = s * 2 + (lane >> 4);
                ldm4(aq[s], sq + (u32)(row * 128 + ((c ^ (row & 7)) << 4)));
            }
        }

        float sc[8][4];
        #pragma unroll
        for (int nt = 0; nt < 8; nt++)
            #pragma unroll
            for (int q = 0; q < 4; q++) sc[nt][q] = 0.f;
        {
            const int pa[6] = {0, 1, 0, 1, 2, 3};
            const int pb[6] = {0, 1, 2, 3, 0, 1};
            #pragma unroll
            for (int vs = 0; vs < 6; vs++) {
                #pragma unroll
                for (int np = 0; np < 4; np++) {
                    u32 bk[4];
                    int brow = np * 16 + (lane & 7) + ((lane >> 4) & 1) * 8;
                    int c    = pb[vs] * 2 + ((lane >> 3) & 1);
                    ldm4(bk, sk + (u32)(brow * 128 + ((c ^ (brow & 7)) << 4)));
                    mma16816(sc[np * 2],     aq[pa[vs]], bk[0], bk[1]);
                    mma16816(sc[np * 2 + 1], aq[pa[vs]], bk[2], bk[3]);
                }
            }
        }

        const float* bmb = g_bm + ((size_t)(wsel * 6 + h) * 49) * 56;
        float m0 = -1e30f, m1 = -1e30f;
        #pragma unroll
        for (int nt = 0; nt < 8; nt++) {
            int c0 = nt * 8 + tcq;
            bool k0 = (c0 < 49), k1 = (c0 + 1 < 49);
            float2 bm0 = make_float2(0.f, 0.f), bm1 = make_float2(0.f, 0.f);
            if (k0 && r0 < 49)     bm0 = *(const float2*)(bmb + r0 * 56 + c0);
            if (k0 && r0 + 8 < 49) bm1 = *(const float2*)(bmb + (r0 + 8) * 56 + c0);
            sc[nt][0] = k0 ? sc[nt][0] + bm0.x : -1e30f;
            sc[nt][1] = k1 ? sc[nt][1] + bm0.y : -1e30f;
            sc[nt][2] = k0 ? sc[nt][2] + bm1.x : -1e30f;
            sc[nt][3] = k1 ? sc[nt][3] + bm1.y : -1e30f;
            m0 = fmaxf(m0, fmaxf(sc[nt][0], sc[nt][1]));
            m1 = fmaxf(m1, fmaxf(sc[nt][2], sc[nt][3]));
        }
        m0 = fmaxf(m0, __shfl_xor_sync(0xFFFFFFFFu, m0, 1));
        m0 = fmaxf(m0, __shfl_xor_sync(0xFFFFFFFFu, m0, 2));
        m1 = fmaxf(m1, __shfl_xor_sync(0xFFFFFFFFu, m1, 1));
        m1 = fmaxf(m1, __shfl_xor_sync(0xFFFFFFFFu, m1, 2));
        float s0 = 0.f, s1 = 0.f;
        #pragma unroll
        for (int nt = 0; nt < 8; nt++) {
            sc[nt][0] = __expf(sc[nt][0] - m0); s0 += sc[nt][0];
            sc[nt][1] = __expf(sc[nt][1] - m0); s0 += sc[nt][1];
            sc[nt][2] = __expf(sc[nt][2] - m1); s1 += sc[nt][2];
            sc[nt][3] = __expf(sc[nt][3] - m1); s1 += sc[nt][3];
        }
        s0 += __shfl_xor_sync(0xFFFFFFFFu, s0, 1);
        s0 += __shfl_xor_sync(0xFFFFFFFFu, s0, 2);
        s1 += __shfl_xor_sync(0xFFFFFFFFu, s1, 1);
        s1 += __shfl_xor_sync(0xFFFFFFFFu, s1, 2);
        float inv0 = 1.f / s0, inv1 = 1.f / s1;

        u32 ph[4][4], pl[4][4];
        #pragma unroll
        for (int s = 0; s < 4; s++) {
            float p00 = sc[2 * s][0] * inv0,     p01 = sc[2 * s][1] * inv0;
            float p10 = sc[2 * s][2] * inv1,     p11 = sc[2 * s][3] * inv1;
            float p20 = sc[2 * s + 1][0] * inv0, p21 = sc[2 * s + 1][1] * inv0;
            float p30 = sc[2 * s + 1][2] * inv1, p31 = sc[2 * s + 1][3] * inv1;
            ph[s][0] = cvt2(p00, p01); pl[s][0] = cvt2(p00 - bflo(ph[s][0]), p01 - bfhi(ph[s][0]));
            ph[s][1] = cvt2(p10, p11); pl[s][1] = cvt2(p10 - bflo(ph[s][1]), p11 - bfhi(ph[s][1]));
            ph[s][2] = cvt2(p20, p21); pl[s][2] = cvt2(p20 - bflo(ph[s][2]), p21 - bfhi(ph[s][2]));
            ph[s][3] = cvt2(p30, p31); pl[s][3] = cvt2(p30 - bflo(ph[s][3]), p31 - bfhi(ph[s][3]));
        }

        float ov[4][4];
        #pragma unroll
        for (int nt = 0; nt < 4; nt++)
            #pragma unroll
            for (int q = 0; q < 4; q++) ov[nt][q] = 0.f;
        #pragma unroll
        for (int term = 0; term < 3; term++) {
            const u32 (*pa)[4] = (term == 2) ? pl : ph;
            const u32 vbase = (term == 1) ? svl : svh;
            #pragma unroll
            for (int s = 0; s < 4; s++) {
                #pragma unroll
                for (int np = 0; np < 2; np++) {
                    u32 bv[4];
                    int brow = np * 16 + (lane & 7) + ((lane >> 4) & 1) * 8;
                    int c    = s * 2 + ((lane >> 3) & 1);
                    ldm4(bv, vbase + (u32)(brow * 128 + ((c ^ (brow & 7)) << 4)));
                    mma16816(ov[np * 2],     pa[s], bv[0], bv[1]);
                    mma16816(ov[np * 2 + 1], pa[s], bv[2], bv[3]);
                }
            }
        }

        #pragma unroll
        for (int nt = 0; nt < 4; nt++) {
            int c0 = nt * 8 + tcq;
            #pragma unroll
            for (int half = 0; half < 2; half++) {
                int iv = r0 + half * 8;
                if (iv < 49) {
                    float x0 = ov[nt][half * 2 + 0];
                    float x1 = ov[nt][half * 2 + 1];
                    u32 hp = cvt2(x0, x1);
                    u32 lp = cvt2(x0 - bflo(hp), x1 - bfhi(hp));
                    __nv_bfloat16* base = g_oe + (tok0 + iv) * 384 + h * 32 + c0;
                    *(u32*)(base)       = hp;
                    *(u32*)(base + 192) = lp;
                }
            }
        }
    }
}

// ---------------- launch ----------------
extern "C" void kernel_launch(void* const* d_in, const int* in_sizes, int n_in,
                              void* d_out, int out_size) {
    const float* x          = (const float*)d_in[0];
    const float* mask       = (const float*)d_in[1];
    const float* qkv_w      = (const float*)d_in[2];
    const float* qkv_b      = (const float*)d_in[3];
    const float* proj_w     = (const float*)d_in[4];
    const float* proj_b     = (const float*)d_in[5];
    const float* bias_table = (const float*)d_in[6];
    const int*   rel_index  = (const int*)d_in[7];
    float* out = (float*)d_out;

    prep_kernel<<<120, 256>>>(qkv_w, proj_w, bias_table, rel_index, mask);
    xconv_kernel<<<(TOKS * 96) / 256, 256>>>(x);

    cudaFuncSetAttribute(gemm_mma, cudaFuncAttributeMaxDynamicSharedMemorySize, GSMEM);

    dim3 gq(9, TOKS / 128);
    gemm_mma<<<gq, 256, GSMEM>>>(qkv_b, nullptr, 0);   // QKV -> split q/k/v layouts
    attn_kernel<<<4096, 128>>>();                       // one CTA per window
    dim3 gp(3, TOKS / 128);
    gemm_mma<<<gp, 256, GSMEM>>>(proj_b, out, 1);       // proj: N=192
}

// round 15
// speedup vs baseline: 1.3801x; 1.0330x over previous
#include <cuda_runtime.h>
#include <cuda_bf16.h>
#include <cstdint>

typedef unsigned long long ull;
typedef uint32_t u32;

#define TOKS 200704          // 4096 windows * 49 tokens (= 1568 * 128)
#define NWIN 64
#define QSCALE 0.17677669529663687f

// ---------------- device scratch (zero-initialized at module load) ----------------
__device__ __nv_bfloat16 g_xe[(size_t)TOKS * 384];           // x split [t][hi|lo]
__device__ __nv_bfloat16 g_oe[(size_t)TOKS * 384];           // attn out split [hi|lo]
__device__ __nv_bfloat16 g_qke[(size_t)4096 * 6 * 49 * 64];  // q scaled, [win][h][i][qh(32)|ql(32)]
__device__ __nv_bfloat16 g_kke[(size_t)4096 * 6 * 49 * 64];  // k, [win][h][j][kh|kl]
__device__ __nv_bfloat16 g_vhe[(size_t)4096 * 6 * 32 * 64];  // v hi, [win][h][c][64j] (j>=49 stays 0)
__device__ __nv_bfloat16 g_vle[(size_t)4096 * 6 * 32 * 64];  // v lo
__device__ __nv_bfloat16 g_wqe[576 * 576];                   // qkv_w packed [n][wh|wl|wh]
__device__ __nv_bfloat16 g_wpe[192 * 576];                   // proj_w packed
__device__ float         g_bm[64 * 6 * 49 * 56];             // bias+mask, j padded to 56

__device__ __forceinline__ u32 smem_u32(const void* p) {
    u32 a;
    asm("{ .reg .u64 t; cvta.to.shared.u64 t, %1; cvt.u32.u64 %0, t; }" : "=r"(a) : "l"(p));
    return a;
}
__device__ __forceinline__ void cp16(u32 saddr, const void* gaddr) {
    asm volatile("cp.async.cg.shared.global [%0], [%1], 16;" :: "r"(saddr), "l"(gaddr));
}
__device__ __forceinline__ void ldm4(u32* r, u32 addr) {
    asm volatile("ldmatrix.sync.aligned.m8n8.x4.shared.b16 {%0,%1,%2,%3}, [%4];"
                 : "=r"(r[0]), "=r"(r[1]), "=r"(r[2]), "=r"(r[3]) : "r"(addr));
}
__device__ __forceinline__ void mma16816(float* d, const u32* a, u32 b0, u32 b1) {
    asm volatile("mma.sync.aligned.m16n8k16.row.col.f32.bf16.bf16.f32 "
                 "{%0,%1,%2,%3}, {%4,%5,%6,%7}, {%8,%9}, {%0,%1,%2,%3};"
                 : "+f"(d[0]), "+f"(d[1]), "+f"(d[2]), "+f"(d[3])
                 : "r"(a[0]), "r"(a[1]), "r"(a[2]), "r"(a[3]), "r"(b0), "r"(b1));
}
// pack two f32 into bf16x2: lo half = first arg
__device__ __forceinline__ u32 cvt2(float lo, float hi) {
    u32 r; asm("cvt.rn.bf16x2.f32 %0, %1, %2;" : "=r"(r) : "f"(hi), "f"(lo)); return r;
}
__device__ __forceinline__ float bflo(u32 p) { return __uint_as_float(p << 16); }
__device__ __forceinline__ float bfhi(u32 p) { return __uint_as_float(p & 0xFFFF0000u); }

// ---------------- prep: split-pack weights + combine bias/mask ----------------
__global__ void prep_kernel(const float* __restrict__ qkv_w, const float* __restrict__ proj_w,
                            const float* __restrict__ bias_table, const int* __restrict__ rel_index,
                            const float* __restrict__ mask) {
    int tid = blockIdx.x * blockDim.x + threadIdx.x;
    int stride = gridDim.x * blockDim.x;
    for (int i = tid; i < 576 * 192; i += stride) {
        int n = i / 192, k = i - n * 192;
        float w = qkv_w[i];
        __nv_bfloat16 h = __float2bfloat16(w);
        __nv_bfloat16 l = __float2bfloat16(w - __bfloat162float(h));
        g_wqe[(size_t)n * 576 + k]       = h;
        g_wqe[(size_t)n * 576 + 192 + k] = l;
        g_wqe[(size_t)n * 576 + 384 + k] = h;
    }
    for (int i = tid; i < 192 * 192; i += stride) {
        int n = i / 192, k = i - n * 192;
        float w = proj_w[i];
        __nv_bfloat16 h = __float2bfloat16(w);
        __nv_bfloat16 l = __float2bfloat16(w - __bfloat162float(h));
        g_wpe[(size_t)n * 576 + k]       = h;
        g_wpe[(size_t)n * 576 + 192 + k] = l;
        g_wpe[(size_t)n * 576 + 384 + k] = h;
    }
    for (int i = tid; i < 64 * 6 * 49 * 56; i += stride) {
        int j = i % 56; int rest = i / 56;
        int ir = rest % 49; rest /= 49;
        int hh = rest % 6; int wm = rest / 6;
        float v = 0.f;
        if (j < 49)
            v = bias_table[rel_index[ir * 49 + j] * 6 + hh] + mask[wm * 2401 + ir * 49 + j];
        g_bm[i] = v;
    }
}

// ---------------- x -> bf16 split [hi|lo] (384 wide) ----------------
__global__ void xconv_kernel(const float* __restrict__ x) {
    size_t idx = (size_t)blockIdx.x * 256 + threadIdx.x;
    size_t t = idx / 96;
    int p = (int)(idx - t * 96);
    float2 v = *(const float2*)(x + t * 192 + 2 * p);
    __nv_bfloat16 h0 = __float2bfloat16(v.x), h1 = __float2bfloat16(v.y);
    __nv_bfloat16 l0 = __float2bfloat16(v.x - __bfloat162float(h0));
    __nv_bfloat16 l1 = __float2bfloat16(v.y - __bfloat162float(h1));
    __nv_bfloat162 hp; hp.x = h0; hp.y = h1;
    __nv_bfloat162 lp; lp.x = l0; lp.y = l1;
    size_t base = t * 384 + 2 * p;
    *(__nv_bfloat162*)(g_xe + base)       = hp;
    *(__nv_bfloat162*)(g_xe + base + 192) = lp;
}

// ---------------- mma.sync GEMM: CTA tile 128x96, 3-stage cp.async ----------------
// 8 warps (4m x 2n), warp tile 32x48; A re-read by only 6 (QKV) / 2 (proj) n-CTAs.
// smem: A bufs 3x16384 @0, B bufs 3x12288 @49152 -> 86016 B, 2 CTAs/SM.
#define GSMEM 86016
#define STG_STRIDE 100

__global__ __launch_bounds__(256, 2)
void gemm_mma(const float* __restrict__ bias, float* __restrict__ out_param, int which) {
    extern __shared__ char sm[];
    const __nv_bfloat16* Ae = which ? g_oe : g_xe;
    const __nv_bfloat16* We = which ? g_wpe : g_wqe;
    const int Ncols = which ? 192 : 576;

    const u32 sb = smem_u32(sm);
    const int tid  = threadIdx.x;
    const int lane = tid & 31;
    const int wid  = tid >> 5;
    const int wm   = wid >> 1;        // 0..3
    const int wn   = wid & 1;         // 0..1
    const size_t row0 = (size_t)blockIdx.y * 128;
    const int    n0   = blockIdx.x * 96;

    float acc[2][6][4];
    #pragma unroll
    for (int mt = 0; mt < 2; mt++)
        #pragma unroll
        for (int nt = 0; nt < 6; nt++)
            #pragma unroll
            for (int q = 0; q < 4; q++) acc[mt][nt][q] = 0.f;

    auto load_chunk = [&](int kc, int buf) {
        int aoff = (kc < 3) ? kc * 64 : (kc < 6 ? (kc - 3) * 64 : (kc - 6) * 64 + 192);
        const u32 sA = sb + (u32)buf * 16384u;
        const u32 sB = sb + 49152u + (u32)buf * 12288u;
        #pragma unroll
        for (int s = 0; s < 7; s++) {
            int j = tid + s * 256;
            if (j < 1024) {
                int r = j >> 3, c = j & 7;
                u32 saddr = sA + (u32)r * 128u + (u32)((c ^ (r & 7)) << 4);
                cp16(saddr, Ae + (row0 + r) * 384 + aoff + c * 8);
            } else {
                int jj = j - 1024;          // 0..767
                int r = jj >> 3, c = jj & 7;
                u32 saddr = sB + (u32)r * 128u + (u32)((c ^ (r & 7)) << 4);
                cp16(saddr, We + (size_t)(n0 + r) * 576 + kc * 64 + c * 8);
            }
        }
        asm volatile("cp.async.commit_group;" ::: "memory");
    };

    load_chunk(0, 0);
    load_chunk(1, 1);

    #pragma unroll 1
    for (int kc = 0; kc < 9; kc++) {
        if (kc < 8) asm volatile("cp.async.wait_group 1;" ::: "memory");
        else        asm volatile("cp.async.wait_group 0;" ::: "memory");
        __syncthreads();
        if (kc + 2 < 9) load_chunk(kc + 2, (kc + 2) % 3);

        const int buf = kc % 3;
        const u32 sA = sb + (u32)buf * 16384u;
        const u32 sB = sb + 49152u + (u32)buf * 12288u;

        #pragma unroll
        for (int ks = 0; ks < 4; ks++) {
            u32 afr[2][4], bfr[3][4];
            #pragma unroll
            for (int mt = 0; mt < 2; mt++) {
                int row = wm * 32 + mt * 16 + (lane & 15);
                int c   = ks * 2 + (lane >> 4);
                ldm4(afr[mt], sA + (u32)row * 128u + (u32)((c ^ (row & 7)) << 4));
            }
            #pragma unroll
            for (int np = 0; np < 3; np++) {
                int brow = wn * 48 + np * 16 + (lane & 7) + ((lane >> 4) & 1) * 8;
                int c    = ks * 2 + ((lane >> 3) & 1);
                ldm4(bfr[np], sB + (u32)brow * 128u + (u32)((c ^ (brow & 7)) << 4));
            }
            #pragma unroll
            for (int mt = 0; mt < 2; mt++)
                #pragma unroll
                for (int nt = 0; nt < 6; nt++)
                    mma16816(acc[mt][nt], afr[mt], bfr[nt >> 1][(nt & 1) * 2], bfr[nt >> 1][(nt & 1) * 2 + 1]);
        }
    }

    const int tr = lane >> 2, tc = (lane & 3) * 2;
    if (which) {
        #pragma unroll
        for (int mt = 0; mt < 2; mt++)
            #pragma unroll
            for (int nt = 0; nt < 6; nt++) {
                int col = n0 + wn * 48 + nt * 8 + tc;
                float b0 = bias[col], b1 = bias[col + 1];
                size_t r_lo = row0 + wm * 32 + mt * 16 + tr;
                float2 v0; v0.x = acc[mt][nt][0] + b0; v0.y = acc[mt][nt][1] + b1;
                float2 v1; v1.x = acc[mt][nt][2] + b0; v1.y = acc[mt][nt][3] + b1;
                *(float2*)(out_param + r_lo * Ncols + col)       = v0;
                *(float2*)(out_param + (r_lo + 8) * Ncols + col) = v1;
            }
    } else {
        __syncthreads();                 // all compute done before reusing buffers as stg
        // ---- stage acc (bias + optional q-scale applied) into smem fp32 tile ----
        const int sec = n0 / 192;        // 0=q, 1=k, 2=v (96-tile never spans sections)
        const int head0 = (n0 % 192) >> 5;   // 0 or 3
        float* stg = (float*)sm;         // [128][STG_STRIDE]
        #pragma unroll
        for (int mt = 0; mt < 2; mt++)
            #pragma unroll
            for (int nt = 0; nt < 6; nt++) {
                int col = wn * 48 + nt * 8 + tc;
                float b0 = bias[n0 + col], b1 = bias[n0 + col + 1];
                #pragma unroll
                for (int half = 0; half < 2; half++) {
                    int r = wm * 32 + mt * 16 + tr + half * 8;
                    float x0 = acc[mt][nt][half * 2 + 0] + b0;
                    float x1 = acc[mt][nt][half * 2 + 1] + b1;
                    if (sec == 0) { x0 *= QSCALE; x1 *= QSCALE; }
                    stg[r * STG_STRIDE + col]     = x0;
                    stg[r * STG_STRIDE + col + 1] = x1;
                }
            }
        __syncthreads();

        if (sec < 2) {
            // q/k: 128 tokens x 24 colgroups of 4; per job write 8B hi + 8B lo
            __nv_bfloat16* gbase = sec == 0 ? g_qke : g_kke;
            for (int idx = tid; idx < 3072; idx += 256) {
                int t = idx / 24, cg = idx - (idx / 24) * 24;
                int hh = cg >> 3, d0 = (cg & 7) * 4;
                u32 r = (u32)(row0 + t);
                u32 win = r / 49u, i = r - win * 49u;
                const float* sp = stg + t * STG_STRIDE + hh * 32 + d0;
                float x0 = sp[0], x1 = sp[1], x2 = sp[2], x3 = sp[3];
                u32 hp0 = cvt2(x0, x1), hp1 = cvt2(x2, x3);
                u32 lp0 = cvt2(x0 - bflo(hp0), x1 - bfhi(hp0));
                u32 lp1 = cvt2(x2 - bflo(hp1), x3 - bfhi(hp1));
                __nv_bfloat16* base = gbase + (((size_t)win * 6 + head0 + hh) * 49 + i) * 64 + d0;
                ((u32*)base)[0] = hp0; ((u32*)base)[1] = hp1;
                ((u32*)(base + 32))[0] = lp0; ((u32*)(base + 32))[1] = lp1;
            }
        } else {
            // v: token-fastest lane order -> contiguous 2B stores per window segment
            for (int idx = tid; idx < 12288; idx += 256) {
                int d = idx >> 7, t = idx & 127;
                int hh = d >> 5, dd = d & 31;
                u32 r = (u32)(row0 + t);
                u32 win = r / 49u, i = r - win * 49u;
                float x = stg[t * STG_STRIDE + d];
                __nv_bfloat16 h0 = __float2bfloat16(x);
                size_t vb = (((size_t)win * 6 + head0 + hh) * 32 + dd) * 64 + i;
                g_vhe[vb] = h0;
                g_vle[vb] = __float2bfloat16(x - __bfloat162float(h0));
            }
        }
    }
}

// ---------------- attention: tensor-core QK^T and P@V, softmax in registers ----
// One CTA per window, 128 threads, 6 heads, cp.async double-buffered staging.
#define HBUF 24576

__global__ __launch_bounds__(128, 4)
void attn_kernel() {
    __shared__ __align__(16) char smbuf[2 * HBUF];
    const u32 sbase = smem_u32(smbuf);

    const int tid  = threadIdx.x;
    const int lane = tid & 31;
    const int wid  = tid >> 5;
    const int win  = blockIdx.x;
    const int wsel = win & (NWIN - 1);
    const size_t tok0 = (size_t)win * 49;

    // zero k pad rows (49..63) in BOTH buffers once
    {
        float4 z = make_float4(0.f, 0.f, 0.f, 0.f);
        #pragma unroll
        for (int b = 0; b < 2; b++)
            for (int idx = tid; idx < 15 * 8; idx += 128) {
                int r = 49 + (idx >> 3), ch = idx & 7;
                *(float4*)(smbuf + b * HBUF + 8192 + r * 128 + ((ch ^ (r & 7)) << 4)) = z;
            }
    }

    auto stage = [&](int h, int buf) {
        const u32 sq = sbase + (u32)buf * HBUF;
        const size_t qb = ((size_t)win * 6 + h) * 49 * 64;
        for (int idx = tid; idx < 392; idx += 128) {
            int r = idx >> 3, ch = idx & 7;
            u32 off = (u32)(r * 128 + ((ch ^ (r & 7)) << 4));
            cp16(sq + off,         g_qke + qb + r * 64 + ch * 8);
            cp16(sq + 8192u + off, g_kke + qb + r * 64 + ch * 8);
        }
        const size_t vb = ((size_t)win * 6 + h) * 32 * 64;
        for (int idx = tid; idx < 256; idx += 128) {
            int c = idx >> 3, ch = idx & 7;
            u32 off = (u32)(c * 128 + ((ch ^ (c & 7)) << 4));
            cp16(sq + 16384u + off, g_vhe + vb + c * 64 + ch * 8);
            cp16(sq + 20480u + off, g_vle + vb + c * 64 + ch * 8);
        }
        asm volatile("cp.async.commit_group;" ::: "memory");
    };

    const int tcq = 2 * (lane & 3);
    const int r0  = wid * 16 + (lane >> 2);

    stage(0, 0);

    #pragma unroll 1
    for (int h = 0; h < 6; h++) {
        __syncthreads();
        if (h < 5) stage(h + 1, (h + 1) & 1);
        if (h < 5) asm volatile("cp.async.wait_group 1;" ::: "memory");
        else       asm volatile("cp.async.wait_group 0;" ::: "memory");
        __syncthreads();

        const u32 sq  = sbase + (u32)(h & 1) * HBUF;
        const u32 sk  = sq + 8192u;
        const u32 svh = sq + 16384u;
        const u32 svl = sq + 20480u;

        u32 aq[4][4];
        {
            int row = wid * 16 + (lane & 15);
            #pragma unroll
            for (int s = 0; s < 4; s++) {
                int c = s * 2 + (lane >> 4);
                ldm4(aq[s], sq + (u32)(row * 128 + ((c ^ (row & 7)) << 4)));
            }
        }

        float sc[8][4];
        #pragma unroll
        for (int nt = 0; nt < 8; nt++)
            #pragma unroll
            for (int q = 0; q < 4; q++) sc[nt][q] = 0.f;
        {
            const int pa[6] = {0, 1, 0, 1, 2, 3};
            const int pb[6] = {0, 1, 2, 3, 0, 1};
            #pragma unroll
            for (int vs = 0; vs < 6; vs++) {
                #pragma unroll
                for (int np = 0; np < 4; np++) {
                    u32 bk[4];
                    int brow = np * 16 + (lane & 7) + ((lane >> 4) & 1) * 8;
                    int c    = pb[vs] * 2 + ((lane >> 3) & 1);
                    ldm4(bk, sk + (u32)(brow * 128 + ((c ^ (brow & 7)) << 4)));
                    mma16816(sc[np * 2],     aq[pa[vs]], bk[0], bk[1]);
                    mma16816(sc[np * 2 + 1], aq[pa[vs]], bk[2], bk[3]);
                }
            }
        }

        const float* bmb = g_bm + ((size_t)(wsel * 6 + h) * 49) * 56;
        float m0 = -1e30f, m1 = -1e30f;
        #pragma unroll
        for (int nt = 0; nt < 8; nt++) {
            int c0 = nt * 8 + tcq;
            bool k0 = (c0 < 49), k1 = (c0 + 1 < 49);
            float2 bm0 = make_float2(0.f, 0.f), bm1 = make_float2(0.f, 0.f);
            if (k0 && r0 < 49)     bm0 = *(const float2*)(bmb + r0 * 56 + c0);
            if (k0 && r0 + 8 < 49) bm1 = *(const float2*)(bmb + (r0 + 8) * 56 + c0);
            sc[nt][0] = k0 ? sc[nt][0] + bm0.x : -1e30f;
            sc[nt][1] = k1 ? sc[nt][1] + bm0.y : -1e30f;
            sc[nt][2] = k0 ? sc[nt][2] + bm1.x : -1e30f;
            sc[nt][3] = k1 ? sc[nt][3] + bm1.y : -1e30f;
            m0 = fmaxf(m0, fmaxf(sc[nt][0], sc[nt][1]));
            m1 = fmaxf(m1, fmaxf(sc[nt][2], sc[nt][3]));
        }
        m0 = fmaxf(m0, __shfl_xor_sync(0xFFFFFFFFu, m0, 1));
        m0 = fmaxf(m0, __shfl_xor_sync(0xFFFFFFFFu, m0, 2));
        m1 = fmaxf(m1, __shfl_xor_sync(0xFFFFFFFFu, m1, 1));
        m1 = fmaxf(m1, __shfl_xor_sync(0xFFFFFFFFu, m1, 2));
        float s0 = 0.f, s1 = 0.f;
        #pragma unroll
        for (int nt = 0; nt < 8; nt++) {
            sc[nt][0] = __expf(sc[nt][0] - m0); s0 += sc[nt][0];
            sc[nt][1] = __expf(sc[nt][1] - m0); s0 += sc[nt][1];
            sc[nt][2] = __expf(sc[nt][2] - m1); s1 += sc[nt][2];
            sc[nt][3] = __expf(sc[nt][3] - m1); s1 += sc[nt][3];
        }
        s0 += __shfl_xor_sync(0xFFFFFFFFu, s0, 1);
        s0 += __shfl_xor_sync(0xFFFFFFFFu, s0, 2);
        s1 += __shfl_xor_sync(0xFFFFFFFFu, s1, 1);
        s1 += __shfl_xor_sync(0xFFFFFFFFu, s1, 2);
        float inv0 = 1.f / s0, inv1 = 1.f / s1;

        u32 ph[4][4], pl[4][4];
        #pragma unroll
        for (int s = 0; s < 4; s++) {
            float p00 = sc[2 * s][0] * inv0,     p01 = sc[2 * s][1] * inv0;
            float p10 = sc[2 * s][2] * inv1,     p11 = sc[2 * s][3] * inv1;
            float p20 = sc[2 * s + 1][0] * inv0, p21 = sc[2 * s + 1][1] * inv0;
            float p30 = sc[2 * s + 1][2] * inv1, p31 = sc[2 * s + 1][3] * inv1;
            ph[s][0] = cvt2(p00, p01); pl[s][0] = cvt2(p00 - bflo(ph[s][0]), p01 - bfhi(ph[s][0]));
            ph[s][1] = cvt2(p10, p11); pl[s][1] = cvt2(p10 - bflo(ph[s][1]), p11 - bfhi(ph[s][1]));
            ph[s][2] = cvt2(p20, p21); pl[s][2] = cvt2(p20 - bflo(ph[s][2]), p21 - bfhi(ph[s][2]));
            ph[s][3] = cvt2(p30, p31); pl[s][3] = cvt2(p30 - bflo(ph[s][3]), p31 - bfhi(ph[s][3]));
        }

        float ov[4][4];
        #pragma unroll
        for (int nt = 0; nt < 4; nt++)
            #pragma unroll
            for (int q = 0; q < 4; q++) ov[nt][q] = 0.f;
        #pragma unroll
        for (int term = 0; term < 3; term++) {
            const u32 (*pa)[4] = (term == 2) ? pl : ph;
            const u32 vbase = (term == 1) ? svl : svh;
            #pragma unroll
            for (int s = 0; s < 4; s++) {
                #pragma unroll
                for (int np = 0; np < 2; np++) {
                    u32 bv[4];
                    int brow = np * 16 + (lane & 7) + ((lane >> 4) & 1) * 8;
                    int c    = s * 2 + ((lane >> 3) & 1);
                    ldm4(bv, vbase + (u32)(brow * 128 + ((c ^ (brow & 7)) << 4)));
                    mma16816(ov[np * 2],     pa[s], bv[0], bv[1]);
                    mma16816(ov[np * 2 + 1], pa[s], bv[2], bv[3]);
                }
            }
        }

        #pragma unroll
        for (int nt = 0; nt < 4; nt++) {
            int c0 = nt * 8 + tcq;
            #pragma unroll
            for (int half = 0; half < 2; half++) {
                int iv = r0 + half * 8;
                if (iv < 49) {
                    float x0 = ov[nt][half * 2 + 0];
                    float x1 = ov[nt][half * 2 + 1];
                    u32 hp = cvt2(x0, x1);
                    u32 lp = cvt2(x0 - bflo(hp), x1 - bfhi(hp));
                    __nv_bfloat16* base = g_oe + (tok0 + iv) * 384 + h * 32 + c0;
                    *(u32*)(base)       = hp;
                    *(u32*)(base + 192) = lp;
                }
            }
        }
    }
}

// ---------------- launch ----------------
extern "C" void kernel_launch(void* const* d_in, const int* in_sizes, int n_in,
                              void* d_out, int out_size) {
    const float* x          = (const float*)d_in[0];
    const float* mask       = (const float*)d_in[1];
    const float* qkv_w      = (const float*)d_in[2];
    const float* qkv_b      = (const float*)d_in[3];
    const float* proj_w     = (const float*)d_in[4];
    const float* proj_b     = (const float*)d_in[5];
    const float* bias_table = (const float*)d_in[6];
    const int*   rel_index  = (const int*)d_in[7];
    float* out = (float*)d_out;

    prep_kernel<<<120, 256>>>(qkv_w, proj_w, bias_table, rel_index, mask);
    xconv_kernel<<<(TOKS * 96) / 256, 256>>>(x);

    cudaFuncSetAttribute(gemm_mma, cudaFuncAttributeMaxDynamicSharedMemorySize, GSMEM);

    dim3 gq(6, TOKS / 128);
    gemm_mma<<<gq, 256, GSMEM>>>(qkv_b, nullptr, 0);   // QKV -> split q/k/v layouts
    attn_kernel<<<4096, 128>>>();                       // one CTA per window
    dim3 gp(2, TOKS / 128);
    gemm_mma<<<gp, 256, GSMEM>>>(proj_b, out, 1);       // proj: N=192
}

// round 16
// speedup vs baseline: 1.3936x; 1.0098x over previous
#include <cuda_runtime.h>
#include <cuda_bf16.h>
#include <cstdint>

typedef unsigned long long ull;
typedef uint32_t u32;

#define TOKS 200704          // 4096 windows * 49 tokens (= 1568 * 128)
#define NWIN 64
#define QSCALE 0.17677669529663687f

// ---------------- device scratch (zero-initialized at module load) ----------------
__device__ __nv_bfloat16 g_xe[(size_t)TOKS * 384];           // x split [t][hi|lo]
__device__ __nv_bfloat16 g_oe[(size_t)TOKS * 384];           // attn out split [hi|lo]
__device__ __nv_bfloat16 g_qke[(size_t)4096 * 6 * 49 * 64];  // q scaled, [win][h][i][qh(32)|ql(32)]
__device__ __nv_bfloat16 g_kke[(size_t)4096 * 6 * 49 * 64];  // k, [win][h][j][kh|kl]
__device__ __nv_bfloat16 g_vhe[(size_t)4096 * 6 * 32 * 64];  // v hi, [win][h][c][64j] (j>=49 stays 0)
__device__ __nv_bfloat16 g_vle[(size_t)4096 * 6 * 32 * 64];  // v lo
__device__ __nv_bfloat16 g_wqe[576 * 576];                   // qkv_w packed [n][wh|wl|wh]
__device__ __nv_bfloat16 g_wpe[192 * 576];                   // proj_w packed
__device__ float         g_bm[64 * 6 * 49 * 56];             // bias+mask, j padded to 56

__device__ __forceinline__ u32 smem_u32(const void* p) {
    u32 a;
    asm("{ .reg .u64 t; cvta.to.shared.u64 t, %1; cvt.u32.u64 %0, t; }" : "=r"(a) : "l"(p));
    return a;
}
__device__ __forceinline__ void cp16(u32 saddr, const void* gaddr) {
    asm volatile("cp.async.cg.shared.global [%0], [%1], 16;" :: "r"(saddr), "l"(gaddr));
}
__device__ __forceinline__ void ldm4(u32* r, u32 addr) {
    asm volatile("ldmatrix.sync.aligned.m8n8.x4.shared.b16 {%0,%1,%2,%3}, [%4];"
                 : "=r"(r[0]), "=r"(r[1]), "=r"(r[2]), "=r"(r[3]) : "r"(addr));
}
__device__ __forceinline__ void mma16816(float* d, const u32* a, u32 b0, u32 b1) {
    asm volatile("mma.sync.aligned.m16n8k16.row.col.f32.bf16.bf16.f32 "
                 "{%0,%1,%2,%3}, {%4,%5,%6,%7}, {%8,%9}, {%0,%1,%2,%3};"
                 : "+f"(d[0]), "+f"(d[1]), "+f"(d[2]), "+f"(d[3])
                 : "r"(a[0]), "r"(a[1]), "r"(a[2]), "r"(a[3]), "r"(b0), "r"(b1));
}
// pack two f32 into bf16x2: lo half = first arg
__device__ __forceinline__ u32 cvt2(float lo, float hi) {
    u32 r; asm("cvt.rn.bf16x2.f32 %0, %1, %2;" : "=r"(r) : "f"(hi), "f"(lo)); return r;
}
__device__ __forceinline__ float bflo(u32 p) { return __uint_as_float(p << 16); }
__device__ __forceinline__ float bfhi(u32 p) { return __uint_as_float(p & 0xFFFF0000u); }

// ---------------- prep: split-pack weights + combine bias/mask ----------------
__global__ void prep_kernel(const float* __restrict__ qkv_w, const float* __restrict__ proj_w,
                            const float* __restrict__ bias_table, const int* __restrict__ rel_index,
                            const float* __restrict__ mask) {
    int tid = blockIdx.x * blockDim.x + threadIdx.x;
    int stride = gridDim.x * blockDim.x;
    for (int i = tid; i < 576 * 192; i += stride) {
        int n = i / 192, k = i - n * 192;
        float w = qkv_w[i];
        __nv_bfloat16 h = __float2bfloat16(w);
        __nv_bfloat16 l = __float2bfloat16(w - __bfloat162float(h));
        g_wqe[(size_t)n * 576 + k]       = h;
        g_wqe[(size_t)n * 576 + 192 + k] = l;
        g_wqe[(size_t)n * 576 + 384 + k] = h;
    }
    for (int i = tid; i < 192 * 192; i += stride) {
        int n = i / 192, k = i - n * 192;
        float w = proj_w[i];
        __nv_bfloat16 h = __float2bfloat16(w);
        __nv_bfloat16 l = __float2bfloat16(w - __bfloat162float(h));
        g_wpe[(size_t)n * 576 + k]       = h;
        g_wpe[(size_t)n * 576 + 192 + k] = l;
        g_wpe[(size_t)n * 576 + 384 + k] = h;
    }
    for (int i = tid; i < 64 * 6 * 49 * 56; i += stride) {
        int j = i % 56; int rest = i / 56;
        int ir = rest % 49; rest /= 49;
        int hh = rest % 6; int wm = rest / 6;
        float v = 0.f;
        if (j < 49)
            v = bias_table[rel_index[ir * 49 + j] * 6 + hh] + mask[wm * 2401 + ir * 49 + j];
        g_bm[i] = v;
    }
}

// ---------------- x -> bf16 split [hi|lo] (384 wide) ----------------
__global__ void xconv_kernel(const float* __restrict__ x) {
    size_t idx = (size_t)blockIdx.x * 256 + threadIdx.x;
    size_t t = idx / 96;
    int p = (int)(idx - t * 96);
    float2 v = *(const float2*)(x + t * 192 + 2 * p);
    __nv_bfloat16 h0 = __float2bfloat16(v.x), h1 = __float2bfloat16(v.y);
    __nv_bfloat16 l0 = __float2bfloat16(v.x - __bfloat162float(h0));
    __nv_bfloat16 l1 = __float2bfloat16(v.y - __bfloat162float(h1));
    __nv_bfloat162 hp; hp.x = h0; hp.y = h1;
    __nv_bfloat162 lp; lp.x = l0; lp.y = l1;
    size_t base = t * 384 + 2 * p;
    *(__nv_bfloat162*)(g_xe + base)       = hp;
    *(__nv_bfloat162*)(g_xe + base + 192) = lp;
}

// ---------------- mma.sync GEMM: CTA tile 128x96, 3-stage cp.async ----------------
// A-chunk reuse: chunks 3..5 need the SAME A bytes as chunks 0..2 (ext-K hi
// re-read), and the 3-buffer cycle leaves that data exactly in buf kc%3 —
// so those chunks load B only. First overwrite of a reused A buf (chunk 6 at
// kc=4) is issued after the barrier proving kc=3's compute finished.
#define GSMEM 86016
#define STG_STRIDE 100

__global__ __launch_bounds__(256, 2)
void gemm_mma(const float* __restrict__ bias, float* __restrict__ out_param, int which) {
    extern __shared__ char sm[];
    const __nv_bfloat16* Ae = which ? g_oe : g_xe;
    const __nv_bfloat16* We = which ? g_wpe : g_wqe;
    const int Ncols = which ? 192 : 576;

    const u32 sb = smem_u32(sm);
    const int tid  = threadIdx.x;
    const int lane = tid & 31;
    const int wid  = tid >> 5;
    const int wm   = wid >> 1;        // 0..3
    const int wn   = wid & 1;         // 0..1
    const size_t row0 = (size_t)blockIdx.y * 128;
    const int    n0   = blockIdx.x * 96;

    float acc[2][6][4];
    #pragma unroll
    for (int mt = 0; mt < 2; mt++)
        #pragma unroll
        for (int nt = 0; nt < 6; nt++)
            #pragma unroll
            for (int q = 0; q < 4; q++) acc[mt][nt][q] = 0.f;

    auto load_chunk = [&](int kc, int buf) {
        const bool loadA = !(kc >= 3 && kc < 6);   // A for 3..5 already in buf
        int aoff = (kc < 3) ? kc * 64 : (kc < 6 ? (kc - 3) * 64 : (kc - 6) * 64 + 192);
        const u32 sA = sb + (u32)buf * 16384u;
        const u32 sB = sb + 49152u + (u32)buf * 12288u;
        if (loadA) {
            #pragma unroll
            for (int s = 0; s < 4; s++) {
                int j = tid + s * 256;              // 0..1023: A chunks
                int r = j >> 3, c = j & 7;
                u32 saddr = sA + (u32)r * 128u + (u32)((c ^ (r & 7)) << 4);
                cp16(saddr, Ae + (row0 + r) * 384 + aoff + c * 8);
            }
        }
        #pragma unroll
        for (int s = 0; s < 3; s++) {
            int j = tid + s * 256;                  // 0..767: B chunks
            int r = j >> 3, c = j & 7;
            u32 saddr = sB + (u32)r * 128u + (u32)((c ^ (r & 7)) << 4);
            cp16(saddr, We + (size_t)(n0 + r) * 576 + kc * 64 + c * 8);
        }
        asm volatile("cp.async.commit_group;" ::: "memory");
    };

    load_chunk(0, 0);
    load_chunk(1, 1);

    #pragma unroll 1
    for (int kc = 0; kc < 9; kc++) {
        if (kc < 8) asm volatile("cp.async.wait_group 1;" ::: "memory");
        else        asm volatile("cp.async.wait_group 0;" ::: "memory");
        __syncthreads();
        if (kc + 2 < 9) load_chunk(kc + 2, (kc + 2) % 3);

        const int buf = kc % 3;
        const u32 sA = sb + (u32)buf * 16384u;
        const u32 sB = sb + 49152u + (u32)buf * 12288u;

        #pragma unroll
        for (int ks = 0; ks < 4; ks++) {
            u32 afr[2][4], bfr[3][4];
            #pragma unroll
            for (int mt = 0; mt < 2; mt++) {
                int row = wm * 32 + mt * 16 + (lane & 15);
                int c   = ks * 2 + (lane >> 4);
                ldm4(afr[mt], sA + (u32)row * 128u + (u32)((c ^ (row & 7)) << 4));
            }
            #pragma unroll
            for (int np = 0; np < 3; np++) {
                int brow = wn * 48 + np * 16 + (lane & 7) + ((lane >> 4) & 1) * 8;
                int c    = ks * 2 + ((lane >> 3) & 1);
                ldm4(bfr[np], sB + (u32)brow * 128u + (u32)((c ^ (brow & 7)) << 4));
            }
            #pragma unroll
            for (int mt = 0; mt < 2; mt++)
                #pragma unroll
                for (int nt = 0; nt < 6; nt++)
                    mma16816(acc[mt][nt], afr[mt], bfr[nt >> 1][(nt & 1) * 2], bfr[nt >> 1][(nt & 1) * 2 + 1]);
        }
    }

    const int tr = lane >> 2, tc = (lane & 3) * 2;
    if (which) {
        #pragma unroll
        for (int mt = 0; mt < 2; mt++)
            #pragma unroll
            for (int nt = 0; nt < 6; nt++) {
                int col = n0 + wn * 48 + nt * 8 + tc;
                float b0 = bias[col], b1 = bias[col + 1];
                size_t r_lo = row0 + wm * 32 + mt * 16 + tr;
                float2 v0; v0.x = acc[mt][nt][0] + b0; v0.y = acc[mt][nt][1] + b1;
                float2 v1; v1.x = acc[mt][nt][2] + b0; v1.y = acc[mt][nt][3] + b1;
                *(float2*)(out_param + r_lo * Ncols + col)       = v0;
                *(float2*)(out_param + (r_lo + 8) * Ncols + col) = v1;
            }
    } else {
        __syncthreads();                 // all compute done before reusing buffers as stg
        // ---- stage acc (bias + optional q-scale applied) into smem fp32 tile ----
        const int sec = n0 / 192;        // 0=q, 1=k, 2=v (96-tile never spans sections)
        const int head0 = (n0 % 192) >> 5;   // 0 or 3
        float* stg = (float*)sm;         // [128][STG_STRIDE]
        #pragma unroll
        for (int mt = 0; mt < 2; mt++)
            #pragma unroll
            for (int nt = 0; nt < 6; nt++) {
                int col = wn * 48 + nt * 8 + tc;
                float b0 = bias[n0 + col], b1 = bias[n0 + col + 1];
                #pragma unroll
                for (int half = 0; half < 2; half++) {
                    int r = wm * 32 + mt * 16 + tr + half * 8;
                    float x0 = acc[mt][nt][half * 2 + 0] + b0;
                    float x1 = acc[mt][nt][half * 2 + 1] + b1;
                    if (sec == 0) { x0 *= QSCALE; x1 *= QSCALE; }
                    stg[r * STG_STRIDE + col]     = x0;
                    stg[r * STG_STRIDE + col + 1] = x1;
                }
            }
        __syncthreads();

        if (sec < 2) {
            // q/k: 128 tokens x 24 colgroups of 4; per job write 8B hi + 8B lo
            __nv_bfloat16* gbase = sec == 0 ? g_qke : g_kke;
            for (int idx = tid; idx < 3072; idx += 256) {
                int t = idx / 24, cg = idx - (idx / 24) * 24;
                int hh = cg >> 3, d0 = (cg & 7) * 4;
                u32 r = (u32)(row0 + t);
                u32 win = r / 49u, i = r - win * 49u;
                const float* sp = stg + t * STG_STRIDE + hh * 32 + d0;
                float x0 = sp[0], x1 = sp[1], x2 = sp[2], x3 = sp[3];
                u32 hp0 = cvt2(x0, x1), hp1 = cvt2(x2, x3);
                u32 lp0 = cvt2(x0 - bflo(hp0), x1 - bfhi(hp0));
                u32 lp1 = cvt2(x2 - bflo(hp1), x3 - bfhi(hp1));
                __nv_bfloat16* base = gbase + (((size_t)win * 6 + head0 + hh) * 49 + i) * 64 + d0;
                ((u32*)base)[0] = hp0; ((u32*)base)[1] = hp1;
                ((u32*)(base + 32))[0] = lp0; ((u32*)(base + 32))[1] = lp1;
            }
        } else {
            // v: token-fastest lane order -> contiguous 2B stores per window segment
            for (int idx = tid; idx < 12288; idx += 256) {
                int d = idx >> 7, t = idx & 127;
                int hh = d >> 5, dd = d & 31;
                u32 r = (u32)(row0 + t);
                u32 win = r / 49u, i = r - win * 49u;
                float x = stg[t * STG_STRIDE + d];
                __nv_bfloat16 h0 = __float2bfloat16(x);
                size_t vb = (((size_t)win * 6 + head0 + hh) * 32 + dd) * 64 + i;
                g_vhe[vb] = h0;
                g_vle[vb] = __float2bfloat16(x - __bfloat162float(h0));
            }
        }
    }
}

// ---------------- attention: tensor-core QK^T and P@V, softmax in registers ----
// One CTA per window, 128 threads, 6 heads, cp.async double-buffered staging.
#define HBUF 24576

__global__ __launch_bounds__(128, 4)
void attn_kernel() {
    __shared__ __align__(16) char smbuf[2 * HBUF];
    const u32 sbase = smem_u32(smbuf);

    const int tid  = threadIdx.x;
    const int lane = tid & 31;
    const int wid  = tid >> 5;
    const int win  = blockIdx.x;
    const int wsel = win & (NWIN - 1);
    const size_t tok0 = (size_t)win * 49;

    // zero k pad rows (49..63) in BOTH buffers once
    {
        float4 z = make_float4(0.f, 0.f, 0.f, 0.f);
        #pragma unroll
        for (int b = 0; b < 2; b++)
            for (int idx = tid; idx < 15 * 8; idx += 128) {
                int r = 49 + (idx >> 3), ch = idx & 7;
                *(float4*)(smbuf + b * HBUF + 8192 + r * 128 + ((ch ^ (r & 7)) << 4)) = z;
            }
    }

    auto stage = [&](int h, int buf) {
        const u32 sq = sbase + (u32)buf * HBUF;
        const size_t qb = ((size_t)win * 6 + h) * 49 * 64;
        for (int idx = tid; idx < 392; idx += 128) {
            int r = idx >> 3, ch = idx & 7;
            u32 off = (u32)(r * 128 + ((ch ^ (r & 7)) << 4));
            cp16(sq + off,         g_qke + qb + r * 64 + ch * 8);
            cp16(sq + 8192u + off, g_kke + qb + r * 64 + ch * 8);
        }
        const size_t vb = ((size_t)win * 6 + h) * 32 * 64;
        for (int idx = tid; idx < 256; idx += 128) {
            int c = idx >> 3, ch = idx & 7;
            u32 off = (u32)(c * 128 + ((ch ^ (c & 7)) << 4));
            cp16(sq + 16384u + off, g_vhe + vb + c * 64 + ch * 8);
            cp16(sq + 20480u + off, g_vle + vb + c * 64 + ch * 8);
        }
        asm volatile("cp.async.commit_group;" ::: "memory");
    };

    const int tcq = 2 * (lane & 3);
    const int r0  = wid * 16 + (lane >> 2);

    stage(0, 0);

    #pragma unroll 1
    for (int h = 0; h < 6; h++) {
        __syncthreads();
        if (h < 5) stage(h + 1, (h + 1) & 1);
        if (h < 5) asm volatile("cp.async.wait_group 1;" ::: "memory");
        else       asm volatile("cp.async.wait_group 0;" ::: "memory");
        __syncthreads();

        const u32 sq  = sbase + (u32)(h & 1) * HBUF;
        const u32 sk  = sq + 8192u;
        const u32 svh = sq + 16384u;
        const u32 svl = sq + 20480u;

        u32 aq[4][4];
        {
            int row = wid * 16 + (lane & 15);
            #pragma unroll
            for (int s = 0; s < 4; s++) {
                int c = s * 2 + (lane >> 4);
                ldm4(aq[s], sq + (u32)(row * 128 + ((c ^ (row & 7)) << 4)));
            }
        }

        float sc[8][4];
        #pragma unroll
        for (int nt = 0; nt < 8; nt++)
            #pragma unroll
            for (int q = 0; q < 4; q++) sc[nt][q] = 0.f;
        {
            const int pa[6] = {0, 1, 0, 1, 2, 3};
            const int pb[6] = {0, 1, 2, 3, 0, 1};
            #pragma unroll
            for (int vs = 0; vs < 6; vs++) {
                #pragma unroll
                for (int np = 0; np < 4; np++) {
                    u32 bk[4];
                    int brow = np * 16 + (lane & 7) + ((lane >> 4) & 1) * 8;
                    int c    = pb[vs] * 2 + ((lane >> 3) & 1);
                    ldm4(bk, sk + (u32)(brow * 128 + ((c ^ (brow & 7)) << 4)));
                    mma16816(sc[np * 2],     aq[pa[vs]], bk[0], bk[1]);
                    mma16816(sc[np * 2 + 1], aq[pa[vs]], bk[2], bk[3]);
                }
            }
        }

        const float* bmb = g_bm + ((size_t)(wsel * 6 + h) * 49) * 56;
        float m0 = -1e30f, m1 = -1e30f;
        #pragma unroll
        for (int nt = 0; nt < 8; nt++) {
            int c0 = nt * 8 + tcq;
            bool k0 = (c0 < 49), k1 = (c0 + 1 < 49);
            float2 bm0 = make_float2(0.f, 0.f), bm1 = make_float2(0.f, 0.f);
            if (k0 && r0 < 49)     bm0 = *(const float2*)(bmb + r0 * 56 + c0);
            if (k0 && r0 + 8 < 49) bm1 = *(const float2*)(bmb + (r0 + 8) * 56 + c0);
            sc[nt][0] = k0 ? sc[nt][0] + bm0.x : -1e30f;
            sc[nt][1] = k1 ? sc[nt][1] + bm0.y : -1e30f;
            sc[nt][2] = k0 ? sc[nt][2] + bm1.x : -1e30f;
            sc[nt][3] = k1 ? sc[nt][3] + bm1.y : -1e30f;
            m0 = fmaxf(m0, fmaxf(sc[nt][0], sc[nt][1]));
            m1 = fmaxf(m1, fmaxf(sc[nt][2], sc[nt][3]));
        }
        m0 = fmaxf(m0, __shfl_xor_sync(0xFFFFFFFFu, m0, 1));
        m0 = fmaxf(m0, __shfl_xor_sync(0xFFFFFFFFu, m0, 2));
        m1 = fmaxf(m1, __shfl_xor_sync(0xFFFFFFFFu, m1, 1));
        m1 = fmaxf(m1, __shfl_xor_sync(0xFFFFFFFFu, m1, 2));
        float s0 = 0.f, s1 = 0.f;
        #pragma unroll
        for (int nt = 0; nt < 8; nt++) {
            sc[nt][0] = __expf(sc[nt][0] - m0); s0 += sc[nt][0];
            sc[nt][1] = __expf(sc[nt][1] - m0); s0 += sc[nt][1];
            sc[nt][2] = __expf(sc[nt][2] - m1); s1 += sc[nt][2];
            sc[nt][3] = __expf(sc[nt][3] - m1); s1 += sc[nt][3];
        }
        s0 += __shfl_xor_sync(0xFFFFFFFFu, s0, 1);
        s0 += __shfl_xor_sync(0xFFFFFFFFu, s0, 2);
        s1 += __shfl_xor_sync(0xFFFFFFFFu, s1, 1);
        s1 += __shfl_xor_sync(0xFFFFFFFFu, s1, 2);
        float inv0 = 1.f / s0, inv1 = 1.f / s1;

        u32 ph[4][4], pl[4][4];
        #pragma unroll
        for (int s = 0; s < 4; s++) {
            float p00 = sc[2 * s][0] * inv0,     p01 = sc[2 * s][1] * inv0;
            float p10 = sc[2 * s][2] * inv1,     p11 = sc[2 * s][3] * inv1;
            float p20 = sc[2 * s + 1][0] * inv0, p21 = sc[2 * s + 1][1] * inv0;
            float p30 = sc[2 * s + 1][2] * inv1, p31 = sc[2 * s + 1][3] * inv1;
            ph[s][0] = cvt2(p00, p01); pl[s][0] = cvt2(p00 - bflo(ph[s][0]), p01 - bfhi(ph[s][0]));
            ph[s][1] = cvt2(p10, p11); pl[s][1] = cvt2(p10 - bflo(ph[s][1]), p11 - bfhi(ph[s][1]));
            ph[s][2] = cvt2(p20, p21); pl[s][2] = cvt2(p20 - bflo(ph[s][2]), p21 - bfhi(ph[s][2]));
            ph[s][3] = cvt2(p30, p31); pl[s][3] = cvt2(p30 - bflo(ph[s][3]), p31 - bfhi(ph[s][3]));
        }

        float ov[4][4];
        #pragma unroll
        for (int nt = 0; nt < 4; nt++)
            #pragma unroll
            for (int q = 0; q < 4; q++) ov[nt][q] = 0.f;
        #pragma unroll
        for (int term = 0; term < 3; term++) {
            const u32 (*pa)[4] = (term == 2) ? pl : ph;
            const u32 vbase = (term == 1) ? svl : svh;
            #pragma unroll
            for (int s = 0; s < 4; s++) {
                #pragma unroll
                for (int np = 0; np < 2; np++) {
                    u32 bv[4];
                    int brow = np * 16 + (lane & 7) + ((lane >> 4) & 1) * 8;
                    int c    = s * 2 + ((lane >> 3) & 1);
                    ldm4(bv, vbase + (u32)(brow * 128 + ((c ^ (brow & 7)) << 4)));
                    mma16816(ov[np * 2],     pa[s], bv[0], bv[1]);
                    mma16816(ov[np * 2 + 1], pa[s], bv[2], bv[3]);
                }
            }
        }

        #pragma unroll
        for (int nt = 0; nt < 4; nt++) {
            int c0 = nt * 8 + tcq;
            #pragma unroll
            for (int half = 0; half < 2; half++) {
                int iv = r0 + half * 8;
                if (iv < 49) {
                    float x0 = ov[nt][half * 2 + 0];
                    float x1 = ov[nt][half * 2 + 1];
                    u32 hp = cvt2(x0, x1);
                    u32 lp = cvt2(x0 - bflo(hp), x1 - bfhi(hp));
                    __nv_bfloat16* base = g_oe + (tok0 + iv) * 384 + h * 32 + c0;
                    *(u32*)(base)       = hp;
                    *(u32*)(base + 192) = lp;
                }
            }
        }
    }
}

// ---------------- launch ----------------
extern "C" void kernel_launch(void* const* d_in, const int* in_sizes, int n_in,
                              void* d_out, int out_size) {
    const float* x          = (const float*)d_in[0];
    const float* mask       = (const float*)d_in[1];
    const float* qkv_w      = (const float*)d_in[2];
    const float* qkv_b      = (const float*)d_in[3];
    const float* proj_w     = (const float*)d_in[4];
    const float* proj_b     = (const float*)d_in[5];
    const float* bias_table = (const float*)d_in[6];
    const int*   rel_index  = (const int*)d_in[7];
    float* out = (float*)d_out;

    prep_kernel<<<120, 256>>>(qkv_w, proj_w, bias_table, rel_index, mask);
    xconv_kernel<<<(TOKS * 96) / 256, 256>>>(x);

    cudaFuncSetAttribute(gemm_mma, cudaFuncAttributeMaxDynamicSharedMemorySize, GSMEM);

    dim3 gq(6, TOKS / 128);
    gemm_mma<<<gq, 256, GSMEM>>>(qkv_b, nullptr, 0);   // QKV -> split q/k/v layouts
    attn_kernel<<<4096, 128>>>();                       // one CTA per window
    dim3 gp(2, TOKS / 128);
    gemm_mma<<<gp, 256, GSMEM>>>(proj_b, out, 1);       // proj: N=192
}

// round 17
// speedup vs baseline: 1.8083x; 1.2975x over previous
#include <cuda_runtime.h>
#include <cuda_fp16.h>
#include <cstdint>

typedef unsigned long long ull;
typedef uint32_t u32;
typedef __half HF;

#define TOKS 200704          // 4096 windows * 49 tokens (= 1568 * 128)
#define NWIN 64
#define QSCALE 0.17677669529663687f

// ---------------- device scratch (zero-initialized at module load) ----------------
__device__ HF    g_xe[(size_t)TOKS * 384];           // x split [t][xh(192)|xl(192)] fp16
__device__ HF    g_oe[(size_t)TOKS * 384];           // attn out split [oh|ol] fp16
__device__ HF    g_qke[(size_t)4096 * 6 * 49 * 64];  // q scaled, [win][h][i][qh(32)|ql(32)]
__device__ HF    g_kke[(size_t)4096 * 6 * 49 * 64];  // k, [win][h][j][kh(32)|zeros(32)]
__device__ HF    g_vhe[(size_t)4096 * 6 * 32 * 64];  // v fp16, [win][h][c][64j] (j>=49 zero)
__device__ HF    g_wqe[576 * 192];                   // qkv_w fp16
__device__ HF    g_wpe[192 * 192];                   // proj_w fp16
__device__ float g_bm[64 * 6 * 49 * 56];             // bias+mask, j padded to 56

__device__ __forceinline__ u32 smem_u32(const void* p) {
    u32 a;
    asm("{ .reg .u64 t; cvta.to.shared.u64 t, %1; cvt.u32.u64 %0, t; }" : "=r"(a) : "l"(p));
    return a;
}
__device__ __forceinline__ void cp16(u32 saddr, const void* gaddr) {
    asm volatile("cp.async.cg.shared.global [%0], [%1], 16;" :: "r"(saddr), "l"(gaddr));
}
__device__ __forceinline__ void ldm4(u32* r, u32 addr) {
    asm volatile("ldmatrix.sync.aligned.m8n8.x4.shared.b16 {%0,%1,%2,%3}, [%4];"
                 : "=r"(r[0]), "=r"(r[1]), "=r"(r[2]), "=r"(r[3]) : "r"(addr));
}
__device__ __forceinline__ void mma16816(float* d, const u32* a, u32 b0, u32 b1) {
    asm volatile("mma.sync.aligned.m16n8k16.row.col.f32.f16.f16.f32 "
                 "{%0,%1,%2,%3}, {%4,%5,%6,%7}, {%8,%9}, {%0,%1,%2,%3};"
                 : "+f"(d[0]), "+f"(d[1]), "+f"(d[2]), "+f"(d[3])
                 : "r"(a[0]), "r"(a[1]), "r"(a[2]), "r"(a[3]), "r"(b0), "r"(b1));
}
// pack two f32 into f16x2: lo half = first arg
__device__ __forceinline__ u32 cvt2(float lo, float hi) {
    u32 r; asm("cvt.rn.f16x2.f32 %0, %1, %2;" : "=r"(r) : "f"(hi), "f"(lo)); return r;
}
__device__ __forceinline__ float h2lo(u32 p) { __half2 h = *reinterpret_cast<__half2*>(&p); return __low2float(h); }
__device__ __forceinline__ float h2hi(u32 p) { __half2 h = *reinterpret_cast<__half2*>(&p); return __high2float(h); }

// ---------------- prep: fp16 weights + combine bias/mask ----------------
__global__ void prep_kernel(const float* __restrict__ qkv_w, const float* __restrict__ proj_w,
                            const float* __restrict__ bias_table, const int* __restrict__ rel_index,
                            const float* __restrict__ mask) {
    int tid = blockIdx.x * blockDim.x + threadIdx.x;
    int stride = gridDim.x * blockDim.x;
    for (int i = tid; i < 576 * 192; i += stride) g_wqe[i] = __float2half_rn(qkv_w[i]);
    for (int i = tid; i < 192 * 192; i += stride) g_wpe[i] = __float2half_rn(proj_w[i]);
    for (int i = tid; i < 64 * 6 * 49 * 56; i += stride) {
        int j = i % 56; int rest = i / 56;
        int ir = rest % 49; rest /= 49;
        int hh = rest % 6; int wm = rest / 6;
        float v = 0.f;
        if (j < 49)
            v = bias_table[rel_index[ir * 49 + j] * 6 + hh] + mask[wm * 2401 + ir * 49 + j];
        g_bm[i] = v;
    }
}

// ---------------- x -> fp16 2-term split [xh|xl] (384 wide) ----------------
__global__ void xconv_kernel(const float* __restrict__ x) {
    size_t idx = (size_t)blockIdx.x * 256 + threadIdx.x;
    size_t t = idx / 96;
    int p = (int)(idx - t * 96);
    float2 v = *(const float2*)(x + t * 192 + 2 * p);
    HF h0 = __float2half_rn(v.x), h1 = __float2half_rn(v.y);
    HF l0 = __float2half_rn(v.x - __half2float(h0));
    HF l1 = __float2half_rn(v.y - __half2float(h1));
    __half2 hp; hp.x = h0; hp.y = h1;
    __half2 lp; lp.x = l0; lp.y = l1;
    size_t base = t * 384 + 2 * p;
    *(__half2*)(g_xe + base)       = hp;
    *(__half2*)(g_xe + base + 192) = lp;
}

// ---------------- fp16 mma GEMM: CTA 128x96, ext-K=384 (6 chunks) ----------------
// A = [xh|xl]; W single fp16 (192 wide). Chunks 3..5 reuse B of chunks 0..2
// (already in buf kc%3): B loads happen only for kc<3.
#define GSMEM 86016
#define STG_STRIDE 100

__global__ __launch_bounds__(256, 2)
void gemm_mma(const float* __restrict__ bias, float* __restrict__ out_param, int which) {
    extern __shared__ char sm[];
    const HF* Ae = which ? g_oe : g_xe;
    const HF* We = which ? g_wpe : g_wqe;
    const int Ncols = which ? 192 : 576;

    const u32 sb = smem_u32(sm);
    const int tid  = threadIdx.x;
    const int lane = tid & 31;
    const int wid  = tid >> 5;
    const int wm   = wid >> 1;        // 0..3
    const int wn   = wid & 1;         // 0..1
    const size_t row0 = (size_t)blockIdx.y * 128;
    const int    n0   = blockIdx.x * 96;

    float acc[2][6][4];
    #pragma unroll
    for (int mt = 0; mt < 2; mt++)
        #pragma unroll
        for (int nt = 0; nt < 6; nt++)
            #pragma unroll
            for (int q = 0; q < 4; q++) acc[mt][nt][q] = 0.f;

    auto load_chunk = [&](int kc, int buf) {
        int aoff = (kc < 3) ? kc * 64 : 192 + (kc - 3) * 64;
        const u32 sA = sb + (u32)buf * 16384u;
        const u32 sB = sb + 49152u + (u32)buf * 12288u;
        #pragma unroll
        for (int s = 0; s < 4; s++) {
            int j = tid + s * 256;              // 0..1023: A
            int r = j >> 3, c = j & 7;
            u32 saddr = sA + (u32)r * 128u + (u32)((c ^ (r & 7)) << 4);
            cp16(saddr, Ae + (row0 + r) * 384 + aoff + c * 8);
        }
        if (kc < 3) {
            #pragma unroll
            for (int s = 0; s < 3; s++) {
                int j = tid + s * 256;          // 0..767: B
                int r = j >> 3, c = j & 7;
                u32 saddr = sB + (u32)r * 128u + (u32)((c ^ (r & 7)) << 4);
                cp16(saddr, We + (size_t)(n0 + r) * 192 + kc * 64 + c * 8);
            }
        }
        asm volatile("cp.async.commit_group;" ::: "memory");
    };

    load_chunk(0, 0);
    load_chunk(1, 1);

    #pragma unroll 1
    for (int kc = 0; kc < 6; kc++) {
        if (kc < 5) asm volatile("cp.async.wait_group 1;" ::: "memory");
        else        asm volatile("cp.async.wait_group 0;" ::: "memory");
        __syncthreads();
        if (kc + 2 < 6) load_chunk(kc + 2, (kc + 2) % 3);

        const int buf = kc % 3;
        const u32 sA = sb + (u32)buf * 16384u;
        const u32 sB = sb + 49152u + (u32)buf * 12288u;

        #pragma unroll
        for (int ks = 0; ks < 4; ks++) {
            u32 afr[2][4], bfr[3][4];
            #pragma unroll
            for (int mt = 0; mt < 2; mt++) {
                int row = wm * 32 + mt * 16 + (lane & 15);
                int c   = ks * 2 + (lane >> 4);
                ldm4(afr[mt], sA + (u32)row * 128u + (u32)((c ^ (row & 7)) << 4));
            }
            #pragma unroll
            for (int np = 0; np < 3; np++) {
                int brow = wn * 48 + np * 16 + (lane & 7) + ((lane >> 4) & 1) * 8;
                int c    = ks * 2 + ((lane >> 3) & 1);
                ldm4(bfr[np], sB + (u32)brow * 128u + (u32)((c ^ (brow & 7)) << 4));
            }
            #pragma unroll
            for (int mt = 0; mt < 2; mt++)
                #pragma unroll
                for (int nt = 0; nt < 6; nt++)
                    mma16816(acc[mt][nt], afr[mt], bfr[nt >> 1][(nt & 1) * 2], bfr[nt >> 1][(nt & 1) * 2 + 1]);
        }
    }

    const int tr = lane >> 2, tc = (lane & 3) * 2;
    if (which) {
        #pragma unroll
        for (int mt = 0; mt < 2; mt++)
            #pragma unroll
            for (int nt = 0; nt < 6; nt++) {
                int col = n0 + wn * 48 + nt * 8 + tc;
                float b0 = bias[col], b1 = bias[col + 1];
                size_t r_lo = row0 + wm * 32 + mt * 16 + tr;
                float2 v0; v0.x = acc[mt][nt][0] + b0; v0.y = acc[mt][nt][1] + b1;
                float2 v1; v1.x = acc[mt][nt][2] + b0; v1.y = acc[mt][nt][3] + b1;
                *(float2*)(out_param + r_lo * Ncols + col)       = v0;
                *(float2*)(out_param + (r_lo + 8) * Ncols + col) = v1;
            }
    } else {
        __syncthreads();                 // compute done before reusing buffers as stg
        const int sec = n0 / 192;        // 0=q, 1=k, 2=v
        const int head0 = (n0 % 192) >> 5;
        float* stg = (float*)sm;         // [128][STG_STRIDE]
        #pragma unroll
        for (int mt = 0; mt < 2; mt++)
            #pragma unroll
            for (int nt = 0; nt < 6; nt++) {
                int col = wn * 48 + nt * 8 + tc;
                float b0 = bias[n0 + col], b1 = bias[n0 + col + 1];
                #pragma unroll
                for (int half = 0; half < 2; half++) {
                    int r = wm * 32 + mt * 16 + tr + half * 8;
                    float x0 = acc[mt][nt][half * 2 + 0] + b0;
                    float x1 = acc[mt][nt][half * 2 + 1] + b1;
                    if (sec == 0) { x0 *= QSCALE; x1 *= QSCALE; }
                    stg[r * STG_STRIDE + col]     = x0;
                    stg[r * STG_STRIDE + col + 1] = x1;
                }
            }
        __syncthreads();

        if (sec < 2) {
            // q: write qh @d0 + ql @d0+32.  k: write kh @d0 only (cols 32..63 stay 0).
            HF* gbase = sec == 0 ? g_qke : g_kke;
            for (int idx = tid; idx < 3072; idx += 256) {
                int t = idx / 24, cg = idx - (idx / 24) * 24;
                int hh = cg >> 3, d0 = (cg & 7) * 4;
                u32 r = (u32)(row0 + t);
                u32 win = r / 49u, i = r - win * 49u;
                const float* sp = stg + t * STG_STRIDE + hh * 32 + d0;
                float x0 = sp[0], x1 = sp[1], x2 = sp[2], x3 = sp[3];
                u32 hp0 = cvt2(x0, x1), hp1 = cvt2(x2, x3);
                HF* base = gbase + (((size_t)win * 6 + head0 + hh) * 49 + i) * 64 + d0;
                ((u32*)base)[0] = hp0; ((u32*)base)[1] = hp1;
                if (sec == 0) {
                    u32 lp0 = cvt2(x0 - h2lo(hp0), x1 - h2hi(hp0));
                    u32 lp1 = cvt2(x2 - h2lo(hp1), x3 - h2hi(hp1));
                    ((u32*)(base + 32))[0] = lp0; ((u32*)(base + 32))[1] = lp1;
                }
            }
        } else {
            // v: token-fastest lane order -> contiguous 2B stores
            for (int idx = tid; idx < 12288; idx += 256) {
                int d = idx >> 7, t = idx & 127;
                int hh = d >> 5, dd = d & 31;
                u32 r = (u32)(row0 + t);
                u32 win = r / 49u, i = r - win * 49u;
                float x = stg[t * STG_STRIDE + d];
                size_t vb = (((size_t)win * 6 + head0 + hh) * 32 + dd) * 64 + i;
                g_vhe[vb] = __float2half_rn(x);
            }
        }
    }
}

// ---------------- attention: fp16 tensor-core, softmax in registers ----------------
// One CTA per window, 128 threads, 6 heads, double-buffered cp.async staging.
// Per buffer: q[64][64] @0 (8K), k[64][64] @8K (cols 32..63 zero), v[32][64] @16K.
#define HBUF 20480

__global__ __launch_bounds__(128, 4)
void attn_kernel() {
    __shared__ __align__(16) char smbuf[2 * HBUF];
    const u32 sbase = smem_u32(smbuf);

    const int tid  = threadIdx.x;
    const int lane = tid & 31;
    const int wid  = tid >> 5;
    const int win  = blockIdx.x;
    const int wsel = win & (NWIN - 1);
    const size_t tok0 = (size_t)win * 49;

    // zero k pad rows (49..63) in BOTH buffers once
    {
        float4 z = make_float4(0.f, 0.f, 0.f, 0.f);
        #pragma unroll
        for (int b = 0; b < 2; b++)
            for (int idx = tid; idx < 15 * 8; idx += 128) {
                int r = 49 + (idx >> 3), ch = idx & 7;
                *(float4*)(smbuf + b * HBUF + 8192 + r * 128 + ((ch ^ (r & 7)) << 4)) = z;
            }
    }

    auto stage = [&](int h, int buf) {
        const u32 sq = sbase + (u32)buf * HBUF;
        const size_t qb = ((size_t)win * 6 + h) * 49 * 64;
        for (int idx = tid; idx < 392; idx += 128) {
            int r = idx >> 3, ch = idx & 7;
            u32 off = (u32)(r * 128 + ((ch ^ (r & 7)) << 4));
            cp16(sq + off,         g_qke + qb + r * 64 + ch * 8);
            cp16(sq + 8192u + off, g_kke + qb + r * 64 + ch * 8);
        }
        const size_t vb = ((size_t)win * 6 + h) * 32 * 64;
        for (int idx = tid; idx < 256; idx += 128) {
            int c = idx >> 3, ch = idx & 7;
            u32 off = (u32)(c * 128 + ((ch ^ (c & 7)) << 4));
            cp16(sq + 16384u + off, g_vhe + vb + c * 64 + ch * 8);
        }
        asm volatile("cp.async.commit_group;" ::: "memory");
    };

    const int tcq = 2 * (lane & 3);
    const int r0  = wid * 16 + (lane >> 2);

    stage(0, 0);

    #pragma unroll 1
    for (int h = 0; h < 6; h++) {
        __syncthreads();
        if (h < 5) stage(h + 1, (h + 1) & 1);
        if (h < 5) asm volatile("cp.async.wait_group 1;" ::: "memory");
        else       asm volatile("cp.async.wait_group 0;" ::: "memory");
        __syncthreads();

        const u32 sq  = sbase + (u32)(h & 1) * HBUF;
        const u32 sk  = sq + 8192u;
        const u32 svh = sq + 16384u;

        // ---- A fragments for q (steps 0,1 = qh; 2,3 = ql) ----
        u32 aq[4][4];
        {
            int row = wid * 16 + (lane & 15);
            #pragma unroll
            for (int s = 0; s < 4; s++) {
                int c = s * 2 + (lane >> 4);
                ldm4(aq[s], sq + (u32)(row * 128 + ((c ^ (row & 7)) << 4)));
            }
        }

        // ---- QK^T: (qh+ql)·kh via 4 split passes ----
        float sc[8][4];
        #pragma unroll
        for (int nt = 0; nt < 8; nt++)
            #pragma unroll
            for (int q = 0; q < 4; q++) sc[nt][q] = 0.f;
        {
            const int pb[4] = {0, 1, 0, 1};   // kh steps reused for ql passes
            #pragma unroll
            for (int vs = 0; vs < 4; vs++) {
                #pragma unroll
                for (int np = 0; np < 4; np++) {
                    u32 bk[4];
                    int brow = np * 16 + (lane & 7) + ((lane >> 4) & 1) * 8;
                    int c    = pb[vs] * 2 + ((lane >> 3) & 1);
                    ldm4(bk, sk + (u32)(brow * 128 + ((c ^ (brow & 7)) << 4)));
                    mma16816(sc[np * 2],     aq[vs], bk[0], bk[1]);
                    mma16816(sc[np * 2 + 1], aq[vs], bk[2], bk[3]);
                }
            }
        }

        const float* bmb = g_bm + ((size_t)(wsel * 6 + h) * 49) * 56;
        float m0 = -1e30f, m1 = -1e30f;
        #pragma unroll
        for (int nt = 0; nt < 8; nt++) {
            int c0 = nt * 8 + tcq;
            bool k0 = (c0 < 49), k1 = (c0 + 1 < 49);
            float2 bm0 = make_float2(0.f, 0.f), bm1 = make_float2(0.f, 0.f);
            if (k0 && r0 < 49)     bm0 = *(const float2*)(bmb + r0 * 56 + c0);
            if (k0 && r0 + 8 < 49) bm1 = *(const float2*)(bmb + (r0 + 8) * 56 + c0);
            sc[nt][0] = k0 ? sc[nt][0] + bm0.x : -1e30f;
            sc[nt][1] = k1 ? sc[nt][1] + bm0.y : -1e30f;
            sc[nt][2] = k0 ? sc[nt][2] + bm1.x : -1e30f;
            sc[nt][3] = k1 ? sc[nt][3] + bm1.y : -1e30f;
            m0 = fmaxf(m0, fmaxf(sc[nt][0], sc[nt][1]));
            m1 = fmaxf(m1, fmaxf(sc[nt][2], sc[nt][3]));
        }
        m0 = fmaxf(m0, __shfl_xor_sync(0xFFFFFFFFu, m0, 1));
        m0 = fmaxf(m0, __shfl_xor_sync(0xFFFFFFFFu, m0, 2));
        m1 = fmaxf(m1, __shfl_xor_sync(0xFFFFFFFFu, m1, 1));
        m1 = fmaxf(m1, __shfl_xor_sync(0xFFFFFFFFu, m1, 2));
        float s0 = 0.f, s1 = 0.f;
        #pragma unroll
        for (int nt = 0; nt < 8; nt++) {
            sc[nt][0] = __expf(sc[nt][0] - m0); s0 += sc[nt][0];
            sc[nt][1] = __expf(sc[nt][1] - m0); s0 += sc[nt][1];
            sc[nt][2] = __expf(sc[nt][2] - m1); s1 += sc[nt][2];
            sc[nt][3] = __expf(sc[nt][3] - m1); s1 += sc[nt][3];
        }
        s0 += __shfl_xor_sync(0xFFFFFFFFu, s0, 1);
        s0 += __shfl_xor_sync(0xFFFFFFFFu, s0, 2);
        s1 += __shfl_xor_sync(0xFFFFFFFFu, s1, 1);
        s1 += __shfl_xor_sync(0xFFFFFFFFu, s1, 2);
        float inv0 = 1.f / s0, inv1 = 1.f / s1;

        // ---- probs -> fp16 2-term A-fragments ----
        u32 ph[4][4], pl[4][4];
        #pragma unroll
        for (int s = 0; s < 4; s++) {
            float p00 = sc[2 * s][0] * inv0,     p01 = sc[2 * s][1] * inv0;
            float p10 = sc[2 * s][2] * inv1,     p11 = sc[2 * s][3] * inv1;
            float p20 = sc[2 * s + 1][0] * inv0, p21 = sc[2 * s + 1][1] * inv0;
            float p30 = sc[2 * s + 1][2] * inv1, p31 = sc[2 * s + 1][3] * inv1;
            ph[s][0] = cvt2(p00, p01); pl[s][0] = cvt2(p00 - h2lo(ph[s][0]), p01 - h2hi(ph[s][0]));
            ph[s][1] = cvt2(p10, p11); pl[s][1] = cvt2(p10 - h2lo(ph[s][1]), p11 - h2hi(ph[s][1]));
            ph[s][2] = cvt2(p20, p21); pl[s][2] = cvt2(p20 - h2lo(ph[s][2]), p21 - h2hi(ph[s][2]));
            ph[s][3] = cvt2(p30, p31); pl[s][3] = cvt2(p30 - h2lo(ph[s][3]), p31 - h2hi(ph[s][3]));
        }

        // ---- P @ V: terms (Ph,V), (Pl,V) ----
        float ov[4][4];
        #pragma unroll
        for (int nt = 0; nt < 4; nt++)
            #pragma unroll
            for (int q = 0; q < 4; q++) ov[nt][q] = 0.f;
        #pragma unroll
        for (int term = 0; term < 2; term++) {
            const u32 (*pa)[4] = term ? pl : ph;
            #pragma unroll
            for (int s = 0; s < 4; s++) {
                #pragma unroll
                for (int np = 0; np < 2; np++) {
                    u32 bv[4];
                    int brow = np * 16 + (lane & 7) + ((lane >> 4) & 1) * 8;
                    int c    = s * 2 + ((lane >> 3) & 1);
                    ldm4(bv, svh + (u32)(brow * 128 + ((c ^ (brow & 7)) << 4)));
                    mma16816(ov[np * 2],     pa[s], bv[0], bv[1]);
                    mma16816(ov[np * 2 + 1], pa[s], bv[2], bv[3]);
                }
            }
        }

        // ---- store o (fp16 2-term split) to g_oe ----
        #pragma unroll
        for (int nt = 0; nt < 4; nt++) {
            int c0 = nt * 8 + tcq;
            #pragma unroll
            for (int half = 0; half < 2; half++) {
                int iv = r0 + half * 8;
                if (iv < 49) {
                    float x0 = ov[nt][half * 2 + 0];
                    float x1 = ov[nt][half * 2 + 1];
                    u32 hp = cvt2(x0, x1);
                    u32 lp = cvt2(x0 - h2lo(hp), x1 - h2hi(hp));
                    HF* base = g_oe + (tok0 + iv) * 384 + h * 32 + c0;
                    *(u32*)(base)       = hp;
                    *(u32*)(base + 192) = lp;
                }
            }
        }
    }
}

// ---------------- launch ----------------
extern "C" void kernel_launch(void* const* d_in, const int* in_sizes, int n_in,
                              void* d_out, int out_size) {
    const float* x          = (const float*)d_in[0];
    const float* mask       = (const float*)d_in[1];
    const float* qkv_w      = (const float*)d_in[2];
    const float* qkv_b      = (const float*)d_in[3];
    const float* proj_w     = (const float*)d_in[4];
    const float* proj_b     = (const float*)d_in[5];
    const float* bias_table = (const float*)d_in[6];
    const int*   rel_index  = (const int*)d_in[7];
    float* out = (float*)d_out;

    prep_kernel<<<120, 256>>>(qkv_w, proj_w, bias_table, rel_index, mask);
    xconv_kernel<<<(TOKS * 96) / 256, 256>>>(x);

    cudaFuncSetAttribute(gemm_mma, cudaFuncAttributeMaxDynamicSharedMemorySize, GSMEM);

    dim3 gq(6, TOKS / 128);
    gemm_mma<<<gq, 256, GSMEM>>>(qkv_b, nullptr, 0);   // QKV -> fp16 q/k/v layouts
    attn_kernel<<<4096, 128>>>();                       // one CTA per window
    dim3 gp(2, TOKS / 128);
    gemm_mma<<<gp, 256, GSMEM>>>(proj_b, out, 1);       // proj: N=192
}